// round 5
// baseline (speedup 1.0000x reference)
#include <cuda_runtime.h>
#include <cuda_bf16.h>
#include <math.h>
#include <stdint.h>

#define Bb 16
#define Ll 512
#define Dd 512
#define Nn 3
#define Hh 8
#define DH 64
#define AH 256
#define KHALF 7

#define BLD 4194304L        // Bb*Ll*Dd
#define CTSZ 37748736L      // 3 * 8192 * 1536

// ---------------- scratch: GEMM tensors as (hi,lo) bf16 pairs -----------------
__device__ __nv_bfloat16 g_segH[BLD],   g_segL[BLD];
__device__ __nv_bfloat16 g_WH[7864320], g_WL[7864320];
__device__ __nv_bfloat16 g_B1H[3*BLD],  g_B1L[3*BLD];
__device__ __nv_bfloat16 g_MH [3*BLD],  g_ML [3*BLD];
__device__ __nv_bfloat16 g_CTH[CTSZ],   g_CTL[CTSZ];       // [n][8192][1536] mq|mv|mk
__device__ __nv_bfloat16 g_AHb[BLD],    g_ALb[BLD];
__device__ __nv_bfloat16 g_SH[(long)Bb*Hh*Ll*Ll], g_SL[(long)Bb*Hh*Ll*Ll];
__device__ float g_H2[Bb*Nn*Dd];
__device__ float g_SW[Bb*Nn];
__device__ float g_biasC[8*1536];

// weight offsets (elements)
#define OFF_HW1 0L
#define OFF_HW3 786432L
#define OFF_LCV 1572864L    // 6 slots of 512x1536
#define OFF_GCV 6291456L    // 2 slots of 512x1536

// ---------------- PTX helpers -------------------------------------------------
__device__ __forceinline__ uint32_t smem_u32(const void* p) {
    uint32_t a;
    asm("{ .reg .u64 t; cvta.to.shared.u64 t, %1; cvt.u32.u64 %0, t; }" : "=r"(a) : "l"(p));
    return a;
}
#define CPA16(dst, src) asm volatile( \
    "cp.async.ca.shared.global [%0], [%1], 16;" :: "r"(dst), "l"(__cvta_generic_to_global(src)))
#define CPA_COMMIT() asm volatile("cp.async.commit_group;" ::: "memory")
#define CPA_WAIT1()  asm volatile("cp.async.wait_group 1;" ::: "memory")

#define LDM_X4(r, a) asm volatile( \
    "ldmatrix.sync.aligned.m8n8.x4.shared.b16 {%0,%1,%2,%3}, [%4];" \
    : "=r"((r)[0]),"=r"((r)[1]),"=r"((r)[2]),"=r"((r)[3]) : "r"(a))
#define LDM_X4T(r, a) asm volatile( \
    "ldmatrix.sync.aligned.m8n8.x4.trans.shared.b16 {%0,%1,%2,%3}, [%4];" \
    : "=r"((r)[0]),"=r"((r)[1]),"=r"((r)[2]),"=r"((r)[3]) : "r"(a))
#define MMA16816(d, a, b) asm volatile( \
    "mma.sync.aligned.m16n8k16.row.col.f32.bf16.bf16.f32 " \
    "{%0,%1,%2,%3}, {%4,%5,%6,%7}, {%8,%9}, {%0,%1,%2,%3};" \
    : "+f"((d)[0]),"+f"((d)[1]),"+f"((d)[2]),"+f"((d)[3]) \
    : "r"((a)[0]),"r"((a)[1]),"r"((a)[2]),"r"((a)[3]), "r"((b)[0]),"r"((b)[1]))

__device__ __forceinline__ float bfadd(__nv_bfloat16 h, __nv_bfloat16 l) {
    return __bfloat162float(h) + __bfloat162float(l);
}
__device__ __forceinline__ void bfsplit(float v, __nv_bfloat16& h, __nv_bfloat16& l) {
    h = __float2bfloat16(v);
    l = __float2bfloat16(v - __bfloat162float(h));
}

// ---------------- split prepasses ---------------------------------------------
__global__ void split_k(const float* __restrict__ s, __nv_bfloat16* __restrict__ h,
                        __nv_bfloat16* __restrict__ l, long n)
{
    for (long i = ((long)blockIdx.x * blockDim.x + threadIdx.x) * 4; i < n;
         i += (long)gridDim.x * blockDim.x * 4) {
        float4 v = *reinterpret_cast<const float4*>(s + i);
        __nv_bfloat16 hh[4], ll[4];
        bfsplit(v.x, hh[0], ll[0]); bfsplit(v.y, hh[1], ll[1]);
        bfsplit(v.z, hh[2], ll[2]); bfsplit(v.w, hh[3], ll[3]);
        *reinterpret_cast<uint2*>(h + i) = *reinterpret_cast<uint2*>(hh);
        *reinterpret_cast<uint2*>(l + i) = *reinterpret_cast<uint2*>(ll);
    }
}

// split src[rows][C1] into dst[rows][1536] at column offset off
__global__ void split_cols_k(const float* __restrict__ s, __nv_bfloat16* __restrict__ h,
                             __nv_bfloat16* __restrict__ l, long rows, int C1, int off)
{
    long total = rows * C1;
    for (long i = ((long)blockIdx.x * blockDim.x + threadIdx.x) * 4; i < total;
         i += (long)gridDim.x * blockDim.x * 4) {
        float4 v = *reinterpret_cast<const float4*>(s + i);
        long r = i / C1;
        int c = (int)(i - r * C1);
        long d = r * 1536 + off + c;
        __nv_bfloat16 hh[4], ll[4];
        bfsplit(v.x, hh[0], ll[0]); bfsplit(v.y, hh[1], ll[1]);
        bfsplit(v.z, hh[2], ll[2]); bfsplit(v.w, hh[3], ll[3]);
        *reinterpret_cast<uint2*>(h + d) = *reinterpret_cast<uint2*>(hh);
        *reinterpret_cast<uint2*>(l + d) = *reinterpret_cast<uint2*>(ll);
    }
}

__global__ void biascat_k(const float* __restrict__ lcb, const float* __restrict__ lvb,
                          const float* __restrict__ gcb, const float* __restrict__ gvb)
{
    int slot = blockIdx.x;   // 0..5 local [n*2+s], 6..7 global
    for (int c = threadIdx.x; c < 1536; c += blockDim.x) {
        float v;
        if (slot < 6) v = (c < 1024) ? lcb[slot * 1024 + c] : lvb[slot * 512 + c - 1024];
        else {
            int s = slot - 6;
            v = (c < 1024) ? gcb[s * 1024 + c] : gvb[s * 512 + c - 1024];
        }
        g_biasC[slot * 1536 + c] = v;
    }
}

// ---------------- bf16-split mma.sync GEMM, 512 threads ------------------------
// C = act( alpha * A @ op(B) + bias ) (+C if beta1); A,B,C are (hi,lo) pairs
// flags: 1=transB (B is [N][K]), 2=relu, 4=accumulate
template<int BN_T>
__global__ void __launch_bounds__(512, 1) mma_gemm_k(
    const __nv_bfloat16* __restrict__ Ah, const __nv_bfloat16* __restrict__ Al,
    const __nv_bfloat16* __restrict__ Bh, const __nv_bfloat16* __restrict__ Bl,
    const float* __restrict__ bias,
    __nv_bfloat16* __restrict__ Ch, __nv_bfloat16* __restrict__ Cl,
    int K, int lda, int ldb, int ldc, int zInner,
    long sAo, long sAi, long sBo, long sBi, long sCo, long sCi, long sBias,
    float alpha, int flags)
{
    constexpr int BK = 32, LDS = 40;
    constexpr int LDSB = BN_T + 8;
    constexpr int RG = (BN_T == 128) ? 4 : 8;      // warp row groups
    constexpr int MT = 128 / (RG * 16);            // 2 or 1
    constexpr int NT = 4;                          // 32 cols per warp
    constexpr int A_BYTES = 128 * LDS * 2;         // 10240
    constexpr int B_NTB = BK * LDSB * 2;
    constexpr int B_TB  = BN_T * LDS * 2;
    constexpr int B_BYTES = (B_NTB > B_TB) ? B_NTB : B_TB;
    constexpr int STAGE = 2 * A_BYTES + 2 * B_BYTES;
    constexpr int BTRF = BK * BN_T / 8;            // B transfers (512 or 256)

    extern __shared__ char dsm[];
    uint32_t sb0 = smem_u32(dsm);

    int z = blockIdx.z, zo = z / zInner, zi = z % zInner;
    Ah += zo * sAo + zi * sAi;  Al += zo * sAo + zi * sAi;
    Bh += zo * sBo + zi * sBi;  Bl += zo * sBo + zi * sBi;
    Ch += zo * sCo + zi * sCi;  Cl += zo * sCo + zi * sCi;
    if (bias) bias += zi * sBias;

    int tid = threadIdx.x, lane = tid & 31, wid = tid >> 5;
    int wm = wid & (RG - 1), wn = wid / RG;
    int m0 = blockIdx.y * 128, n0 = blockIdx.x * BN_T;
    const bool tb = flags & 1;
    int nc = K / BK;

    auto fill = [&](int c) {
        int k0 = c * BK;
        uint32_t st = sb0 + (c % 3) * STAGE;
        {   // A hi/lo: 512 transfers each, 1 per thread
            int row = tid >> 2, u = tid & 3;
            uint32_t d = st + row * (LDS * 2) + u * 16;
            long g = (long)(m0 + row) * lda + k0 + u * 8;
            CPA16(d, Ah + g);
            CPA16(d + A_BYTES, Al + g);
        }
        if (BN_T == 128 || tid < BTRF) {
            if (!tb) {
                int kk = tid / (BN_T / 8), u = tid % (BN_T / 8);
                uint32_t d = st + 2 * A_BYTES + kk * (LDSB * 2) + u * 16;
                long g = (long)(k0 + kk) * ldb + n0 + u * 8;
                CPA16(d, Bh + g);
                CPA16(d + B_BYTES, Bl + g);
            } else {
                int nn = tid >> 2, u = tid & 3;
                uint32_t d = st + 2 * A_BYTES + nn * (LDS * 2) + u * 16;
                long g = (long)(n0 + nn) * ldb + k0 + u * 8;
                CPA16(d, Bh + g);
                CPA16(d + B_BYTES, Bl + g);
            }
        }
    };

    float acc[MT][NT][4];
    #pragma unroll
    for (int i = 0; i < MT; i++)
        #pragma unroll
        for (int j = 0; j < NT; j++)
            #pragma unroll
            for (int e = 0; e < 4; e++) acc[i][j][e] = 0.f;

    fill(0); CPA_COMMIT();
    fill(1); CPA_COMMIT();

    int alr = lane & 15, alc = (lane >> 4) << 3;
    int blr = (lane & 7) + (((lane >> 4) & 1) << 3);   // tb, non-trans ldm
    int blc = ((lane >> 3) & 1) << 3;
    int btr = (lane & 7) + (((lane >> 3) & 1) << 3);   // !tb, trans ldm
    int btc = ((lane >> 4) & 1) << 3;

    for (int c = 0; c < nc; c++) {
        CPA_WAIT1();
        __syncthreads();
        if (c + 2 < nc) fill(c + 2);
        CPA_COMMIT();

        uint32_t base = sb0 + (c % 3) * STAGE;

        #pragma unroll
        for (int kk = 0; kk < 2; kk++) {
            uint32_t ah[MT][4], al[MT][4], bh[NT][2], bl[NT][2];
            #pragma unroll
            for (int mt = 0; mt < MT; mt++) {
                uint32_t o = base + (uint32_t)(((wm * MT * 16 + mt * 16 + alr) * LDS + kk * 16 + alc) * 2);
                LDM_X4(ah[mt], o);
                LDM_X4(al[mt], o + A_BYTES);
            }
            if (!tb) {
                uint32_t aB = base + 2 * A_BYTES +
                              (uint32_t)(((kk * 16 + btr) * LDSB + wn * 32 + btc) * 2);
                #pragma unroll
                for (int p = 0; p < 2; p++) {
                    uint32_t o = (uint32_t)(p * 16 * 2);
                    uint32_t r[4];
                    LDM_X4T(r, aB + o);
                    bh[2*p][0]=r[0]; bh[2*p][1]=r[1]; bh[2*p+1][0]=r[2]; bh[2*p+1][1]=r[3];
                    LDM_X4T(r, aB + B_BYTES + o);
                    bl[2*p][0]=r[0]; bl[2*p][1]=r[1]; bl[2*p+1][0]=r[2]; bl[2*p+1][1]=r[3];
                }
            } else {
                uint32_t aB = base + 2 * A_BYTES +
                              (uint32_t)(((wn * 32 + blr) * LDS + kk * 16 + blc) * 2);
                #pragma unroll
                for (int p = 0; p < 2; p++) {
                    uint32_t o = (uint32_t)(p * 16 * LDS * 2);
                    uint32_t r[4];
                    LDM_X4(r, aB + o);
                    bh[2*p][0]=r[0]; bh[2*p][1]=r[1]; bh[2*p+1][0]=r[2]; bh[2*p+1][1]=r[3];
                    LDM_X4(r, aB + B_BYTES + o);
                    bl[2*p][0]=r[0]; bl[2*p][1]=r[1]; bl[2*p+1][0]=r[2]; bl[2*p+1][1]=r[3];
                }
            }
            #pragma unroll
            for (int mt = 0; mt < MT; mt++)
                #pragma unroll
                for (int nt = 0; nt < NT; nt++) {
                    MMA16816(acc[mt][nt], ah[mt], bh[nt]);
                    MMA16816(acc[mt][nt], ah[mt], bl[nt]);
                    MMA16816(acc[mt][nt], al[mt], bh[nt]);
                }
        }
    }

    // ---- epilogue
    #pragma unroll
    for (int mt = 0; mt < MT; mt++) {
        int row = m0 + wm * MT * 16 + mt * 16 + (lane >> 2);
        #pragma unroll
        for (int nt = 0; nt < NT; nt++) {
            int col = n0 + wn * 32 + nt * 8 + (lane & 3) * 2;
            float d0 = acc[mt][nt][0] * alpha, d1 = acc[mt][nt][1] * alpha;
            float d2 = acc[mt][nt][2] * alpha, d3 = acc[mt][nt][3] * alpha;
            if (bias) {
                float b0 = bias[col], b1 = bias[col + 1];
                d0 += b0; d1 += b1; d2 += b0; d3 += b1;
            }
            if (flags & 2) {
                d0 = fmaxf(d0, 0.f); d1 = fmaxf(d1, 0.f);
                d2 = fmaxf(d2, 0.f); d3 = fmaxf(d3, 0.f);
            }
            long o0 = (long)row * ldc + col;
            long o1 = o0 + (long)8 * ldc;
            if (flags & 4) {
                __nv_bfloat162 h0 = *reinterpret_cast<const __nv_bfloat162*>(Ch + o0);
                __nv_bfloat162 l0 = *reinterpret_cast<const __nv_bfloat162*>(Cl + o0);
                __nv_bfloat162 h1 = *reinterpret_cast<const __nv_bfloat162*>(Ch + o1);
                __nv_bfloat162 l1 = *reinterpret_cast<const __nv_bfloat162*>(Cl + o1);
                d0 += bfadd(h0.x, l0.x); d1 += bfadd(h0.y, l0.y);
                d2 += bfadd(h1.x, l1.x); d3 += bfadd(h1.y, l1.y);
            }
            __nv_bfloat16 h[4], l[4];
            bfsplit(d0, h[0], l[0]); bfsplit(d1, h[1], l[1]);
            bfsplit(d2, h[2], l[2]); bfsplit(d3, h[3], l[3]);
            *reinterpret_cast<__nv_bfloat162*>(Ch + o0) = __nv_bfloat162{h[0], h[1]};
            *reinterpret_cast<__nv_bfloat162*>(Cl + o0) = __nv_bfloat162{l[0], l[1]};
            *reinterpret_cast<__nv_bfloat162*>(Ch + o1) = __nv_bfloat162{h[2], h[3]};
            *reinterpret_cast<__nv_bfloat162*>(Cl + o1) = __nv_bfloat162{l[2], l[3]};
        }
    }
}

// ---------------- small kernels ------------------------------------------------
__global__ void h2_k(const float* __restrict__ se, const float* __restrict__ w2,
                     const float* __restrict__ b2)
{
    int bn = blockIdx.x;
    int n = bn % Nn;
    int h = threadIdx.x;
    const float* x = se + (long)bn * Dd;
    const float* w = w2 + (long)n * Dd * Dd;
    float acc = b2[n * Dd + h];
    for (int d = 0; d < Dd; d++) acc = fmaf(x[d], w[(long)d * Dd + h], acc);
    g_H2[(long)bn * Dd + h] = fmaxf(acc, 0.f);
}

__global__ void mulh2_k()
{
    long total = 3 * BLD;
    for (long i = (long)blockIdx.x * blockDim.x + threadIdx.x; i < total;
         i += (long)gridDim.x * blockDim.x) {
        int h = (int)(i % Dd);
        long r = i / Dd;
        int b = (int)((r / Ll) % Bb);
        int n = (int)(r / ((long)Ll * Bb));
        float v = bfadd(g_B1H[i], g_B1L[i]) * g_H2[((long)b * Nn + n) * Dd + h];
        bfsplit(v, g_B1H[i], g_B1L[i]);
    }
}

// banded local attention + residual; warp per (n,b,l,h); CT = [mq|mv|mk] x1536
__global__ void local_attn_k(const float* __restrict__ mask)
{
    int gw = (int)(((long)blockIdx.x * blockDim.x + threadIdx.x) >> 5);
    int lane = threadIdx.x & 31;
    if (gw >= Nn * Bb * Ll * Hh) return;
    int h = gw % Hh;
    int l = (gw / Hh) % Ll;
    int b = (gw / (Hh * Ll)) % Bb;
    int n = gw / (Hh * Ll * Bb);

    const __nv_bfloat16* CTH_ = g_CTH + (long)n * 8192 * 1536;
    const __nv_bfloat16* CTL_ = g_CTL + (long)n * 8192 * 1536;

    long ro = ((long)b * Ll + l) * 1536 + h * DH;
    float k0 = bfadd(CTH_[ro + 1024 + lane], CTL_[ro + 1024 + lane]);
    float k1 = bfadd(CTH_[ro + 1024 + lane + 32], CTL_[ro + 1024 + lane + 32]);

    float sc[15];
    #pragma unroll
    for (int j = 0; j < 15; j++) {
        int m = l + (j - KHALF);
        float s = -1e30f;
        if (m >= 0 && m < Ll && mask[(long)b * Ll + m] != 0.f) {
            long mo = ((long)b * Ll + m) * 1536 + h * DH;
            float q0 = bfadd(CTH_[mo + lane], CTL_[mo + lane]);
            float q1 = bfadd(CTH_[mo + lane + 32], CTL_[mo + lane + 32]);
            float d = k0 * q0 + k1 * q1;
            #pragma unroll
            for (int o = 16; o; o >>= 1) d += __shfl_xor_sync(0xffffffffu, d, o);
            s = d * 0.125f;
        }
        sc[j] = s;
    }
    float mx = -1e30f;
    #pragma unroll
    for (int j = 0; j < 15; j++) mx = fmaxf(mx, sc[j]);
    float w[15], sum = 0.f;
    #pragma unroll
    for (int j = 0; j < 15; j++) {
        w[j] = (sc[j] > -1e29f) ? expf(sc[j] - mx) : 0.f;
        sum += w[j];
    }
    float inv = 1.f / sum;
    float o0 = 0.f, o1 = 0.f;
    #pragma unroll
    for (int j = 0; j < 15; j++) {
        if (w[j] != 0.f) {
            int m = l + (j - KHALF);
            long mo = ((long)b * Ll + m) * 1536 + 512 + h * DH;
            float ww = w[j] * inv;
            o0 = fmaf(ww, bfadd(CTH_[mo + lane], CTL_[mo + lane]), o0);
            o1 = fmaf(ww, bfadd(CTH_[mo + lane + 32], CTL_[mo + lane + 32]), o1);
        }
    }
    long xo = (long)n * BLD + ((long)b * Ll + l) * Dd + h * DH;
    __nv_bfloat16* XH = g_MH + xo;
    __nv_bfloat16* XL = g_ML + xo;
    float x0 = bfadd(XH[lane], XL[lane]) + o0;
    float x1 = bfadd(XH[lane + 32], XL[lane + 32]) + o1;
    bfsplit(x0, XH[lane], XL[lane]);
    bfsplit(x1, XH[lane + 32], XL[lane + 32]);
}

__global__ void softmax_k(const float* __restrict__ mask)
{
    long row = blockIdx.x;
    int b = (int)(row / ((long)Hh * Ll));
    __nv_bfloat16* sh = g_SH + row * Ll;
    __nv_bfloat16* sl = g_SL + row * Ll;
    const float* mrow = mask + (long)b * Ll;
    int t = threadIdx.x;

    float v0 = (mrow[t]       != 0.f) ? bfadd(sh[t], sl[t])             : -1e9f;
    float v1 = (mrow[t + 256] != 0.f) ? bfadd(sh[t + 256], sl[t + 256]) : -1e9f;

    __shared__ float red[256];
    red[t] = fmaxf(v0, v1);
    __syncthreads();
    for (int o = 128; o; o >>= 1) { if (t < o) red[t] = fmaxf(red[t], red[t + o]); __syncthreads(); }
    float mx = red[0];
    __syncthreads();

    float e0 = expf(v0 - mx), e1 = expf(v1 - mx);
    red[t] = e0 + e1;
    __syncthreads();
    for (int o = 128; o; o >>= 1) { if (t < o) red[t] += red[t + o]; __syncthreads(); }
    float inv = 1.f / red[0];
    bfsplit(e0 * inv, sh[t], sl[t]);
    bfsplit(e1 * inv, sh[t + 256], sl[t + 256]);
}

__global__ void satt_k(const float* __restrict__ se, const float* __restrict__ w1,
                       const float* __restrict__ w2, float* __restrict__ out_tail)
{
    int b = blockIdx.x, t = threadIdx.x;
    __shared__ float red[256];
    __shared__ float alpha[Nn];
    for (int n = 0; n < Nn; n++) {
        const float* x = se + ((long)b * Nn + n) * Dd;
        float acc = 0.f;
        for (int d = 0; d < Dd; d++) acc = fmaf(x[d], w1[(long)d * AH + t], acc);
        red[t] = tanhf(acc) * w2[t];
        __syncthreads();
        for (int o = 128; o; o >>= 1) { if (t < o) red[t] += red[t + o]; __syncthreads(); }
        if (t == 0) alpha[n] = red[0];
        __syncthreads();
    }
    if (t == 0) {
        float mx = fmaxf(alpha[0], fmaxf(alpha[1], alpha[2]));
        float e[Nn], sum = 0.f;
        for (int n = 0; n < Nn; n++) { e[n] = expf(alpha[n] - mx); sum += e[n]; }
        for (int n = 0; n < Nn; n++) {
            float w = e[n] / sum;
            g_SW[b * Nn + n] = w;
            out_tail[b * Nn + n] = w;
        }
    }
}

__global__ void agg_k()
{
    long stride = (long)Ll * Dd;
    for (long i = (long)blockIdx.x * blockDim.x + threadIdx.x; i < BLD;
         i += (long)gridDim.x * blockDim.x) {
        int b = (int)(i / stride);
        float acc = 0.f;
        #pragma unroll
        for (int n = 0; n < Nn; n++)
            acc = fmaf(g_SW[b * Nn + n], bfadd(g_MH[(long)n * BLD + i], g_ML[(long)n * BLD + i]), acc);
        bfsplit(acc, g_AHb[i], g_ALb[i]);
    }
}

__global__ void copyout_k(float* __restrict__ out)
{
    for (long i = (long)blockIdx.x * blockDim.x + threadIdx.x; i < BLD;
         i += (long)gridDim.x * blockDim.x)
        out[i] = bfadd(g_AHb[i], g_ALb[i]);
}

// ---------------- host orchestration ------------------------------------------
static void mgemm(int BN, const __nv_bfloat16* Ah, const __nv_bfloat16* Al,
                  const __nv_bfloat16* Bh, const __nv_bfloat16* Bl,
                  const float* bias, __nv_bfloat16* Ch, __nv_bfloat16* Cl,
                  int M, int N, int K, int lda, int ldb, int ldc,
                  int batches, int zInner,
                  long sAo, long sAi, long sBo, long sBi, long sCo, long sCi, long sBias,
                  float alpha, int flags)
{
    dim3 grid(N / BN, M / 128, batches);
    if (BN == 128)
        mma_gemm_k<128><<<grid, 512, 122880>>>(Ah, Al, Bh, Bl, bias, Ch, Cl, K,
            lda, ldb, ldc, zInner, sAo, sAi, sBo, sBi, sCo, sCi, sBias, alpha, flags);
    else
        mma_gemm_k<64><<<grid, 512, 92160>>>(Ah, Al, Bh, Bl, bias, Ch, Cl, K,
            lda, ldb, ldc, zInner, sAo, sAi, sBo, sBi, sCo, sCi, sBias, alpha, flags);
}

extern "C" void kernel_launch(void* const* d_in, const int* in_sizes, int n_in,
                              void* d_out, int out_size)
{
    const float* seg   = (const float*)d_in[0];
    const float* mask  = (const float*)d_in[1];
    const float* se    = (const float*)d_in[2];
    const float* hw1   = (const float*)d_in[3];
    const float* hb1   = (const float*)d_in[4];
    const float* hw2   = (const float*)d_in[5];
    const float* hb2   = (const float*)d_in[6];
    const float* hw3   = (const float*)d_in[7];
    const float* hb3   = (const float*)d_in[8];
    const float* lcW   = (const float*)d_in[9];
    const float* lcb   = (const float*)d_in[10];
    const float* lvW   = (const float*)d_in[11];
    const float* lvb   = (const float*)d_in[12];
    const float* gcW   = (const float*)d_in[13];
    const float* gcb   = (const float*)d_in[14];
    const float* gvW   = (const float*)d_in[15];
    const float* gvb   = (const float*)d_in[16];
    const float* sw1   = (const float*)d_in[17];
    const float* sw2   = (const float*)d_in[18];
    float* out = (float*)d_out;

    cudaFuncSetAttribute(mma_gemm_k<128>, cudaFuncAttributeMaxDynamicSharedMemorySize, 122880);
    cudaFuncSetAttribute(mma_gemm_k<64>,  cudaFuncAttributeMaxDynamicSharedMemorySize, 92160);

    __nv_bfloat16 *pSegH, *pSegL, *pWH, *pWL, *pB1H, *pB1L, *pMH, *pML,
                  *pCTH, *pCTL, *pAH, *pAL, *pSH, *pSL;
    float *pBias;
    cudaGetSymbolAddress((void**)&pSegH, g_segH); cudaGetSymbolAddress((void**)&pSegL, g_segL);
    cudaGetSymbolAddress((void**)&pWH, g_WH);     cudaGetSymbolAddress((void**)&pWL, g_WL);
    cudaGetSymbolAddress((void**)&pB1H, g_B1H);   cudaGetSymbolAddress((void**)&pB1L, g_B1L);
    cudaGetSymbolAddress((void**)&pMH, g_MH);     cudaGetSymbolAddress((void**)&pML, g_ML);
    cudaGetSymbolAddress((void**)&pCTH, g_CTH);   cudaGetSymbolAddress((void**)&pCTL, g_CTL);
    cudaGetSymbolAddress((void**)&pAH, g_AHb);    cudaGetSymbolAddress((void**)&pAL, g_ALb);
    cudaGetSymbolAddress((void**)&pSH, g_SH);     cudaGetSymbolAddress((void**)&pSL, g_SL);
    cudaGetSymbolAddress((void**)&pBias, g_biasC);

    const int ML_ = Bb * Ll;          // 8192
    const long CTN = 8192L * 1536;    // per-n CT stride

    // ---- prepasses: splits + weight/bias concat
    split_k<<<1024, 256>>>(seg, pSegH, pSegL, BLD);
    split_k<<<512, 256>>>(hw1, pWH + OFF_HW1, pWL + OFF_HW1, 786432);
    split_k<<<512, 256>>>(hw3, pWH + OFF_HW3, pWL + OFF_HW3, 786432);
    split_cols_k<<<1024, 256>>>(lcW, pWH + OFF_LCV, pWL + OFF_LCV, 3072, 1024, 0);
    split_cols_k<<<512, 256>>>(lvW, pWH + OFF_LCV, pWL + OFF_LCV, 3072, 512, 1024);
    split_cols_k<<<512, 256>>>(gcW, pWH + OFF_GCV, pWL + OFF_GCV, 1024, 1024, 0);
    split_cols_k<<<512, 256>>>(gvW, pWH + OFF_GCV, pWL + OFF_GCV, 1024, 512, 1024);
    biascat_k<<<8, 256>>>(lcb, lvb, gcb, gvb);

    // 1) h2
    h2_k<<<Bb * Nn, Dd>>>(se, hw2, hb2);

    // 2) h1 = relu(seg @ w1 + b1), batched over n
    mgemm(128, pSegH, pSegL, pWH + OFF_HW1, pWL + OFF_HW1, hb1, pB1H, pB1L,
          ML_, Dd, Dd, Dd, Dd, Dd, Nn, Nn,
          0, 0, 0, (long)Dd * Dd, 0, BLD, Dd, 1.f, 2);

    // 3) h1 *= h2
    mulh2_k<<<4096, 256>>>();

    // 4) m = relu(h1m @ w3 + b3)
    mgemm(128, pB1H, pB1L, pWH + OFF_HW3, pWL + OFF_HW3, hb3, pMH, pML,
          ML_, Dd, Dd, Dd, Dd, Dd, Nn, Nn,
          0, BLD, 0, (long)Dd * Dd, 0, BLD, Dd, 1.f, 2);

    // 5) local NL: fused [cW|vW] projection (N=1536) + banded attn, batched n
    for (int s = 0; s < 2; s++) {
        mgemm(128, pMH, pML, pWH + OFF_LCV + (long)s * 786432,
              pWL + OFF_LCV + (long)s * 786432, pBias + s * 1536, pCTH, pCTL,
              ML_, 1536, Dd, Dd, 1536, 1536, Nn, Nn,
              0, BLD, 0, (long)2 * 786432, 0, CTN, (long)2 * 1536, 1.f, 0);
        local_attn_k<<<Nn * Bb * Ll * Hh * 32 / 128, 128>>>(mask);
    }

    // 6) segment attention weights
    satt_k<<<Bb, AH>>>(se, sw1, sw2, out + BLD);

    // 7) aggregate
    agg_k<<<4096, 256>>>();

    // 8) global NL blocks
    for (int s = 0; s < 2; s++) {
        mgemm(128, pAH, pAL, pWH + OFF_GCV + (long)s * 786432,
              pWL + OFF_GCV + (long)s * 786432, pBias + (6 + s) * 1536, pCTH, pCTL,
              ML_, 1536, Dd, Dd, 1536, 1536, 1, 1,
              0, 0, 0, 0, 0, 0, 0, 1.f, 0);
        // scores: S[b,h] = (mk_bh @ mq_bh^T) / 8   (mk at CT+1024, mq at CT+0)
        mgemm(128, pCTH + 1024, pCTL + 1024, pCTH, pCTL, nullptr, pSH, pSL,
              Ll, Ll, DH, 1536, 1536, Ll, Bb * Hh, Hh,
              (long)Ll * 1536, DH,
              (long)Ll * 1536, DH,
              (long)Hh * Ll * Ll, (long)Ll * Ll, 0,
              0.125f, 1);
        softmax_k<<<Bb * Hh * Ll, 256>>>(mask);
        // out: A[b,:,h*64:] += W[b,h] @ mv_bh   (mv at CT+512)
        mgemm(64, pSH, pSL, pCTH + 512, pCTL + 512, nullptr, pAH, pAL,
              Ll, DH, Ll, Ll, 1536, Dd, Bb * Hh, Hh,
              (long)Hh * Ll * Ll, (long)Ll * Ll,
              (long)Ll * 1536, DH,
              (long)Ll * Dd, DH, 0,
              1.f, 4);
    }

    // 9) output
    copyout_k<<<4096, 256>>>(out);
}

// round 6
// speedup vs baseline: 1.2786x; 1.2786x over previous
#include <cuda_runtime.h>
#include <cuda_bf16.h>
#include <math.h>
#include <stdint.h>

#define Bb 16
#define Ll 512
#define Dd 512
#define Nn 3
#define Hh 8
#define DH 64
#define AH 256
#define KHALF 7

#define BLD 4194304L        // Bb*Ll*Dd
#define CTSZ 37748736L      // 3 * 8192 * 1536

// ---------------- scratch: GEMM tensors as (hi,lo) bf16 pairs -----------------
__device__ __nv_bfloat16 g_segH[BLD],   g_segL[BLD];
__device__ __nv_bfloat16 g_WH[7864320], g_WL[7864320];
__device__ __nv_bfloat16 g_B1H[3*BLD],  g_B1L[3*BLD];
__device__ __nv_bfloat16 g_MH [3*BLD],  g_ML [3*BLD];
__device__ __nv_bfloat16 g_CTH[CTSZ],   g_CTL[CTSZ];       // [n][8192][1536] mq|mv|mk
__device__ __nv_bfloat16 g_AHb[BLD],    g_ALb[BLD];
__device__ float g_H2[Bb*Nn*Dd];
__device__ float g_SW[Bb*Nn];
__device__ float g_biasC[8*1536];

// weight offsets (elements)
#define OFF_HW1 0L
#define OFF_HW3 786432L
#define OFF_LCV 1572864L    // 6 slots of 512x1536
#define OFF_GCV 6291456L    // 2 slots of 512x1536

// ---------------- PTX helpers -------------------------------------------------
__device__ __forceinline__ uint32_t smem_u32(const void* p) {
    uint32_t a;
    asm("{ .reg .u64 t; cvta.to.shared.u64 t, %1; cvt.u32.u64 %0, t; }" : "=r"(a) : "l"(p));
    return a;
}
#define CPA16(dst, src) asm volatile( \
    "cp.async.ca.shared.global [%0], [%1], 16;" :: "r"(dst), "l"(__cvta_generic_to_global(src)))
#define CPA_COMMIT() asm volatile("cp.async.commit_group;" ::: "memory")
#define CPA_WAIT1()  asm volatile("cp.async.wait_group 1;" ::: "memory")

#define LDM_X4(r, a) asm volatile( \
    "ldmatrix.sync.aligned.m8n8.x4.shared.b16 {%0,%1,%2,%3}, [%4];" \
    : "=r"((r)[0]),"=r"((r)[1]),"=r"((r)[2]),"=r"((r)[3]) : "r"(a))
#define LDM_X4T(r, a) asm volatile( \
    "ldmatrix.sync.aligned.m8n8.x4.trans.shared.b16 {%0,%1,%2,%3}, [%4];" \
    : "=r"((r)[0]),"=r"((r)[1]),"=r"((r)[2]),"=r"((r)[3]) : "r"(a))
#define MMA16816(d, a, b) asm volatile( \
    "mma.sync.aligned.m16n8k16.row.col.f32.bf16.bf16.f32 " \
    "{%0,%1,%2,%3}, {%4,%5,%6,%7}, {%8,%9}, {%0,%1,%2,%3};" \
    : "+f"((d)[0]),"+f"((d)[1]),"+f"((d)[2]),"+f"((d)[3]) \
    : "r"((a)[0]),"r"((a)[1]),"r"((a)[2]),"r"((a)[3]), "r"((b)[0]),"r"((b)[1]))

__device__ __forceinline__ float bfadd(__nv_bfloat16 h, __nv_bfloat16 l) {
    return __bfloat162float(h) + __bfloat162float(l);
}
__device__ __forceinline__ void bfsplit(float v, __nv_bfloat16& h, __nv_bfloat16& l) {
    h = __float2bfloat16(v);
    l = __float2bfloat16(v - __bfloat162float(h));
}
__device__ __forceinline__ uint32_t pack_hi2(float a, float b) {
    __nv_bfloat162 t = __floats2bfloat162_rn(a, b);
    return *reinterpret_cast<uint32_t*>(&t);
}
__device__ __forceinline__ void pack_split2(float a, float b, uint32_t& hp, uint32_t& lp) {
    __nv_bfloat16 ha, la, hb, lb;
    bfsplit(a, ha, la); bfsplit(b, hb, lb);
    __nv_bfloat162 th{ha, hb}, tl{la, lb};
    hp = *reinterpret_cast<uint32_t*>(&th);
    lp = *reinterpret_cast<uint32_t*>(&tl);
}

// ---------------- split prepasses ---------------------------------------------
__global__ void split_k(const float* __restrict__ s, __nv_bfloat16* __restrict__ h,
                        __nv_bfloat16* __restrict__ l, long n)
{
    for (long i = ((long)blockIdx.x * blockDim.x + threadIdx.x) * 4; i < n;
         i += (long)gridDim.x * blockDim.x * 4) {
        float4 v = *reinterpret_cast<const float4*>(s + i);
        __nv_bfloat16 hh[4], ll[4];
        bfsplit(v.x, hh[0], ll[0]); bfsplit(v.y, hh[1], ll[1]);
        bfsplit(v.z, hh[2], ll[2]); bfsplit(v.w, hh[3], ll[3]);
        *reinterpret_cast<uint2*>(h + i) = *reinterpret_cast<uint2*>(hh);
        *reinterpret_cast<uint2*>(l + i) = *reinterpret_cast<uint2*>(ll);
    }
}

__global__ void split_cols_k(const float* __restrict__ s, __nv_bfloat16* __restrict__ h,
                             __nv_bfloat16* __restrict__ l, long rows, int C1, int off)
{
    long total = rows * C1;
    for (long i = ((long)blockIdx.x * blockDim.x + threadIdx.x) * 4; i < total;
         i += (long)gridDim.x * blockDim.x * 4) {
        float4 v = *reinterpret_cast<const float4*>(s + i);
        long r = i / C1;
        int c = (int)(i - r * C1);
        long d = r * 1536 + off + c;
        __nv_bfloat16 hh[4], ll[4];
        bfsplit(v.x, hh[0], ll[0]); bfsplit(v.y, hh[1], ll[1]);
        bfsplit(v.z, hh[2], ll[2]); bfsplit(v.w, hh[3], ll[3]);
        *reinterpret_cast<uint2*>(h + d) = *reinterpret_cast<uint2*>(hh);
        *reinterpret_cast<uint2*>(l + d) = *reinterpret_cast<uint2*>(ll);
    }
}

__global__ void biascat_k(const float* __restrict__ lcb, const float* __restrict__ lvb,
                          const float* __restrict__ gcb, const float* __restrict__ gvb)
{
    int slot = blockIdx.x;   // 0..5 local [n*2+s], 6..7 global
    for (int c = threadIdx.x; c < 1536; c += blockDim.x) {
        float v;
        if (slot < 6) v = (c < 1024) ? lcb[slot * 1024 + c] : lvb[slot * 512 + c - 1024];
        else {
            int s = slot - 6;
            v = (c < 1024) ? gcb[s * 1024 + c] : gvb[s * 512 + c - 1024];
        }
        g_biasC[slot * 1536 + c] = v;
    }
}

// ---------------- bf16-split mma.sync GEMM (R4 config: 256 thr, 8 warps) ------
// C = act( alpha * A @ B + bias ) ; A,B,C (hi,lo) pairs ; flags: 2=relu
__global__ void __launch_bounds__(256, 1) mma_gemm_k(
    const __nv_bfloat16* __restrict__ Ah, const __nv_bfloat16* __restrict__ Al,
    const __nv_bfloat16* __restrict__ Bh, const __nv_bfloat16* __restrict__ Bl,
    const float* __restrict__ bias,
    __nv_bfloat16* __restrict__ Ch, __nv_bfloat16* __restrict__ Cl,
    int K, int lda, int ldb, int ldc, int zInner,
    long sAo, long sAi, long sBo, long sBi, long sCo, long sCi, long sBias,
    float alpha, int flags)
{
    constexpr int BN_T = 128;
    constexpr int BK = 32, LDS = 40;
    constexpr int LDSB = BN_T + 8;
    constexpr int WN = BN_T / 4;          // 32
    constexpr int NT = 4, MT = 4;
    constexpr int A_BYTES = 128 * LDS * 2;
    constexpr int B_BYTES = BK * LDSB * 2;
    constexpr int STAGE = 2 * A_BYTES + 2 * B_BYTES;

    extern __shared__ char dsm[];
    uint32_t sb0 = smem_u32(dsm);

    int z = blockIdx.z, zo = z / zInner, zi = z % zInner;
    Ah += zo * sAo + zi * sAi;  Al += zo * sAo + zi * sAi;
    Bh += zo * sBo + zi * sBi;  Bl += zo * sBo + zi * sBi;
    Ch += zo * sCo + zi * sCi;  Cl += zo * sCo + zi * sCi;
    if (bias) bias += zi * sBias;

    int tid = threadIdx.x, lane = tid & 31, wid = tid >> 5;
    int wm = wid & 1, wn = wid >> 1;
    int m0 = blockIdx.y * 128, n0 = blockIdx.x * BN_T;
    int nc = K / BK;

    auto fill = [&](int c) {
        int k0 = c * BK;
        uint32_t st = sb0 + (c % 3) * STAGE;
        #pragma unroll
        for (int it = 0; it < 2; it++) {
            int idx = tid + it * 256;
            int row = idx >> 2, u = idx & 3;
            uint32_t d = st + row * (LDS * 2) + u * 16;
            long g = (long)(m0 + row) * lda + k0 + u * 8;
            CPA16(d, Ah + g);
            CPA16(d + A_BYTES, Al + g);
        }
        #pragma unroll
        for (int it = 0; it < 2; it++) {
            int idx = tid + it * 256;
            int kk = idx >> 4, u = idx & 15;
            uint32_t d = st + 2 * A_BYTES + kk * (LDSB * 2) + u * 16;
            long g = (long)(k0 + kk) * ldb + n0 + u * 8;
            CPA16(d, Bh + g);
            CPA16(d + B_BYTES, Bl + g);
        }
    };

    float acc[MT][NT][4];
    #pragma unroll
    for (int i = 0; i < MT; i++)
        #pragma unroll
        for (int j = 0; j < NT; j++)
            #pragma unroll
            for (int e = 0; e < 4; e++) acc[i][j][e] = 0.f;

    fill(0); CPA_COMMIT();
    fill(1); CPA_COMMIT();

    int alr = lane & 15, alc = (lane >> 4) << 3;
    int btr = (lane & 7) + (((lane >> 3) & 1) << 3);
    int btc = ((lane >> 4) & 1) << 3;

    for (int c = 0; c < nc; c++) {
        CPA_WAIT1();
        __syncthreads();
        if (c + 2 < nc) fill(c + 2);
        CPA_COMMIT();

        uint32_t base = sb0 + (c % 3) * STAGE;
        uint32_t aAhi = base + ((wm * 64 + alr) * LDS + alc) * 2;

        #pragma unroll
        for (int kk = 0; kk < 2; kk++) {
            uint32_t ah[MT][4], al[MT][4], bh[NT][2], bl[NT][2];
            #pragma unroll
            for (int mt = 0; mt < MT; mt++) {
                uint32_t o = (uint32_t)((mt * 16 * LDS + kk * 16) * 2);
                LDM_X4(ah[mt], aAhi + o);
                LDM_X4(al[mt], aAhi + A_BYTES + o);
            }
            {
                uint32_t aB = base + 2 * A_BYTES +
                              (uint32_t)(((kk * 16 + btr) * LDSB + wn * WN + btc) * 2);
                #pragma unroll
                for (int p = 0; p < 2; p++) {
                    uint32_t o = (uint32_t)(p * 16 * 2);
                    uint32_t r[4];
                    LDM_X4T(r, aB + o);
                    bh[2*p][0]=r[0]; bh[2*p][1]=r[1]; bh[2*p+1][0]=r[2]; bh[2*p+1][1]=r[3];
                    LDM_X4T(r, aB + B_BYTES + o);
                    bl[2*p][0]=r[0]; bl[2*p][1]=r[1]; bl[2*p+1][0]=r[2]; bl[2*p+1][1]=r[3];
                }
            }
            #pragma unroll
            for (int mt = 0; mt < MT; mt++)
                #pragma unroll
                for (int nt = 0; nt < NT; nt++) {
                    MMA16816(acc[mt][nt], ah[mt], bh[nt]);
                    MMA16816(acc[mt][nt], ah[mt], bl[nt]);
                    MMA16816(acc[mt][nt], al[mt], bh[nt]);
                }
        }
    }

    #pragma unroll
    for (int mt = 0; mt < MT; mt++) {
        int row = m0 + wm * 64 + mt * 16 + (lane >> 2);
        #pragma unroll
        for (int nt = 0; nt < NT; nt++) {
            int col = n0 + wn * WN + nt * 8 + (lane & 3) * 2;
            float d0 = acc[mt][nt][0] * alpha, d1 = acc[mt][nt][1] * alpha;
            float d2 = acc[mt][nt][2] * alpha, d3 = acc[mt][nt][3] * alpha;
            if (bias) {
                float b0 = bias[col], b1 = bias[col + 1];
                d0 += b0; d1 += b1; d2 += b0; d3 += b1;
            }
            if (flags & 2) {
                d0 = fmaxf(d0, 0.f); d1 = fmaxf(d1, 0.f);
                d2 = fmaxf(d2, 0.f); d3 = fmaxf(d3, 0.f);
            }
            long o0 = (long)row * ldc + col;
            long o1 = o0 + (long)8 * ldc;
            __nv_bfloat16 h[4], l[4];
            bfsplit(d0, h[0], l[0]); bfsplit(d1, h[1], l[1]);
            bfsplit(d2, h[2], l[2]); bfsplit(d3, h[3], l[3]);
            *reinterpret_cast<__nv_bfloat162*>(Ch + o0) = __nv_bfloat162{h[0], h[1]};
            *reinterpret_cast<__nv_bfloat162*>(Cl + o0) = __nv_bfloat162{l[0], l[1]};
            *reinterpret_cast<__nv_bfloat162*>(Ch + o1) = __nv_bfloat162{h[2], h[3]};
            *reinterpret_cast<__nv_bfloat162*>(Cl + o1) = __nv_bfloat162{l[2], l[3]};
        }
    }
}

// ---------------- flash global attention (fused scores+softmax+PV+residual) ----
// CT slot 0 holds [mq|mv|mk]; A += softmax(mk@mq^T/8 + maskbias) @ mv
#define FLDQ 72
#define FQH 0
#define FQL 18432
#define FKH 36864
#define FKL 55296
#define FVH 73728
#define FVL 92160
#define FMSK 110592
#define FSMEM 112640

__global__ void __launch_bounds__(256, 1) flash_k(const float* __restrict__ mask)
{
    extern __shared__ char sm[];
    uint32_t sb = smem_u32(sm);
    float* mbias = reinterpret_cast<float*>(sm + FMSK);
    int tid = threadIdx.x, lane = tid & 31, w = tid >> 5;
    int b = blockIdx.y >> 3, h = blockIdx.y & 7;
    int l0 = blockIdx.x * 128;
    long base = (long)b * 512 * 1536;

    // Q = mk rows [l0, l0+128), cols 1024+h*64
    for (int i = tid; i < 1024; i += 256) {
        int row = i >> 3, u = i & 7;
        long g = base + (long)(l0 + row) * 1536 + 1024 + h * DH + u * 8;
        *reinterpret_cast<uint4*>(sm + FQH + row * 144 + u * 16) =
            *reinterpret_cast<const uint4*>(g_CTH + g);
        *reinterpret_cast<uint4*>(sm + FQL + row * 144 + u * 16) =
            *reinterpret_cast<const uint4*>(g_CTL + g);
    }
    for (int i = tid; i < 512; i += 256)
        mbias[i] = (mask[(long)b * 512 + i] != 0.f) ? 0.f : -1e9f;

    float O[8][4];
    #pragma unroll
    for (int i = 0; i < 8; i++)
        #pragma unroll
        for (int e = 0; e < 4; e++) O[i][e] = 0.f;
    float mrow[2] = {-1e30f, -1e30f}, lrow[2] = {0.f, 0.f};

    int alr = lane & 15, alc = (lane >> 4) << 3;
    int blr = (lane & 7) + (((lane >> 4) & 1) << 3), blc = ((lane >> 3) & 1) << 3;
    int btr = (lane & 7) + (((lane >> 3) & 1) << 3), btc = ((lane >> 4) & 1) << 3;
    int c0 = (lane & 3) * 2;

    for (int mi = 0; mi < 4; mi++) {
        int m0 = mi * 128;
        __syncthreads();
        for (int i = tid; i < 1024; i += 256) {
            int row = i >> 3, u = i & 7;
            long gq = base + (long)(m0 + row) * 1536 + h * DH + u * 8;
            long gv = gq + 512;
            *reinterpret_cast<uint4*>(sm + FKH + row * 144 + u * 16) =
                *reinterpret_cast<const uint4*>(g_CTH + gq);
            *reinterpret_cast<uint4*>(sm + FKL + row * 144 + u * 16) =
                *reinterpret_cast<const uint4*>(g_CTL + gq);
            *reinterpret_cast<uint4*>(sm + FVH + row * 144 + u * 16) =
                *reinterpret_cast<const uint4*>(g_CTH + gv);
            *reinterpret_cast<uint4*>(sm + FVL + row * 144 + u * 16) =
                *reinterpret_cast<const uint4*>(g_CTL + gv);
        }
        __syncthreads();

        float S[16][4];
        #pragma unroll
        for (int i = 0; i < 16; i++)
            #pragma unroll
            for (int e = 0; e < 4; e++) S[i][e] = 0.f;

        #pragma unroll
        for (int kc = 0; kc < 4; kc++) {
            uint32_t qh[4], ql[4];
            uint32_t ao = sb + FQH + (uint32_t)(((w * 16 + alr) * FLDQ + kc * 16 + alc) * 2);
            LDM_X4(qh, ao);
            LDM_X4(ql, ao + (FQL - FQH));
            #pragma unroll
            for (int p = 0; p < 8; p++) {
                uint32_t kf[4], kl[4];
                uint32_t bo = sb + FKH + (uint32_t)(((p * 16 + blr) * FLDQ + kc * 16 + blc) * 2);
                LDM_X4(kf, bo);
                LDM_X4(kl, bo + (FKL - FKH));
                uint32_t b0[2] = {kf[0], kf[1]}, b1[2] = {kf[2], kf[3]};
                uint32_t b0l[2] = {kl[0], kl[1]}, b1l[2] = {kl[2], kl[3]};
                MMA16816(S[2*p],   qh, b0);  MMA16816(S[2*p],   qh, b0l); MMA16816(S[2*p],   ql, b0);
                MMA16816(S[2*p+1], qh, b1);  MMA16816(S[2*p+1], qh, b1l); MMA16816(S[2*p+1], ql, b1);
            }
        }

        // scale + mask + row max
        float cmax[2] = {-1e30f, -1e30f};
        #pragma unroll
        for (int nt = 0; nt < 16; nt++)
            #pragma unroll
            for (int e = 0; e < 4; e++) {
                int col = m0 + nt * 8 + c0 + (e & 1);
                float v = S[nt][e] * 0.125f + mbias[col];
                S[nt][e] = v;
                cmax[e >> 1] = fmaxf(cmax[e >> 1], v);
            }
        #pragma unroll
        for (int o = 1; o <= 2; o <<= 1) {
            cmax[0] = fmaxf(cmax[0], __shfl_xor_sync(0xffffffffu, cmax[0], o));
            cmax[1] = fmaxf(cmax[1], __shfl_xor_sync(0xffffffffu, cmax[1], o));
        }
        float mn0 = fmaxf(mrow[0], cmax[0]), mn1 = fmaxf(mrow[1], cmax[1]);
        float a0 = __expf(mrow[0] - mn0), a1 = __expf(mrow[1] - mn1);
        mrow[0] = mn0; mrow[1] = mn1;
        lrow[0] *= a0; lrow[1] *= a1;
        #pragma unroll
        for (int i = 0; i < 8; i++) {
            O[i][0] *= a0; O[i][1] *= a0; O[i][2] *= a1; O[i][3] *= a1;
        }
        #pragma unroll
        for (int nt = 0; nt < 16; nt++)
            #pragma unroll
            for (int e = 0; e < 4; e++) {
                float p = __expf(S[nt][e] - ((e < 2) ? mn0 : mn1));
                S[nt][e] = p;
                lrow[e >> 1] += p;
            }

        // PV: O += P @ V
        #pragma unroll
        for (int kc = 0; kc < 8; kc++) {
            uint32_t ph[4], pl[4];
            pack_split2(S[2*kc][0],   S[2*kc][1],   ph[0], pl[0]);
            pack_split2(S[2*kc][2],   S[2*kc][3],   ph[1], pl[1]);
            pack_split2(S[2*kc+1][0], S[2*kc+1][1], ph[2], pl[2]);
            pack_split2(S[2*kc+1][2], S[2*kc+1][3], ph[3], pl[3]);
            #pragma unroll
            for (int p = 0; p < 4; p++) {
                uint32_t vh[4], vl[4];
                uint32_t bo = sb + FVH + (uint32_t)(((kc * 16 + btr) * FLDQ + p * 16 + btc) * 2);
                LDM_X4T(vh, bo);
                LDM_X4T(vl, bo + (FVL - FVH));
                uint32_t b0[2] = {vh[0], vh[1]}, b1[2] = {vh[2], vh[3]};
                uint32_t b0l[2] = {vl[0], vl[1]}, b1l[2] = {vl[2], vl[3]};
                MMA16816(O[2*p],   ph, b0);  MMA16816(O[2*p],   ph, b0l); MMA16816(O[2*p],   pl, b0);
                MMA16816(O[2*p+1], ph, b1);  MMA16816(O[2*p+1], ph, b1l); MMA16816(O[2*p+1], pl, b1);
            }
        }
    }

    #pragma unroll
    for (int o = 1; o <= 2; o <<= 1) {
        lrow[0] += __shfl_xor_sync(0xffffffffu, lrow[0], o);
        lrow[1] += __shfl_xor_sync(0xffffffffu, lrow[1], o);
    }
    float inv0 = 1.f / lrow[0], inv1 = 1.f / lrow[1];

    int r0g = l0 + w * 16 + (lane >> 2);
    #pragma unroll
    for (int nt = 0; nt < 8; nt++) {
        int col = h * DH + nt * 8 + c0;
        long o0 = ((long)b * 512 + r0g) * 512 + col;
        long o1 = o0 + 8 * 512;
        __nv_bfloat162 h0 = *reinterpret_cast<const __nv_bfloat162*>(g_AHb + o0);
        __nv_bfloat162 l0v = *reinterpret_cast<const __nv_bfloat162*>(g_ALb + o0);
        __nv_bfloat162 h1 = *reinterpret_cast<const __nv_bfloat162*>(g_AHb + o1);
        __nv_bfloat162 l1v = *reinterpret_cast<const __nv_bfloat162*>(g_ALb + o1);
        float d0 = bfadd(h0.x, l0v.x) + O[nt][0] * inv0;
        float d1 = bfadd(h0.y, l0v.y) + O[nt][1] * inv0;
        float d2 = bfadd(h1.x, l1v.x) + O[nt][2] * inv1;
        float d3 = bfadd(h1.y, l1v.y) + O[nt][3] * inv1;
        __nv_bfloat16 hh[4], ll[4];
        bfsplit(d0, hh[0], ll[0]); bfsplit(d1, hh[1], ll[1]);
        bfsplit(d2, hh[2], ll[2]); bfsplit(d3, hh[3], ll[3]);
        *reinterpret_cast<__nv_bfloat162*>(g_AHb + o0) = __nv_bfloat162{hh[0], hh[1]};
        *reinterpret_cast<__nv_bfloat162*>(g_ALb + o0) = __nv_bfloat162{ll[0], ll[1]};
        *reinterpret_cast<__nv_bfloat162*>(g_AHb + o1) = __nv_bfloat162{hh[2], hh[3]};
        *reinterpret_cast<__nv_bfloat162*>(g_ALb + o1) = __nv_bfloat162{ll[2], ll[3]};
    }
}

// ---------------- small kernels ------------------------------------------------
__global__ void h2_k(const float* __restrict__ se, const float* __restrict__ w2,
                     const float* __restrict__ b2)
{
    int bn = blockIdx.x;
    int n = bn % Nn;
    int h = threadIdx.x;
    const float* x = se + (long)bn * Dd;
    const float* w = w2 + (long)n * Dd * Dd;
    float acc = b2[n * Dd + h];
    for (int d = 0; d < Dd; d++) acc = fmaf(x[d], w[(long)d * Dd + h], acc);
    g_H2[(long)bn * Dd + h] = fmaxf(acc, 0.f);
}

__global__ void mulh2_k()
{
    long total = 3 * BLD;
    for (long i = (long)blockIdx.x * blockDim.x + threadIdx.x; i < total;
         i += (long)gridDim.x * blockDim.x) {
        int h = (int)(i % Dd);
        long r = i / Dd;
        int b = (int)((r / Ll) % Bb);
        int n = (int)(r / ((long)Ll * Bb));
        float v = bfadd(g_B1H[i], g_B1L[i]) * g_H2[((long)b * Nn + n) * Dd + h];
        bfsplit(v, g_B1H[i], g_B1L[i]);
    }
}

__global__ void local_attn_k(const float* __restrict__ mask)
{
    int gw = (int)(((long)blockIdx.x * blockDim.x + threadIdx.x) >> 5);
    int lane = threadIdx.x & 31;
    if (gw >= Nn * Bb * Ll * Hh) return;
    int h = gw % Hh;
    int l = (gw / Hh) % Ll;
    int b = (gw / (Hh * Ll)) % Bb;
    int n = gw / (Hh * Ll * Bb);

    const __nv_bfloat16* CTH_ = g_CTH + (long)n * 8192 * 1536;
    const __nv_bfloat16* CTL_ = g_CTL + (long)n * 8192 * 1536;

    long ro = ((long)b * Ll + l) * 1536 + h * DH;
    float k0 = bfadd(CTH_[ro + 1024 + lane], CTL_[ro + 1024 + lane]);
    float k1 = bfadd(CTH_[ro + 1024 + lane + 32], CTL_[ro + 1024 + lane + 32]);

    float sc[15];
    #pragma unroll
    for (int j = 0; j < 15; j++) {
        int m = l + (j - KHALF);
        float s = -1e30f;
        if (m >= 0 && m < Ll && mask[(long)b * Ll + m] != 0.f) {
            long mo = ((long)b * Ll + m) * 1536 + h * DH;
            float q0 = bfadd(CTH_[mo + lane], CTL_[mo + lane]);
            float q1 = bfadd(CTH_[mo + lane + 32], CTL_[mo + lane + 32]);
            float d = k0 * q0 + k1 * q1;
            #pragma unroll
            for (int o = 16; o; o >>= 1) d += __shfl_xor_sync(0xffffffffu, d, o);
            s = d * 0.125f;
        }
        sc[j] = s;
    }
    float mx = -1e30f;
    #pragma unroll
    for (int j = 0; j < 15; j++) mx = fmaxf(mx, sc[j]);
    float w[15], sum = 0.f;
    #pragma unroll
    for (int j = 0; j < 15; j++) {
        w[j] = (sc[j] > -1e29f) ? expf(sc[j] - mx) : 0.f;
        sum += w[j];
    }
    float inv = 1.f / sum;
    float o0 = 0.f, o1 = 0.f;
    #pragma unroll
    for (int j = 0; j < 15; j++) {
        if (w[j] != 0.f) {
            int m = l + (j - KHALF);
            long mo = ((long)b * Ll + m) * 1536 + 512 + h * DH;
            float ww = w[j] * inv;
            o0 = fmaf(ww, bfadd(CTH_[mo + lane], CTL_[mo + lane]), o0);
            o1 = fmaf(ww, bfadd(CTH_[mo + lane + 32], CTL_[mo + lane + 32]), o1);
        }
    }
    long xo = (long)n * BLD + ((long)b * Ll + l) * Dd + h * DH;
    __nv_bfloat16* XH = g_MH + xo;
    __nv_bfloat16* XL = g_ML + xo;
    float x0 = bfadd(XH[lane], XL[lane]) + o0;
    float x1 = bfadd(XH[lane + 32], XL[lane + 32]) + o1;
    bfsplit(x0, XH[lane], XL[lane]);
    bfsplit(x1, XH[lane + 32], XL[lane + 32]);
}

__global__ void satt_k(const float* __restrict__ se, const float* __restrict__ w1,
                       const float* __restrict__ w2, float* __restrict__ out_tail)
{
    int b = blockIdx.x, t = threadIdx.x;
    __shared__ float red[256];
    __shared__ float alpha[Nn];
    for (int n = 0; n < Nn; n++) {
        const float* x = se + ((long)b * Nn + n) * Dd;
        float acc = 0.f;
        for (int d = 0; d < Dd; d++) acc = fmaf(x[d], w1[(long)d * AH + t], acc);
        red[t] = tanhf(acc) * w2[t];
        __syncthreads();
        for (int o = 128; o; o >>= 1) { if (t < o) red[t] += red[t + o]; __syncthreads(); }
        if (t == 0) alpha[n] = red[0];
        __syncthreads();
    }
    if (t == 0) {
        float mx = fmaxf(alpha[0], fmaxf(alpha[1], alpha[2]));
        float e[Nn], sum = 0.f;
        for (int n = 0; n < Nn; n++) { e[n] = expf(alpha[n] - mx); sum += e[n]; }
        for (int n = 0; n < Nn; n++) {
            float w = e[n] / sum;
            g_SW[b * Nn + n] = w;
            out_tail[b * Nn + n] = w;
        }
    }
}

__global__ void agg_k()
{
    long stride = (long)Ll * Dd;
    for (long i = (long)blockIdx.x * blockDim.x + threadIdx.x; i < BLD;
         i += (long)gridDim.x * blockDim.x) {
        int b = (int)(i / stride);
        float acc = 0.f;
        #pragma unroll
        for (int n = 0; n < Nn; n++)
            acc = fmaf(g_SW[b * Nn + n], bfadd(g_MH[(long)n * BLD + i], g_ML[(long)n * BLD + i]), acc);
        bfsplit(acc, g_AHb[i], g_ALb[i]);
    }
}

__global__ void copyout_k(float* __restrict__ out)
{
    for (long i = (long)blockIdx.x * blockDim.x + threadIdx.x; i < BLD;
         i += (long)gridDim.x * blockDim.x)
        out[i] = bfadd(g_AHb[i], g_ALb[i]);
}

// ---------------- host orchestration ------------------------------------------
static void mgemm(const __nv_bfloat16* Ah, const __nv_bfloat16* Al,
                  const __nv_bfloat16* Bh, const __nv_bfloat16* Bl,
                  const float* bias, __nv_bfloat16* Ch, __nv_bfloat16* Cl,
                  int M, int N, int K, int lda, int ldb, int ldc,
                  int batches, int zInner,
                  long sAo, long sAi, long sBo, long sBi, long sCo, long sCi, long sBias,
                  float alpha, int flags)
{
    dim3 grid(N / 128, M / 128, batches);
    mma_gemm_k<<<grid, 256, 122880>>>(Ah, Al, Bh, Bl, bias, Ch, Cl, K,
        lda, ldb, ldc, zInner, sAo, sAi, sBo, sBi, sCo, sCi, sBias, alpha, flags);
}

extern "C" void kernel_launch(void* const* d_in, const int* in_sizes, int n_in,
                              void* d_out, int out_size)
{
    const float* seg   = (const float*)d_in[0];
    const float* mask  = (const float*)d_in[1];
    const float* se    = (const float*)d_in[2];
    const float* hw1   = (const float*)d_in[3];
    const float* hb1   = (const float*)d_in[4];
    const float* hw2   = (const float*)d_in[5];
    const float* hb2   = (const float*)d_in[6];
    const float* hw3   = (const float*)d_in[7];
    const float* hb3   = (const float*)d_in[8];
    const float* lcW   = (const float*)d_in[9];
    const float* lcb   = (const float*)d_in[10];
    const float* lvW   = (const float*)d_in[11];
    const float* lvb   = (const float*)d_in[12];
    const float* gcW   = (const float*)d_in[13];
    const float* gcb   = (const float*)d_in[14];
    const float* gvW   = (const float*)d_in[15];
    const float* gvb   = (const float*)d_in[16];
    const float* sw1   = (const float*)d_in[17];
    const float* sw2   = (const float*)d_in[18];
    float* out = (float*)d_out;

    cudaFuncSetAttribute(mma_gemm_k, cudaFuncAttributeMaxDynamicSharedMemorySize, 122880);
    cudaFuncSetAttribute(flash_k,    cudaFuncAttributeMaxDynamicSharedMemorySize, FSMEM);

    __nv_bfloat16 *pSegH, *pSegL, *pWH, *pWL, *pB1H, *pB1L, *pMH, *pML,
                  *pCTH, *pCTL, *pAH, *pAL;
    float *pBias;
    cudaGetSymbolAddress((void**)&pSegH, g_segH); cudaGetSymbolAddress((void**)&pSegL, g_segL);
    cudaGetSymbolAddress((void**)&pWH, g_WH);     cudaGetSymbolAddress((void**)&pWL, g_WL);
    cudaGetSymbolAddress((void**)&pB1H, g_B1H);   cudaGetSymbolAddress((void**)&pB1L, g_B1L);
    cudaGetSymbolAddress((void**)&pMH, g_MH);     cudaGetSymbolAddress((void**)&pML, g_ML);
    cudaGetSymbolAddress((void**)&pCTH, g_CTH);   cudaGetSymbolAddress((void**)&pCTL, g_CTL);
    cudaGetSymbolAddress((void**)&pAH, g_AHb);    cudaGetSymbolAddress((void**)&pAL, g_ALb);
    cudaGetSymbolAddress((void**)&pBias, g_biasC);

    const int ML_ = Bb * Ll;
    const long CTN = 8192L * 1536;

    // prepasses
    split_k<<<1024, 256>>>(seg, pSegH, pSegL, BLD);
    split_k<<<512, 256>>>(hw1, pWH + OFF_HW1, pWL + OFF_HW1, 786432);
    split_k<<<512, 256>>>(hw3, pWH + OFF_HW3, pWL + OFF_HW3, 786432);
    split_cols_k<<<1024, 256>>>(lcW, pWH + OFF_LCV, pWL + OFF_LCV, 3072, 1024, 0);
    split_cols_k<<<512, 256>>>(lvW, pWH + OFF_LCV, pWL + OFF_LCV, 3072, 512, 1024);
    split_cols_k<<<512, 256>>>(gcW, pWH + OFF_GCV, pWL + OFF_GCV, 1024, 1024, 0);
    split_cols_k<<<512, 256>>>(gvW, pWH + OFF_GCV, pWL + OFF_GCV, 1024, 512, 1024);
    biascat_k<<<8, 256>>>(lcb, lvb, gcb, gvb);

    // 1) h2
    h2_k<<<Bb * Nn, Dd>>>(se, hw2, hb2);

    // 2) h1 = relu(seg @ w1 + b1)
    mgemm(pSegH, pSegL, pWH + OFF_HW1, pWL + OFF_HW1, hb1, pB1H, pB1L,
          ML_, Dd, Dd, Dd, Dd, Dd, Nn, Nn,
          0, 0, 0, (long)Dd * Dd, 0, BLD, Dd, 1.f, 2);

    // 3) h1 *= h2
    mulh2_k<<<4096, 256>>>();

    // 4) m = relu(h1m @ w3 + b3)
    mgemm(pB1H, pB1L, pWH + OFF_HW3, pWL + OFF_HW3, hb3, pMH, pML,
          ML_, Dd, Dd, Dd, Dd, Dd, Nn, Nn,
          0, BLD, 0, (long)Dd * Dd, 0, BLD, Dd, 1.f, 2);

    // 5) local NL: fused [cW|vW] projection + banded attn, batched n
    for (int s = 0; s < 2; s++) {
        mgemm(pMH, pML, pWH + OFF_LCV + (long)s * 786432,
              pWL + OFF_LCV + (long)s * 786432, pBias + s * 1536, pCTH, pCTL,
              ML_, 1536, Dd, Dd, 1536, 1536, Nn, Nn,
              0, BLD, 0, (long)2 * 786432, 0, CTN, (long)2 * 1536, 1.f, 0);
        local_attn_k<<<Nn * Bb * Ll * Hh * 32 / 128, 128>>>(mask);
    }

    // 6) segment attention weights
    satt_k<<<Bb, AH>>>(se, sw1, sw2, out + BLD);

    // 7) aggregate
    agg_k<<<4096, 256>>>();

    // 8) global NL: fused projection + flash attention
    for (int s = 0; s < 2; s++) {
        mgemm(pAH, pAL, pWH + OFF_GCV + (long)s * 786432,
              pWL + OFF_GCV + (long)s * 786432, pBias + (6 + s) * 1536, pCTH, pCTL,
              ML_, 1536, Dd, Dd, 1536, 1536, 1, 1,
              0, 0, 0, 0, 0, 0, 0, 1.f, 0);
        flash_k<<<dim3(Ll / 128, Bb * Hh), 256, FSMEM>>>(mask);
    }

    // 9) output
    copyout_k<<<4096, 256>>>(out);
}

// round 7
// speedup vs baseline: 1.3136x; 1.0274x over previous
#include <cuda_runtime.h>
#include <cuda_bf16.h>
#include <math.h>
#include <stdint.h>

#define Bb 16
#define Ll 512
#define Dd 512
#define Nn 3
#define Hh 8
#define DH 64
#define AH 256
#define KHALF 7

#define BLD 4194304L        // Bb*Ll*Dd
#define CTSZ 37748736L      // 3 * 8192 * 1536

// ---------------- scratch ------------------------------------------------------
__device__ __nv_bfloat16 g_segH[BLD],   g_segL[BLD];
__device__ __nv_bfloat16 g_WH[7864320], g_WL[7864320];   // tiled 32x128 blocks
__device__ __nv_bfloat16 g_B1H[3*BLD],  g_B1L[3*BLD];
__device__ __nv_bfloat16 g_MH [3*BLD],  g_ML [3*BLD];
__device__ __nv_bfloat16 g_CTH[CTSZ],   g_CTL[CTSZ];     // [n][8192][1536] mq|mv|mk
__device__ __nv_bfloat16 g_AHb[BLD],    g_ALb[BLD];
__device__ float g_H2[Bb*Nn*Dd];
__device__ float g_SW[Bb*Nn];
__device__ float g_biasC[8*1536];

// weight offsets (elements)
#define OFF_HW1 0L
#define OFF_HW3 786432L
#define OFF_LCV 1572864L    // 6 slots of 512x1536
#define OFF_GCV 6291456L    // 2 slots of 512x1536

// ---------------- PTX helpers --------------------------------------------------
__device__ __forceinline__ uint32_t smem_u32(const void* p) {
    uint32_t a;
    asm("{ .reg .u64 t; cvta.to.shared.u64 t, %1; cvt.u32.u64 %0, t; }" : "=r"(a) : "l"(p));
    return a;
}
#define CPA16(dst, src) asm volatile( \
    "cp.async.ca.shared.global [%0], [%1], 16;" :: "r"(dst), "l"(__cvta_generic_to_global(src)))
#define CPA_COMMIT() asm volatile("cp.async.commit_group;" ::: "memory")
#define CPA_WAIT1()  asm volatile("cp.async.wait_group 1;" ::: "memory")

#define BULK(dst, src, sz, mb) asm volatile( \
    "cp.async.bulk.shared::cta.global.mbarrier::complete_tx::bytes [%0], [%1], %2, [%3];" \
    :: "r"(dst), "l"(__cvta_generic_to_global(src)), "r"((uint32_t)(sz)), "r"(mb) : "memory")

#define MBAR_INIT(mb, c)   asm volatile("mbarrier.init.shared.b64 [%0], %1;" :: "r"(mb), "r"((uint32_t)(c)) : "memory")
#define MBAR_EXPECT(mb, tx) asm volatile("mbarrier.arrive.expect_tx.shared.b64 _, [%0], %1;" :: "r"(mb), "r"((uint32_t)(tx)) : "memory")
#define FENCE_ASYNC_SHARED() asm volatile("fence.proxy.async.shared::cta;" ::: "memory")
#define MBAR_WAIT(mb, ph) do { \
    uint32_t _m = (mb), _p = (ph), _d; \
    asm volatile("{\n\t.reg .pred p;\n\tmbarrier.try_wait.parity.acquire.cta.shared::cta.b64 p, [%1], %2;\n\tselp.b32 %0, 1, 0, p;\n\t}" \
        : "=r"(_d) : "r"(_m), "r"(_p) : "memory"); \
    if (!_d) { \
        asm volatile("{\n\t.reg .pred P1;\n\tWL_%=:\n\tmbarrier.try_wait.parity.acquire.cta.shared::cta.b64 P1, [%0], %1, 0x989680;\n\t@P1 bra.uni WD_%=;\n\tbra.uni WL_%=;\n\tWD_%=:\n\t}" \
            :: "r"(_m), "r"(_p) : "memory"); \
    } } while (0)

#define LDM_X4(r, a) asm volatile( \
    "ldmatrix.sync.aligned.m8n8.x4.shared.b16 {%0,%1,%2,%3}, [%4];" \
    : "=r"((r)[0]),"=r"((r)[1]),"=r"((r)[2]),"=r"((r)[3]) : "r"(a))
#define LDM_X4T(r, a) asm volatile( \
    "ldmatrix.sync.aligned.m8n8.x4.trans.shared.b16 {%0,%1,%2,%3}, [%4];" \
    : "=r"((r)[0]),"=r"((r)[1]),"=r"((r)[2]),"=r"((r)[3]) : "r"(a))
#define MMA16816(d, a, b) asm volatile( \
    "mma.sync.aligned.m16n8k16.row.col.f32.bf16.bf16.f32 " \
    "{%0,%1,%2,%3}, {%4,%5,%6,%7}, {%8,%9}, {%0,%1,%2,%3};" \
    : "+f"((d)[0]),"+f"((d)[1]),"+f"((d)[2]),"+f"((d)[3]) \
    : "r"((a)[0]),"r"((a)[1]),"r"((a)[2]),"r"((a)[3]), "r"((b)[0]),"r"((b)[1]))

__device__ __forceinline__ float bfadd(__nv_bfloat16 h, __nv_bfloat16 l) {
    return __bfloat162float(h) + __bfloat162float(l);
}
__device__ __forceinline__ void bfsplit(float v, __nv_bfloat16& h, __nv_bfloat16& l) {
    h = __float2bfloat16(v);
    l = __float2bfloat16(v - __bfloat162float(h));
}
__device__ __forceinline__ void pack_split2(float a, float b, uint32_t& hp, uint32_t& lp) {
    __nv_bfloat16 ha, la, hb, lb;
    bfsplit(a, ha, la); bfsplit(b, hb, lb);
    __nv_bfloat162 th{ha, hb}, tl{la, lb};
    hp = *reinterpret_cast<uint32_t*>(&th);
    lp = *reinterpret_cast<uint32_t*>(&tl);
}

// ---------------- prepasses ----------------------------------------------------
__global__ void split_k(const float* __restrict__ s, __nv_bfloat16* __restrict__ h,
                        __nv_bfloat16* __restrict__ l, long n)
{
    for (long i = ((long)blockIdx.x * blockDim.x + threadIdx.x) * 4; i < n;
         i += (long)gridDim.x * blockDim.x * 4) {
        float4 v = *reinterpret_cast<const float4*>(s + i);
        __nv_bfloat16 hh[4], ll[4];
        bfsplit(v.x, hh[0], ll[0]); bfsplit(v.y, hh[1], ll[1]);
        bfsplit(v.z, hh[2], ll[2]); bfsplit(v.w, hh[3], ll[3]);
        *reinterpret_cast<uint2*>(h + i) = *reinterpret_cast<uint2*>(hh);
        *reinterpret_cast<uint2*>(l + i) = *reinterpret_cast<uint2*>(ll);
    }
}

// weights -> tiled blocks: block (nt,kc) at (nt*16+kc)*4096; elem (k,n):
// (k&31)*128 + ((((n&127)>>3) ^ (k&7))<<3) + (n&7)   (XOR-swizzled for ldmatrix)
__global__ void wtile_k(const float* __restrict__ s, __nv_bfloat16* __restrict__ h,
                        __nv_bfloat16* __restrict__ l, int C1, int off, long ds, long total)
{
    long sS = 512L * C1;
    for (long i = ((long)blockIdx.x * blockDim.x + threadIdx.x) * 4; i < total;
         i += (long)gridDim.x * blockDim.x * 4) {
        float4 v = *reinterpret_cast<const float4*>(s + i);
        long sl = i / sS;
        long rem = i - sl * sS;
        int k = (int)(rem / C1), c = (int)(rem - (long)(rem / C1) * C1);
        int n = off + c;
        long d = sl * ds + ((long)((n >> 7) * 16 + (k >> 5))) * 4096
               + (k & 31) * 128 + ((((n & 127) >> 3) ^ (k & 7)) << 3) + (n & 7);
        __nv_bfloat16 hh[4], ll[4];
        bfsplit(v.x, hh[0], ll[0]); bfsplit(v.y, hh[1], ll[1]);
        bfsplit(v.z, hh[2], ll[2]); bfsplit(v.w, hh[3], ll[3]);
        *reinterpret_cast<uint2*>(h + d) = *reinterpret_cast<uint2*>(hh);
        *reinterpret_cast<uint2*>(l + d) = *reinterpret_cast<uint2*>(ll);
    }
}

__global__ void biascat_k(const float* __restrict__ lcb, const float* __restrict__ lvb,
                          const float* __restrict__ gcb, const float* __restrict__ gvb)
{
    int slot = blockIdx.x;   // 0..5 local [n*2+s], 6..7 global
    for (int c = threadIdx.x; c < 1536; c += blockDim.x) {
        float v;
        if (slot < 6) v = (c < 1024) ? lcb[slot * 1024 + c] : lvb[slot * 512 + c - 1024];
        else {
            int s = slot - 6;
            v = (c < 1024) ? gcb[s * 1024 + c] : gvb[s * 512 + c - 1024];
        }
        g_biasC[slot * 1536 + c] = v;
    }
}

// ---------------- GEMM: LDGSTS A + bulk-copy B + 3-MMA bf16 split --------------
// flags: 2=relu, 8=mul by H2
__global__ void __launch_bounds__(256, 1) mma_gemm_k(
    const __nv_bfloat16* __restrict__ Ah, const __nv_bfloat16* __restrict__ Al,
    const __nv_bfloat16* __restrict__ Bh, const __nv_bfloat16* __restrict__ Bl,
    const float* __restrict__ bias, const float* __restrict__ H2,
    __nv_bfloat16* __restrict__ Ch, __nv_bfloat16* __restrict__ Cl,
    int K, int lda, int ldc,
    long sAi, long sBi, long sCi, long sBias, int flags)
{
    constexpr int LDS = 40;
    constexpr int A_BYTES = 128 * LDS * 2;      // 10240
    constexpr int B_BYTES = 8192;
    constexpr int STAGE = 2 * A_BYTES + 2 * B_BYTES;  // 36864
    extern __shared__ char dsm[];
    uint32_t sb0 = smem_u32(dsm);
    uint32_t mbar0 = sb0 + 3 * STAGE;

    int z = blockIdx.z;
    Ah += z * sAi;  Al += z * sAi;
    Bh += z * sBi;  Bl += z * sBi;
    Ch += z * sCi;  Cl += z * sCi;
    if (bias) bias += z * sBias;

    int tid = threadIdx.x, lane = tid & 31, wid = tid >> 5;
    int wm = wid & 1, wn = wid >> 1;
    int m0 = blockIdx.y * 128;
    int nt = blockIdx.x, n0 = nt * 128;
    int nc = K / 32;

    if (tid == 0) {
        MBAR_INIT(mbar0, 1); MBAR_INIT(mbar0 + 8, 1); MBAR_INIT(mbar0 + 16, 1);
        FENCE_ASYNC_SHARED();
    }
    __syncthreads();

    auto fillA = [&](int c) {
        int k0 = c * 32;
        uint32_t st = sb0 + (c % 3) * STAGE;
        #pragma unroll
        for (int it = 0; it < 2; it++) {
            int idx = tid + it * 256;
            int row = idx >> 2, u = idx & 3;
            uint32_t d = st + row * (LDS * 2) + u * 16;
            long g = (long)(m0 + row) * lda + k0 + u * 8;
            CPA16(d, Ah + g);
            CPA16(d + A_BYTES, Al + g);
        }
    };
    auto fillB = [&](int c) {
        uint32_t st = sb0 + (c % 3) * STAGE + 2 * A_BYTES;
        uint32_t mb = mbar0 + (c % 3) * 8;
        MBAR_EXPECT(mb, 16384u);
        long off = ((long)nt * nc + c) * 4096;
        BULK(st, Bh + off, 8192, mb);
        BULK(st + B_BYTES, Bl + off, 8192, mb);
    };

    float acc[4][4][4] = {};

    fillA(0); CPA_COMMIT();
    fillA(1); CPA_COMMIT();
    if (tid == 0) { fillB(0); fillB(1); }

    int alr = lane & 15, alc = (lane >> 4) << 3;
    int btr = (lane & 7) + (((lane >> 3) & 1) << 3);
    int btcc = (lane >> 4) & 1;

    for (int c = 0; c < nc; c++) {
        CPA_WAIT1();
        MBAR_WAIT(mbar0 + (c % 3) * 8, (c / 3) & 1);
        __syncthreads();
        if (c + 2 < nc) { fillA(c + 2); if (tid == 0) fillB(c + 2); }
        CPA_COMMIT();

        uint32_t base = sb0 + (c % 3) * STAGE;
        uint32_t aAhi = base + ((wm * 64 + alr) * LDS + alc) * 2;
        uint32_t bB = base + 2 * A_BYTES;

        #pragma unroll
        for (int kk = 0; kk < 2; kk++) {
            uint32_t ah[4][4], al[4][4], bh[4][2], bl[4][2];
            #pragma unroll
            for (int mt = 0; mt < 4; mt++) {
                uint32_t o = (uint32_t)((mt * 16 * LDS + kk * 16) * 2);
                LDM_X4(ah[mt], aAhi + o);
                LDM_X4(al[mt], aAhi + A_BYTES + o);
            }
            int krow = kk * 16 + btr;
            #pragma unroll
            for (int p = 0; p < 2; p++) {
                int c16 = wn * 4 + p * 2 + btcc;
                uint32_t ad = bB + (uint32_t)(krow * 256 + ((c16 ^ (krow & 7)) << 4));
                uint32_t r[4];
                LDM_X4T(r, ad);
                bh[2*p][0]=r[0]; bh[2*p][1]=r[1]; bh[2*p+1][0]=r[2]; bh[2*p+1][1]=r[3];
                LDM_X4T(r, ad + B_BYTES);
                bl[2*p][0]=r[0]; bl[2*p][1]=r[1]; bl[2*p+1][0]=r[2]; bl[2*p+1][1]=r[3];
            }
            #pragma unroll
            for (int mt = 0; mt < 4; mt++)
                #pragma unroll
                for (int ntb = 0; ntb < 4; ntb++) {
                    MMA16816(acc[mt][ntb], ah[mt], bh[ntb]);
                    MMA16816(acc[mt][ntb], ah[mt], bl[ntb]);
                    MMA16816(acc[mt][ntb], al[mt], bh[ntb]);
                }
        }
    }

    const float* H2b = (flags & 8) ? (H2 + ((long)(m0 >> 9) * Nn + z) * 512) : nullptr;

    #pragma unroll
    for (int mt = 0; mt < 4; mt++) {
        int row = m0 + wm * 64 + mt * 16 + (lane >> 2);
        #pragma unroll
        for (int ntb = 0; ntb < 4; ntb++) {
            int col = n0 + wn * 32 + ntb * 8 + (lane & 3) * 2;
            float d0 = acc[mt][ntb][0], d1 = acc[mt][ntb][1];
            float d2 = acc[mt][ntb][2], d3 = acc[mt][ntb][3];
            if (bias) {
                float b0 = bias[col], b1 = bias[col + 1];
                d0 += b0; d1 += b1; d2 += b0; d3 += b1;
            }
            if (flags & 2) {
                d0 = fmaxf(d0, 0.f); d1 = fmaxf(d1, 0.f);
                d2 = fmaxf(d2, 0.f); d3 = fmaxf(d3, 0.f);
            }
            if (H2b) {
                float f0 = H2b[col], f1 = H2b[col + 1];
                d0 *= f0; d1 *= f1; d2 *= f0; d3 *= f1;
            }
            long o0 = (long)row * ldc + col;
            long o1 = o0 + (long)8 * ldc;
            __nv_bfloat16 h[4], l[4];
            bfsplit(d0, h[0], l[0]); bfsplit(d1, h[1], l[1]);
            bfsplit(d2, h[2], l[2]); bfsplit(d3, h[3], l[3]);
            *reinterpret_cast<__nv_bfloat162*>(Ch + o0) = __nv_bfloat162{h[0], h[1]};
            *reinterpret_cast<__nv_bfloat162*>(Cl + o0) = __nv_bfloat162{l[0], l[1]};
            *reinterpret_cast<__nv_bfloat162*>(Ch + o1) = __nv_bfloat162{h[2], h[3]};
            *reinterpret_cast<__nv_bfloat162*>(Cl + o1) = __nv_bfloat162{l[2], l[3]};
        }
    }
}

// ---------------- flash global attention ---------------------------------------
#define FLDQ 72
#define FQH 0
#define FQL 18432
#define FKH 36864
#define FKL 55296
#define FVH 73728
#define FVL 92160
#define FMSK 110592
#define FSMEM 112640

__global__ void __launch_bounds__(256, 1) flash_k(const float* __restrict__ mask,
                                                  float* __restrict__ outp)
{
    extern __shared__ char sm[];
    uint32_t sb = smem_u32(sm);
    float* mbias = reinterpret_cast<float*>(sm + FMSK);
    int tid = threadIdx.x, lane = tid & 31, w = tid >> 5;
    int b = blockIdx.y >> 3, h = blockIdx.y & 7;
    int l0 = blockIdx.x * 128;
    long base = (long)b * 512 * 1536;

    for (int i = tid; i < 1024; i += 256) {
        int row = i >> 3, u = i & 7;
        long g = base + (long)(l0 + row) * 1536 + 1024 + h * DH + u * 8;
        *reinterpret_cast<uint4*>(sm + FQH + row * 144 + u * 16) =
            *reinterpret_cast<const uint4*>(g_CTH + g);
        *reinterpret_cast<uint4*>(sm + FQL + row * 144 + u * 16) =
            *reinterpret_cast<const uint4*>(g_CTL + g);
    }
    for (int i = tid; i < 512; i += 256)
        mbias[i] = (mask[(long)b * 512 + i] != 0.f) ? 0.f : -1e9f;

    float O[8][4];
    #pragma unroll
    for (int i = 0; i < 8; i++)
        #pragma unroll
        for (int e = 0; e < 4; e++) O[i][e] = 0.f;
    float mrow[2] = {-1e30f, -1e30f}, lrow[2] = {0.f, 0.f};

    int alr = lane & 15, alc = (lane >> 4) << 3;
    int blr = (lane & 7) + (((lane >> 4) & 1) << 3), blc = ((lane >> 3) & 1) << 3;
    int btr = (lane & 7) + (((lane >> 3) & 1) << 3), btc = ((lane >> 4) & 1) << 3;
    int c0 = (lane & 3) * 2;

    for (int mi = 0; mi < 4; mi++) {
        int m0 = mi * 128;
        __syncthreads();
        for (int i = tid; i < 1024; i += 256) {
            int row = i >> 3, u = i & 7;
            long gq = base + (long)(m0 + row) * 1536 + h * DH + u * 8;
            long gv = gq + 512;
            *reinterpret_cast<uint4*>(sm + FKH + row * 144 + u * 16) =
                *reinterpret_cast<const uint4*>(g_CTH + gq);
            *reinterpret_cast<uint4*>(sm + FKL + row * 144 + u * 16) =
                *reinterpret_cast<const uint4*>(g_CTL + gq);
            *reinterpret_cast<uint4*>(sm + FVH + row * 144 + u * 16) =
                *reinterpret_cast<const uint4*>(g_CTH + gv);
            *reinterpret_cast<uint4*>(sm + FVL + row * 144 + u * 16) =
                *reinterpret_cast<const uint4*>(g_CTL + gv);
        }
        __syncthreads();

        float S[16][4];
        #pragma unroll
        for (int i = 0; i < 16; i++)
            #pragma unroll
            for (int e = 0; e < 4; e++) S[i][e] = 0.f;

        #pragma unroll
        for (int kc = 0; kc < 4; kc++) {
            uint32_t qh[4], ql[4];
            uint32_t ao = sb + FQH + (uint32_t)(((w * 16 + alr) * FLDQ + kc * 16 + alc) * 2);
            LDM_X4(qh, ao);
            LDM_X4(ql, ao + (FQL - FQH));
            #pragma unroll
            for (int p = 0; p < 8; p++) {
                uint32_t kf[4], kl[4];
                uint32_t bo = sb + FKH + (uint32_t)(((p * 16 + blr) * FLDQ + kc * 16 + blc) * 2);
                LDM_X4(kf, bo);
                LDM_X4(kl, bo + (FKL - FKH));
                uint32_t b0[2] = {kf[0], kf[1]}, b1[2] = {kf[2], kf[3]};
                uint32_t b0l[2] = {kl[0], kl[1]}, b1l[2] = {kl[2], kl[3]};
                MMA16816(S[2*p],   qh, b0);  MMA16816(S[2*p],   qh, b0l); MMA16816(S[2*p],   ql, b0);
                MMA16816(S[2*p+1], qh, b1);  MMA16816(S[2*p+1], qh, b1l); MMA16816(S[2*p+1], ql, b1);
            }
        }

        float cmax[2] = {-1e30f, -1e30f};
        #pragma unroll
        for (int nt = 0; nt < 16; nt++)
            #pragma unroll
            for (int e = 0; e < 4; e++) {
                int col = m0 + nt * 8 + c0 + (e & 1);
                float v = S[nt][e] * 0.125f + mbias[col];
                S[nt][e] = v;
                cmax[e >> 1] = fmaxf(cmax[e >> 1], v);
            }
        #pragma unroll
        for (int o = 1; o <= 2; o <<= 1) {
            cmax[0] = fmaxf(cmax[0], __shfl_xor_sync(0xffffffffu, cmax[0], o));
            cmax[1] = fmaxf(cmax[1], __shfl_xor_sync(0xffffffffu, cmax[1], o));
        }
        float mn0 = fmaxf(mrow[0], cmax[0]), mn1 = fmaxf(mrow[1], cmax[1]);
        float a0 = __expf(mrow[0] - mn0), a1 = __expf(mrow[1] - mn1);
        mrow[0] = mn0; mrow[1] = mn1;
        lrow[0] *= a0; lrow[1] *= a1;
        #pragma unroll
        for (int i = 0; i < 8; i++) {
            O[i][0] *= a0; O[i][1] *= a0; O[i][2] *= a1; O[i][3] *= a1;
        }
        #pragma unroll
        for (int nt = 0; nt < 16; nt++)
            #pragma unroll
            for (int e = 0; e < 4; e++) {
                float p = __expf(S[nt][e] - ((e < 2) ? mn0 : mn1));
                S[nt][e] = p;
                lrow[e >> 1] += p;
            }

        #pragma unroll
        for (int kc = 0; kc < 8; kc++) {
            uint32_t ph[4], pl[4];
            pack_split2(S[2*kc][0],   S[2*kc][1],   ph[0], pl[0]);
            pack_split2(S[2*kc][2],   S[2*kc][3],   ph[1], pl[1]);
            pack_split2(S[2*kc+1][0], S[2*kc+1][1], ph[2], pl[2]);
            pack_split2(S[2*kc+1][2], S[2*kc+1][3], ph[3], pl[3]);
            #pragma unroll
            for (int p = 0; p < 4; p++) {
                uint32_t vh[4], vl[4];
                uint32_t bo = sb + FVH + (uint32_t)(((kc * 16 + btr) * FLDQ + p * 16 + btc) * 2);
                LDM_X4T(vh, bo);
                LDM_X4T(vl, bo + (FVL - FVH));
                uint32_t b0[2] = {vh[0], vh[1]}, b1[2] = {vh[2], vh[3]};
                uint32_t b0l[2] = {vl[0], vl[1]}, b1l[2] = {vl[2], vl[3]};
                MMA16816(O[2*p],   ph, b0);  MMA16816(O[2*p],   ph, b0l); MMA16816(O[2*p],   pl, b0);
                MMA16816(O[2*p+1], ph, b1);  MMA16816(O[2*p+1], ph, b1l); MMA16816(O[2*p+1], pl, b1);
            }
        }
    }

    #pragma unroll
    for (int o = 1; o <= 2; o <<= 1) {
        lrow[0] += __shfl_xor_sync(0xffffffffu, lrow[0], o);
        lrow[1] += __shfl_xor_sync(0xffffffffu, lrow[1], o);
    }
    float inv0 = 1.f / lrow[0], inv1 = 1.f / lrow[1];

    int r0g = l0 + w * 16 + (lane >> 2);
    #pragma unroll
    for (int nt = 0; nt < 8; nt++) {
        int col = h * DH + nt * 8 + c0;
        long o0 = ((long)b * 512 + r0g) * 512 + col;
        long o1 = o0 + 8 * 512;
        __nv_bfloat162 h0 = *reinterpret_cast<const __nv_bfloat162*>(g_AHb + o0);
        __nv_bfloat162 l0v = *reinterpret_cast<const __nv_bfloat162*>(g_ALb + o0);
        __nv_bfloat162 h1 = *reinterpret_cast<const __nv_bfloat162*>(g_AHb + o1);
        __nv_bfloat162 l1v = *reinterpret_cast<const __nv_bfloat162*>(g_ALb + o1);
        float d0 = bfadd(h0.x, l0v.x) + O[nt][0] * inv0;
        float d1 = bfadd(h0.y, l0v.y) + O[nt][1] * inv0;
        float d2 = bfadd(h1.x, l1v.x) + O[nt][2] * inv1;
        float d3 = bfadd(h1.y, l1v.y) + O[nt][3] * inv1;
        if (outp) {
            *reinterpret_cast<float2*>(outp + o0) = make_float2(d0, d1);
            *reinterpret_cast<float2*>(outp + o1) = make_float2(d2, d3);
        } else {
            __nv_bfloat16 hh[4], ll[4];
            bfsplit(d0, hh[0], ll[0]); bfsplit(d1, hh[1], ll[1]);
            bfsplit(d2, hh[2], ll[2]); bfsplit(d3, hh[3], ll[3]);
            *reinterpret_cast<__nv_bfloat162*>(g_AHb + o0) = __nv_bfloat162{hh[0], hh[1]};
            *reinterpret_cast<__nv_bfloat162*>(g_ALb + o0) = __nv_bfloat162{ll[0], ll[1]};
            *reinterpret_cast<__nv_bfloat162*>(g_AHb + o1) = __nv_bfloat162{hh[2], hh[3]};
            *reinterpret_cast<__nv_bfloat162*>(g_ALb + o1) = __nv_bfloat162{ll[2], ll[3]};
        }
    }
}

// ---------------- small kernels ------------------------------------------------
__global__ void h2_k(const float* __restrict__ se, const float* __restrict__ w2,
                     const float* __restrict__ b2)
{
    int bn = blockIdx.x;
    int n = bn % Nn;
    int h = threadIdx.x;
    const float* x = se + (long)bn * Dd;
    const float* w = w2 + (long)n * Dd * Dd;
    float acc = b2[n * Dd + h];
    for (int d = 0; d < Dd; d++) acc = fmaf(x[d], w[(long)d * Dd + h], acc);
    g_H2[(long)bn * Dd + h] = fmaxf(acc, 0.f);
}

__global__ void local_attn_k(const float* __restrict__ mask)
{
    int gw = (int)(((long)blockIdx.x * blockDim.x + threadIdx.x) >> 5);
    int lane = threadIdx.x & 31;
    if (gw >= Nn * Bb * Ll * Hh) return;
    int h = gw % Hh;
    int l = (gw / Hh) % Ll;
    int b = (gw / (Hh * Ll)) % Bb;
    int n = gw / (Hh * Ll * Bb);

    const __nv_bfloat16* CTH_ = g_CTH + (long)n * 8192 * 1536;
    const __nv_bfloat16* CTL_ = g_CTL + (long)n * 8192 * 1536;

    long ro = ((long)b * Ll + l) * 1536 + h * DH;
    float k0 = bfadd(CTH_[ro + 1024 + lane], CTL_[ro + 1024 + lane]);
    float k1 = bfadd(CTH_[ro + 1024 + lane + 32], CTL_[ro + 1024 + lane + 32]);

    float sc[15];
    #pragma unroll
    for (int j = 0; j < 15; j++) {
        int m = l + (j - KHALF);
        float s = -1e30f;
        if (m >= 0 && m < Ll && mask[(long)b * Ll + m] != 0.f) {
            long mo = ((long)b * Ll + m) * 1536 + h * DH;
            float q0 = bfadd(CTH_[mo + lane], CTL_[mo + lane]);
            float q1 = bfadd(CTH_[mo + lane + 32], CTL_[mo + lane + 32]);
            float d = k0 * q0 + k1 * q1;
            #pragma unroll
            for (int o = 16; o; o >>= 1) d += __shfl_xor_sync(0xffffffffu, d, o);
            s = d * 0.125f;
        }
        sc[j] = s;
    }
    float mx = -1e30f;
    #pragma unroll
    for (int j = 0; j < 15; j++) mx = fmaxf(mx, sc[j]);
    float w[15], sum = 0.f;
    #pragma unroll
    for (int j = 0; j < 15; j++) {
        w[j] = (sc[j] > -1e29f) ? expf(sc[j] - mx) : 0.f;
        sum += w[j];
    }
    float inv = 1.f / sum;
    float o0 = 0.f, o1 = 0.f;
    #pragma unroll
    for (int j = 0; j < 15; j++) {
        if (w[j] != 0.f) {
            int m = l + (j - KHALF);
            long mo = ((long)b * Ll + m) * 1536 + 512 + h * DH;
            float ww = w[j] * inv;
            o0 = fmaf(ww, bfadd(CTH_[mo + lane], CTL_[mo + lane]), o0);
            o1 = fmaf(ww, bfadd(CTH_[mo + lane + 32], CTL_[mo + lane + 32]), o1);
        }
    }
    long xo = (long)n * BLD + ((long)b * Ll + l) * Dd + h * DH;
    __nv_bfloat16* XH = g_MH + xo;
    __nv_bfloat16* XL = g_ML + xo;
    float x0 = bfadd(XH[lane], XL[lane]) + o0;
    float x1 = bfadd(XH[lane + 32], XL[lane + 32]) + o1;
    bfsplit(x0, XH[lane], XL[lane]);
    bfsplit(x1, XH[lane + 32], XL[lane + 32]);
}

__global__ void satt_k(const float* __restrict__ se, const float* __restrict__ w1,
                       const float* __restrict__ w2, float* __restrict__ out_tail)
{
    int b = blockIdx.x, t = threadIdx.x;
    __shared__ float red[256];
    __shared__ float alpha[Nn];
    for (int n = 0; n < Nn; n++) {
        const float* x = se + ((long)b * Nn + n) * Dd;
        float acc = 0.f;
        for (int d = 0; d < Dd; d++) acc = fmaf(x[d], w1[(long)d * AH + t], acc);
        red[t] = tanhf(acc) * w2[t];
        __syncthreads();
        for (int o = 128; o; o >>= 1) { if (t < o) red[t] += red[t + o]; __syncthreads(); }
        if (t == 0) alpha[n] = red[0];
        __syncthreads();
    }
    if (t == 0) {
        float mx = fmaxf(alpha[0], fmaxf(alpha[1], alpha[2]));
        float e[Nn], sum = 0.f;
        for (int n = 0; n < Nn; n++) { e[n] = expf(alpha[n] - mx); sum += e[n]; }
        for (int n = 0; n < Nn; n++) {
            float w = e[n] / sum;
            g_SW[b * Nn + n] = w;
            out_tail[b * Nn + n] = w;
        }
    }
}

__global__ void agg_k()
{
    long stride = (long)Ll * Dd;
    for (long i = (long)blockIdx.x * blockDim.x + threadIdx.x; i < BLD;
         i += (long)gridDim.x * blockDim.x) {
        int b = (int)(i / stride);
        float acc = 0.f;
        #pragma unroll
        for (int n = 0; n < Nn; n++)
            acc = fmaf(g_SW[b * Nn + n], bfadd(g_MH[(long)n * BLD + i], g_ML[(long)n * BLD + i]), acc);
        bfsplit(acc, g_AHb[i], g_ALb[i]);
    }
}

// ---------------- host orchestration ------------------------------------------
#define GSMEM 110624

static void mgemm(const __nv_bfloat16* Ah, const __nv_bfloat16* Al,
                  const __nv_bfloat16* Bh, const __nv_bfloat16* Bl,
                  const float* bias, const float* H2,
                  __nv_bfloat16* Ch, __nv_bfloat16* Cl,
                  int N, int K, int lda, int ldc, int batches,
                  long sAi, long sBi, long sCi, long sBias, int flags)
{
    dim3 grid(N / 128, 64, batches);
    mma_gemm_k<<<grid, 256, GSMEM>>>(Ah, Al, Bh, Bl, bias, H2, Ch, Cl, K,
                                     lda, ldc, sAi, sBi, sCi, sBias, flags);
}

extern "C" void kernel_launch(void* const* d_in, const int* in_sizes, int n_in,
                              void* d_out, int out_size)
{
    const float* seg   = (const float*)d_in[0];
    const float* mask  = (const float*)d_in[1];
    const float* se    = (const float*)d_in[2];
    const float* hw1   = (const float*)d_in[3];
    const float* hb1   = (const float*)d_in[4];
    const float* hw2   = (const float*)d_in[5];
    const float* hb2   = (const float*)d_in[6];
    const float* hw3   = (const float*)d_in[7];
    const float* hb3   = (const float*)d_in[8];
    const float* lcW   = (const float*)d_in[9];
    const float* lcb   = (const float*)d_in[10];
    const float* lvW   = (const float*)d_in[11];
    const float* lvb   = (const float*)d_in[12];
    const float* gcW   = (const float*)d_in[13];
    const float* gcb   = (const float*)d_in[14];
    const float* gvW   = (const float*)d_in[15];
    const float* gvb   = (const float*)d_in[16];
    const float* sw1   = (const float*)d_in[17];
    const float* sw2   = (const float*)d_in[18];
    float* out = (float*)d_out;

    cudaFuncSetAttribute(mma_gemm_k, cudaFuncAttributeMaxDynamicSharedMemorySize, GSMEM);
    cudaFuncSetAttribute(flash_k,    cudaFuncAttributeMaxDynamicSharedMemorySize, FSMEM);

    __nv_bfloat16 *pSegH, *pSegL, *pWH, *pWL, *pB1H, *pB1L, *pMH, *pML,
                  *pCTH, *pCTL, *pAH, *pAL;
    float *pBias, *pH2;
    cudaGetSymbolAddress((void**)&pSegH, g_segH); cudaGetSymbolAddress((void**)&pSegL, g_segL);
    cudaGetSymbolAddress((void**)&pWH, g_WH);     cudaGetSymbolAddress((void**)&pWL, g_WL);
    cudaGetSymbolAddress((void**)&pB1H, g_B1H);   cudaGetSymbolAddress((void**)&pB1L, g_B1L);
    cudaGetSymbolAddress((void**)&pMH, g_MH);     cudaGetSymbolAddress((void**)&pML, g_ML);
    cudaGetSymbolAddress((void**)&pCTH, g_CTH);   cudaGetSymbolAddress((void**)&pCTL, g_CTL);
    cudaGetSymbolAddress((void**)&pAH, g_AHb);    cudaGetSymbolAddress((void**)&pAL, g_ALb);
    cudaGetSymbolAddress((void**)&pBias, g_biasC);
    cudaGetSymbolAddress((void**)&pH2, g_H2);

    const long CTN = 8192L * 1536;

    // prepasses
    split_k<<<1024, 256>>>(seg, pSegH, pSegL, BLD);
    wtile_k<<<512, 256>>>(hw1, pWH + OFF_HW1, pWL + OFF_HW1, 512, 0, 262144L, 786432L);
    wtile_k<<<512, 256>>>(hw3, pWH + OFF_HW3, pWL + OFF_HW3, 512, 0, 262144L, 786432L);
    wtile_k<<<1024, 256>>>(lcW, pWH + OFF_LCV, pWL + OFF_LCV, 1024, 0, 786432L, 3145728L);
    wtile_k<<<512, 256>>>(lvW, pWH + OFF_LCV, pWL + OFF_LCV, 512, 1024, 786432L, 1572864L);
    wtile_k<<<512, 256>>>(gcW, pWH + OFF_GCV, pWL + OFF_GCV, 1024, 0, 786432L, 1048576L);
    wtile_k<<<512, 256>>>(gvW, pWH + OFF_GCV, pWL + OFF_GCV, 512, 1024, 786432L, 524288L);
    biascat_k<<<8, 256>>>(lcb, lvb, gcb, gvb);

    // 1) h2
    h2_k<<<Bb * Nn, Dd>>>(se, hw2, hb2);

    // 2) h1 = relu(seg @ w1 + b1) * h2   (mulh2 fused into epilogue)
    mgemm(pSegH, pSegL, pWH + OFF_HW1, pWL + OFF_HW1, hb1, pH2, pB1H, pB1L,
          512, 512, 512, 512, Nn, 0, 262144L, BLD, 512, 2 | 8);

    // 3) m = relu(h1m @ w3 + b3)
    mgemm(pB1H, pB1L, pWH + OFF_HW3, pWL + OFF_HW3, hb3, nullptr, pMH, pML,
          512, 512, 512, 512, Nn, BLD, 262144L, BLD, 512, 2);

    // 4) local NL: fused [cW|vW] projection + banded attn, batched over n
    for (int s = 0; s < 2; s++) {
        mgemm(pMH, pML, pWH + OFF_LCV + (long)s * 786432, pWL + OFF_LCV + (long)s * 786432,
              pBias + s * 1536, nullptr, pCTH, pCTL,
              1536, 512, 512, 1536, Nn, BLD, 2L * 786432, CTN, 3072, 0);
        local_attn_k<<<Nn * Bb * Ll * Hh * 32 / 128, 128>>>(mask);
    }

    // 5) segment attention weights
    satt_k<<<Bb, AH>>>(se, sw1, sw2, out + BLD);

    // 6) aggregate
    agg_k<<<4096, 256>>>();

    // 7) global NL: fused projection + flash attention (final stage writes out)
    for (int s = 0; s < 2; s++) {
        mgemm(pAH, pAL, pWH + OFF_GCV + (long)s * 786432, pWL + OFF_GCV + (long)s * 786432,
              pBias + (6 + s) * 1536, nullptr, pCTH, pCTL,
              1536, 512, 512, 1536, 1, 0, 0, 0, 0, 0);
        flash_k<<<dim3(Ll / 128, Bb * Hh), 256, FSMEM>>>(mask, (s == 1) ? out : nullptr);
    }
}

// round 8
// speedup vs baseline: 2.3667x; 1.8017x over previous
#include <cuda_runtime.h>
#include <cuda_fp16.h>
#include <math.h>
#include <stdint.h>

#define Bb 16
#define Ll 512
#define Dd 512
#define Nn 3
#define Hh 8
#define DH 64
#define AH 256
#define KHALF 7

#define BLD 4194304L        // Bb*Ll*Dd
#define CTN 12582912L       // 8192*1536 per n
#define CTSZ 37748736L      // 3 * CTN

// ---------------- scratch ------------------------------------------------------
__device__ __half g_seg[BLD];
__device__ __half g_WH[7864320], g_WL[7864320];   // fp16 hi/lo, tiled 32x128 blocks
__device__ __half g_B1[3*BLD];
__device__ __half g_M [3*BLD];
__device__ __half g_CT[CTSZ];                     // [n][8192][1536] mq|mv|mk
__device__ __half g_A [BLD];
__device__ float g_H2[Bb*Nn*Dd];
__device__ float g_SW[Bb*Nn];
__device__ float g_biasC[8*1536];

#define OFF_HW1 0L
#define OFF_HW3 786432L
#define OFF_LCV 1572864L
#define OFF_GCV 6291456L

// ---------------- PTX helpers --------------------------------------------------
__device__ __forceinline__ uint32_t smem_u32(const void* p) {
    uint32_t a;
    asm("{ .reg .u64 t; cvta.to.shared.u64 t, %1; cvt.u32.u64 %0, t; }" : "=r"(a) : "l"(p));
    return a;
}
#define CPA16(dst, src) asm volatile( \
    "cp.async.ca.shared.global [%0], [%1], 16;" :: "r"(dst), "l"(__cvta_generic_to_global(src)))
#define CPA_COMMIT() asm volatile("cp.async.commit_group;" ::: "memory")
#define CPA_WAIT1()  asm volatile("cp.async.wait_group 1;" ::: "memory")

#define BULK(dst, src, sz, mb) asm volatile( \
    "cp.async.bulk.shared::cta.global.mbarrier::complete_tx::bytes [%0], [%1], %2, [%3];" \
    :: "r"(dst), "l"(__cvta_generic_to_global(src)), "r"((uint32_t)(sz)), "r"(mb) : "memory")

#define MBAR_INIT(mb, c)   asm volatile("mbarrier.init.shared.b64 [%0], %1;" :: "r"(mb), "r"((uint32_t)(c)) : "memory")
#define MBAR_EXPECT(mb, tx) asm volatile("mbarrier.arrive.expect_tx.shared.b64 _, [%0], %1;" :: "r"(mb), "r"((uint32_t)(tx)) : "memory")
#define FENCE_ASYNC_SHARED() asm volatile("fence.proxy.async.shared::cta;" ::: "memory")
#define MBAR_WAIT(mb, ph) do { \
    uint32_t _m = (mb), _p = (ph), _d; \
    asm volatile("{\n\t.reg .pred p;\n\tmbarrier.try_wait.parity.acquire.cta.shared::cta.b64 p, [%1], %2;\n\tselp.b32 %0, 1, 0, p;\n\t}" \
        : "=r"(_d) : "r"(_m), "r"(_p) : "memory"); \
    if (!_d) { \
        asm volatile("{\n\t.reg .pred P1;\n\tWL_%=:\n\tmbarrier.try_wait.parity.acquire.cta.shared::cta.b64 P1, [%0], %1, 0x989680;\n\t@P1 bra.uni WD_%=;\n\tbra.uni WL_%=;\n\tWD_%=:\n\t}" \
            :: "r"(_m), "r"(_p) : "memory"); \
    } } while (0)

#define LDM_X4(r, a) asm volatile( \
    "ldmatrix.sync.aligned.m8n8.x4.shared.b16 {%0,%1,%2,%3}, [%4];" \
    : "=r"((r)[0]),"=r"((r)[1]),"=r"((r)[2]),"=r"((r)[3]) : "r"(a))
#define LDM_X4T(r, a) asm volatile( \
    "ldmatrix.sync.aligned.m8n8.x4.trans.shared.b16 {%0,%1,%2,%3}, [%4];" \
    : "=r"((r)[0]),"=r"((r)[1]),"=r"((r)[2]),"=r"((r)[3]) : "r"(a))
#define MMAF16(d, a, b) asm volatile( \
    "mma.sync.aligned.m16n8k16.row.col.f32.f16.f16.f32 " \
    "{%0,%1,%2,%3}, {%4,%5,%6,%7}, {%8,%9}, {%0,%1,%2,%3};" \
    : "+f"((d)[0]),"+f"((d)[1]),"+f"((d)[2]),"+f"((d)[3]) \
    : "r"((a)[0]),"r"((a)[1]),"r"((a)[2]),"r"((a)[3]), "r"((b)[0]),"r"((b)[1]))

__device__ __forceinline__ uint32_t packh2(float a, float b) {
    __half2 t = __floats2half2_rn(a, b);
    return *reinterpret_cast<uint32_t*>(&t);
}

// ---------------- prepasses ----------------------------------------------------
__global__ void cvt_k(const float* __restrict__ s, __half* __restrict__ d, long n)
{
    for (long i = ((long)blockIdx.x * blockDim.x + threadIdx.x) * 4; i < n;
         i += (long)gridDim.x * blockDim.x * 4) {
        float4 v = *reinterpret_cast<const float4*>(s + i);
        uint2 o;
        o.x = packh2(v.x, v.y);
        o.y = packh2(v.z, v.w);
        *reinterpret_cast<uint2*>(d + i) = o;
    }
}

// weights -> tiled fp16 hi/lo blocks (same layout as R7): block (nb,kc) = 4096 elems
__global__ void wtile_k(const float* __restrict__ s, __half* __restrict__ h,
                        __half* __restrict__ l, int C1, int off, long ds, long total)
{
    long sS = 512L * C1;
    for (long i = ((long)blockIdx.x * blockDim.x + threadIdx.x) * 4; i < total;
         i += (long)gridDim.x * blockDim.x * 4) {
        float4 v = *reinterpret_cast<const float4*>(s + i);
        long sl = i / sS;
        long rem = i - sl * sS;
        int k = (int)(rem / C1), c = (int)(rem - (long)(rem / C1) * C1);
        int n = off + c;
        long d = sl * ds + ((long)((n >> 7) * 16 + (k >> 5))) * 4096
               + (k & 31) * 128 + ((((n & 127) >> 3) ^ (k & 7)) << 3) + (n & 7);
        float vv[4] = {v.x, v.y, v.z, v.w};
        #pragma unroll
        for (int e = 0; e < 4; e++) {
            __half hh = __float2half_rn(vv[e]);
            __half ll = __float2half_rn(vv[e] - __half2float(hh));
            h[d + e] = hh;
            l[d + e] = ll;
        }
    }
}

__global__ void biascat_k(const float* __restrict__ lcb, const float* __restrict__ lvb,
                          const float* __restrict__ gcb, const float* __restrict__ gvb)
{
    int slot = blockIdx.x;
    for (int c = threadIdx.x; c < 1536; c += blockDim.x) {
        float v;
        if (slot < 6) v = (c < 1024) ? lcb[slot * 1024 + c] : lvb[slot * 512 + c - 1024];
        else {
            int s = slot - 6;
            v = (c < 1024) ? gcb[s * 1024 + c] : gvb[s * 512 + c - 1024];
        }
        g_biasC[slot * 1536 + c] = v;
    }
}

// ---------------- GEMM: fp16 A (single) x fp16 hi/lo B, 2 MMAs, BN=256 ---------
// flags: 2=relu, 8=mul by H2
#define GSMEM 129056
__global__ void __launch_bounds__(256, 1) mma_gemm_k(
    const __half* __restrict__ A, const __half* __restrict__ WH,
    const __half* __restrict__ WL, const float* __restrict__ bias,
    const float* __restrict__ H2, __half* __restrict__ C,
    int K, int lda, int ldc,
    long sAi, long sBi, long sCi, long sBias, int flags)
{
    constexpr int LDS = 40;                    // fp16 elems per A row
    constexpr int A_BYTES = 128 * LDS * 2;     // 10240
    constexpr int B_BYTES = 16384;             // hi (two 128-col blocks)
    constexpr int STAGE = A_BYTES + 2 * B_BYTES;   // 43008
    extern __shared__ char dsm[];
    uint32_t sb0 = smem_u32(dsm);
    uint32_t mbar0 = sb0 + 3 * STAGE;

    int z = blockIdx.z;
    A  += z * sAi;
    WH += z * sBi;  WL += z * sBi;
    C  += z * sCi;
    if (bias) bias += z * sBias;

    int tid = threadIdx.x, lane = tid & 31, wid = tid >> 5;
    int wm = wid & 1, wn = wid >> 1;
    int m0 = blockIdx.y * 128;
    int bx = blockIdx.x, n0 = bx * 256;
    int nc = K / 32;

    if (tid == 0) {
        MBAR_INIT(mbar0, 1); MBAR_INIT(mbar0 + 8, 1); MBAR_INIT(mbar0 + 16, 1);
        FENCE_ASYNC_SHARED();
    }
    __syncthreads();

    auto fillA = [&](int c) {
        int k0 = c * 32;
        uint32_t st = sb0 + (c % 3) * STAGE;
        #pragma unroll
        for (int it = 0; it < 2; it++) {
            int idx = tid + it * 256;
            int row = idx >> 2, u = idx & 3;
            CPA16(st + row * 80 + u * 16, A + (long)(m0 + row) * lda + k0 + u * 8);
        }
    };
    auto fillB = [&](int c) {
        uint32_t st = sb0 + (c % 3) * STAGE + A_BYTES;
        uint32_t mb = mbar0 + (c % 3) * 8;
        MBAR_EXPECT(mb, 32768u);
        long off0 = ((long)(bx * 2) * nc + c) * 4096;
        long off1 = ((long)(bx * 2 + 1) * nc + c) * 4096;
        BULK(st,                  WH + off0, 8192, mb);
        BULK(st + 8192,           WH + off1, 8192, mb);
        BULK(st + B_BYTES,        WL + off0, 8192, mb);
        BULK(st + B_BYTES + 8192, WL + off1, 8192, mb);
    };

    float acc[4][8][4] = {};

    fillA(0); CPA_COMMIT();
    fillA(1); CPA_COMMIT();
    if (tid == 0) { fillB(0); fillB(1); }

    int alr = lane & 15, alc = (lane >> 4) << 3;
    int btr = (lane & 7) + (((lane >> 3) & 1) << 3);
    int btcc = (lane >> 4) & 1;

    for (int c = 0; c < nc; c++) {
        CPA_WAIT1();
        MBAR_WAIT(mbar0 + (c % 3) * 8, (c / 3) & 1);
        __syncthreads();
        if (c + 2 < nc) { fillA(c + 2); if (tid == 0) fillB(c + 2); }
        CPA_COMMIT();

        uint32_t base = sb0 + (c % 3) * STAGE;
        uint32_t aA = base + ((wm * 64 + alr) * LDS + alc) * 2;
        uint32_t bB = base + A_BYTES + (wn >> 1) * 8192;

        #pragma unroll
        for (int kk = 0; kk < 2; kk++) {
            uint32_t ah[4][4], bh[8][2], bl[8][2];
            #pragma unroll
            for (int mt = 0; mt < 4; mt++)
                LDM_X4(ah[mt], aA + (uint32_t)((mt * 16 * LDS + kk * 16) * 2));
            int krow = kk * 16 + btr;
            #pragma unroll
            for (int p = 0; p < 4; p++) {
                int c16 = (wn & 1) * 8 + p * 2 + btcc;
                uint32_t ad = bB + (uint32_t)(krow * 256 + ((c16 ^ (krow & 7)) << 4));
                uint32_t r[4];
                LDM_X4T(r, ad);
                bh[2*p][0]=r[0]; bh[2*p][1]=r[1]; bh[2*p+1][0]=r[2]; bh[2*p+1][1]=r[3];
                LDM_X4T(r, ad + B_BYTES);
                bl[2*p][0]=r[0]; bl[2*p][1]=r[1]; bl[2*p+1][0]=r[2]; bl[2*p+1][1]=r[3];
            }
            #pragma unroll
            for (int mt = 0; mt < 4; mt++)
                #pragma unroll
                for (int nt = 0; nt < 8; nt++) {
                    MMAF16(acc[mt][nt], ah[mt], bh[nt]);
                    MMAF16(acc[mt][nt], ah[mt], bl[nt]);
                }
        }
    }

    const float* H2b = (flags & 8) ? (H2 + ((long)(m0 >> 9) * Nn + z) * 512) : nullptr;

    #pragma unroll
    for (int mt = 0; mt < 4; mt++) {
        int row = m0 + wm * 64 + mt * 16 + (lane >> 2);
        #pragma unroll
        for (int nt = 0; nt < 8; nt++) {
            int col = n0 + wn * 64 + nt * 8 + (lane & 3) * 2;
            float d0 = acc[mt][nt][0], d1 = acc[mt][nt][1];
            float d2 = acc[mt][nt][2], d3 = acc[mt][nt][3];
            if (bias) {
                float b0 = bias[col], b1 = bias[col + 1];
                d0 += b0; d1 += b1; d2 += b0; d3 += b1;
            }
            if (flags & 2) {
                d0 = fmaxf(d0, 0.f); d1 = fmaxf(d1, 0.f);
                d2 = fmaxf(d2, 0.f); d3 = fmaxf(d3, 0.f);
            }
            if (H2b) {
                float f0 = H2b[col], f1 = H2b[col + 1];
                d0 *= f0; d1 *= f1; d2 *= f0; d3 *= f1;
            }
            long o0 = (long)row * ldc + col;
            long o1 = o0 + (long)8 * ldc;
            *reinterpret_cast<uint32_t*>(C + o0) = packh2(d0, d1);
            *reinterpret_cast<uint32_t*>(C + o1) = packh2(d2, d3);
        }
    }
}

// ---------------- flash global attention (fp16 single, 1 MMA/product) ----------
#define FQ 0
#define FK 18432
#define FV 36864
#define FMSK 55296
#define FSMEM 57344
#define FLDQ 72

__global__ void __launch_bounds__(256, 1) flash_k(const float* __restrict__ mask,
                                                  float* __restrict__ outp)
{
    extern __shared__ char sm[];
    uint32_t sb = smem_u32(sm);
    float* mbias = reinterpret_cast<float*>(sm + FMSK);
    int tid = threadIdx.x, lane = tid & 31, w = tid >> 5;
    int b = blockIdx.y >> 3, h = blockIdx.y & 7;
    int l0 = blockIdx.x * 128;
    long base = (long)b * 512 * 1536;

    for (int i = tid; i < 1024; i += 256) {
        int row = i >> 3, u = i & 7;
        *reinterpret_cast<uint4*>(sm + FQ + row * 144 + u * 16) =
            *reinterpret_cast<const uint4*>(g_CT + base + (long)(l0 + row) * 1536 + 1024 + h * DH + u * 8);
    }
    for (int i = tid; i < 512; i += 256)
        mbias[i] = (mask[(long)b * 512 + i] != 0.f) ? 0.f : -1e9f;

    float O[8][4];
    #pragma unroll
    for (int i = 0; i < 8; i++)
        #pragma unroll
        for (int e = 0; e < 4; e++) O[i][e] = 0.f;
    float mrow[2] = {-1e30f, -1e30f}, lrow[2] = {0.f, 0.f};

    int alr = lane & 15, alc = (lane >> 4) << 3;
    int blr = (lane & 7) + (((lane >> 4) & 1) << 3), blc = ((lane >> 3) & 1) << 3;
    int btr = (lane & 7) + (((lane >> 3) & 1) << 3), btc = ((lane >> 4) & 1) << 3;
    int c0 = (lane & 3) * 2;

    for (int mi = 0; mi < 4; mi++) {
        int m0 = mi * 128;
        __syncthreads();
        for (int i = tid; i < 1024; i += 256) {
            int row = i >> 3, u = i & 7;
            long gq = base + (long)(m0 + row) * 1536 + h * DH + u * 8;
            *reinterpret_cast<uint4*>(sm + FK + row * 144 + u * 16) =
                *reinterpret_cast<const uint4*>(g_CT + gq);
            *reinterpret_cast<uint4*>(sm + FV + row * 144 + u * 16) =
                *reinterpret_cast<const uint4*>(g_CT + gq + 512);
        }
        __syncthreads();

        float S[16][4];
        #pragma unroll
        for (int i = 0; i < 16; i++)
            #pragma unroll
            for (int e = 0; e < 4; e++) S[i][e] = 0.f;

        #pragma unroll
        for (int kc = 0; kc < 4; kc++) {
            uint32_t q[4];
            LDM_X4(q, sb + FQ + (uint32_t)(((w * 16 + alr) * FLDQ + kc * 16 + alc) * 2));
            #pragma unroll
            for (int p = 0; p < 8; p++) {
                uint32_t kf[4];
                LDM_X4(kf, sb + FK + (uint32_t)(((p * 16 + blr) * FLDQ + kc * 16 + blc) * 2));
                uint32_t b0[2] = {kf[0], kf[1]}, b1[2] = {kf[2], kf[3]};
                MMAF16(S[2*p],   q, b0);
                MMAF16(S[2*p+1], q, b1);
            }
        }

        float cmax[2] = {-1e30f, -1e30f};
        #pragma unroll
        for (int nt = 0; nt < 16; nt++)
            #pragma unroll
            for (int e = 0; e < 4; e++) {
                int col = m0 + nt * 8 + c0 + (e & 1);
                float v = S[nt][e] * 0.125f + mbias[col];
                S[nt][e] = v;
                cmax[e >> 1] = fmaxf(cmax[e >> 1], v);
            }
        #pragma unroll
        for (int o = 1; o <= 2; o <<= 1) {
            cmax[0] = fmaxf(cmax[0], __shfl_xor_sync(0xffffffffu, cmax[0], o));
            cmax[1] = fmaxf(cmax[1], __shfl_xor_sync(0xffffffffu, cmax[1], o));
        }
        float mn0 = fmaxf(mrow[0], cmax[0]), mn1 = fmaxf(mrow[1], cmax[1]);
        float a0 = __expf(mrow[0] - mn0), a1 = __expf(mrow[1] - mn1);
        mrow[0] = mn0; mrow[1] = mn1;
        lrow[0] *= a0; lrow[1] *= a1;
        #pragma unroll
        for (int i = 0; i < 8; i++) {
            O[i][0] *= a0; O[i][1] *= a0; O[i][2] *= a1; O[i][3] *= a1;
        }
        #pragma unroll
        for (int nt = 0; nt < 16; nt++)
            #pragma unroll
            for (int e = 0; e < 4; e++) {
                float p = __expf(S[nt][e] - ((e < 2) ? mn0 : mn1));
                S[nt][e] = p;
                lrow[e >> 1] += p;
            }

        #pragma unroll
        for (int kc = 0; kc < 8; kc++) {
            uint32_t ph[4];
            ph[0] = packh2(S[2*kc][0],   S[2*kc][1]);
            ph[1] = packh2(S[2*kc][2],   S[2*kc][3]);
            ph[2] = packh2(S[2*kc+1][0], S[2*kc+1][1]);
            ph[3] = packh2(S[2*kc+1][2], S[2*kc+1][3]);
            #pragma unroll
            for (int p = 0; p < 4; p++) {
                uint32_t vh[4];
                LDM_X4T(vh, sb + FV + (uint32_t)(((kc * 16 + btr) * FLDQ + p * 16 + btc) * 2));
                uint32_t b0[2] = {vh[0], vh[1]}, b1[2] = {vh[2], vh[3]};
                MMAF16(O[2*p],   ph, b0);
                MMAF16(O[2*p+1], ph, b1);
            }
        }
    }

    #pragma unroll
    for (int o = 1; o <= 2; o <<= 1) {
        lrow[0] += __shfl_xor_sync(0xffffffffu, lrow[0], o);
        lrow[1] += __shfl_xor_sync(0xffffffffu, lrow[1], o);
    }
    float inv0 = 1.f / lrow[0], inv1 = 1.f / lrow[1];

    int r0g = l0 + w * 16 + (lane >> 2);
    #pragma unroll
    for (int nt = 0; nt < 8; nt++) {
        int col = h * DH + nt * 8 + c0;
        long o0 = ((long)b * 512 + r0g) * 512 + col;
        long o1 = o0 + 8 * 512;
        __half2 x0 = *reinterpret_cast<const __half2*>(g_A + o0);
        __half2 x1 = *reinterpret_cast<const __half2*>(g_A + o1);
        float d0 = __low2float(x0) + O[nt][0] * inv0;
        float d1 = __high2float(x0) + O[nt][1] * inv0;
        float d2 = __low2float(x1) + O[nt][2] * inv1;
        float d3 = __high2float(x1) + O[nt][3] * inv1;
        if (outp) {
            *reinterpret_cast<float2*>(outp + o0) = make_float2(d0, d1);
            *reinterpret_cast<float2*>(outp + o1) = make_float2(d2, d3);
        } else {
            *reinterpret_cast<uint32_t*>(g_A + o0) = packh2(d0, d1);
            *reinterpret_cast<uint32_t*>(g_A + o1) = packh2(d2, d3);
        }
    }
}

// ---------------- tiled banded local attention ---------------------------------
// smem: mk[128][64] @0 (16384), mq[142][64] @16384, mv[142][64] @34816, bias @53248
#define LSM_MQ 16384
#define LSM_MV 34816
#define LSM_BI 53248
#define LSMEM 53824

__global__ void __launch_bounds__(256, 1) local_attn_k(const float* __restrict__ mask)
{
    extern __shared__ char sm[];
    float* sBias = reinterpret_cast<float*>(sm + LSM_BI);
    int tid = threadIdx.x, lane = tid & 31, w = tid >> 5;
    int b = blockIdx.y >> 3, h = blockIdx.y & 7;
    int n = blockIdx.z;
    int l0 = blockIdx.x * 128;
    long base = (long)n * CTN + (long)b * 512 * 1536;

    for (int i = tid; i < 1024; i += 256) {       // mk rows l0..l0+127
        int row = i >> 3, u = i & 7;
        *reinterpret_cast<uint4*>(sm + row * 128 + u * 16) =
            *reinterpret_cast<const uint4*>(g_CT + base + (long)(l0 + row) * 1536 + 1024 + h * DH + u * 8);
    }
    for (int i = tid; i < 142 * 8; i += 256) {    // mq/mv rows l0-7..l0+134
        int r = i >> 3, u = i & 7;
        int m = l0 - 7 + r;
        if (m >= 0 && m < 512) {
            long g = base + (long)m * 1536 + h * DH + u * 8;
            *reinterpret_cast<uint4*>(sm + LSM_MQ + r * 128 + u * 16) =
                *reinterpret_cast<const uint4*>(g_CT + g);
            *reinterpret_cast<uint4*>(sm + LSM_MV + r * 128 + u * 16) =
                *reinterpret_cast<const uint4*>(g_CT + g + 512);
        }
    }
    for (int i = tid; i < 142; i += 256) {
        int m = l0 - 7 + i;
        sBias[i] = (m >= 0 && m < 512) ? mask[(long)b * 512 + m] : 0.f;
    }
    __syncthreads();

    for (int j = 0; j < 16; j++) {
        int l = l0 + w * 16 + j;
        int lr = l - l0;
        __half2 kv = *reinterpret_cast<const __half2*>(sm + lr * 128 + lane * 4);
        float k0f = __low2float(kv), k1f = __high2float(kv);

        float sc[15];
        #pragma unroll
        for (int jj = 0; jj < 15; jj++) {
            int r = lr + jj;
            float s = -1e30f;
            if (sBias[r] != 0.f) {
                __half2 q = *reinterpret_cast<const __half2*>(sm + LSM_MQ + r * 128 + lane * 4);
                float d = k0f * __low2float(q) + k1f * __high2float(q);
                #pragma unroll
                for (int o = 16; o; o >>= 1) d += __shfl_xor_sync(0xffffffffu, d, o);
                s = d * 0.125f;
            }
            sc[jj] = s;
        }
        float mx = -1e30f;
        #pragma unroll
        for (int jj = 0; jj < 15; jj++) mx = fmaxf(mx, sc[jj]);
        float wgt[15], sum = 0.f;
        #pragma unroll
        for (int jj = 0; jj < 15; jj++) {
            wgt[jj] = (sc[jj] > -1e29f) ? expf(sc[jj] - mx) : 0.f;
            sum += wgt[jj];
        }
        float inv = 1.f / sum;
        float o0 = 0.f, o1 = 0.f;
        #pragma unroll
        for (int jj = 0; jj < 15; jj++) {
            if (wgt[jj] != 0.f) {
                int r = lr + jj;
                __half2 v = *reinterpret_cast<const __half2*>(sm + LSM_MV + r * 128 + lane * 4);
                float ww = wgt[jj] * inv;
                o0 = fmaf(ww, __low2float(v), o0);
                o1 = fmaf(ww, __high2float(v), o1);
            }
        }
        long xo = (long)n * BLD + ((long)b * 512 + l) * 512 + h * DH + lane * 2;
        __half2 xv = *reinterpret_cast<const __half2*>(g_M + xo);
        *reinterpret_cast<uint32_t*>(g_M + xo) =
            packh2(__low2float(xv) + o0, __high2float(xv) + o1);
    }
}

// ---------------- small kernels ------------------------------------------------
__global__ void h2_k(const float* __restrict__ se, const float* __restrict__ w2,
                     const float* __restrict__ b2)
{
    int bn = blockIdx.x;
    int n = bn % Nn;
    int h = threadIdx.x;
    const float* x = se + (long)bn * Dd;
    const float* w = w2 + (long)n * Dd * Dd;
    float acc = b2[n * Dd + h];
    for (int d = 0; d < Dd; d++) acc = fmaf(x[d], w[(long)d * Dd + h], acc);
    g_H2[(long)bn * Dd + h] = fmaxf(acc, 0.f);
}

__global__ void satt_k(const float* __restrict__ se, const float* __restrict__ w1,
                       const float* __restrict__ w2, float* __restrict__ out_tail)
{
    int b = blockIdx.x, t = threadIdx.x;
    __shared__ float red[256];
    __shared__ float alpha[Nn];
    for (int n = 0; n < Nn; n++) {
        const float* x = se + ((long)b * Nn + n) * Dd;
        float acc = 0.f;
        for (int d = 0; d < Dd; d++) acc = fmaf(x[d], w1[(long)d * AH + t], acc);
        red[t] = tanhf(acc) * w2[t];
        __syncthreads();
        for (int o = 128; o; o >>= 1) { if (t < o) red[t] += red[t + o]; __syncthreads(); }
        if (t == 0) alpha[n] = red[0];
        __syncthreads();
    }
    if (t == 0) {
        float mx = fmaxf(alpha[0], fmaxf(alpha[1], alpha[2]));
        float e[Nn], sum = 0.f;
        for (int n = 0; n < Nn; n++) { e[n] = expf(alpha[n] - mx); sum += e[n]; }
        for (int n = 0; n < Nn; n++) {
            float w = e[n] / sum;
            g_SW[b * Nn + n] = w;
            out_tail[b * Nn + n] = w;
        }
    }
}

__global__ void agg_k()
{
    long half_total = BLD / 2;
    long stride = (long)Ll * Dd / 2;
    for (long i = (long)blockIdx.x * blockDim.x + threadIdx.x; i < half_total;
         i += (long)gridDim.x * blockDim.x) {
        int b = (int)(i / stride);
        float a0 = 0.f, a1 = 0.f;
        #pragma unroll
        for (int n = 0; n < Nn; n++) {
            float sw = g_SW[b * Nn + n];
            __half2 v = *reinterpret_cast<const __half2*>(g_M + (long)n * BLD + i * 2);
            a0 = fmaf(sw, __low2float(v), a0);
            a1 = fmaf(sw, __high2float(v), a1);
        }
        *reinterpret_cast<uint32_t*>(g_A + i * 2) = packh2(a0, a1);
    }
}

// ---------------- host orchestration ------------------------------------------
static void mgemm(const __half* A, const __half* WH, const __half* WL,
                  const float* bias, const float* H2, __half* C,
                  int N, int K, int lda, int ldc, int batches,
                  long sAi, long sBi, long sCi, long sBias, int flags)
{
    dim3 grid(N / 256, 64, batches);
    mma_gemm_k<<<grid, 256, GSMEM>>>(A, WH, WL, bias, H2, C, K,
                                     lda, ldc, sAi, sBi, sCi, sBias, flags);
}

extern "C" void kernel_launch(void* const* d_in, const int* in_sizes, int n_in,
                              void* d_out, int out_size)
{
    const float* seg   = (const float*)d_in[0];
    const float* mask  = (const float*)d_in[1];
    const float* se    = (const float*)d_in[2];
    const float* hw1   = (const float*)d_in[3];
    const float* hb1   = (const float*)d_in[4];
    const float* hw2   = (const float*)d_in[5];
    const float* hb2   = (const float*)d_in[6];
    const float* hw3   = (const float*)d_in[7];
    const float* hb3   = (const float*)d_in[8];
    const float* lcW   = (const float*)d_in[9];
    const float* lcb   = (const float*)d_in[10];
    const float* lvW   = (const float*)d_in[11];
    const float* lvb   = (const float*)d_in[12];
    const float* gcW   = (const float*)d_in[13];
    const float* gcb   = (const float*)d_in[14];
    const float* gvW   = (const float*)d_in[15];
    const float* gvb   = (const float*)d_in[16];
    const float* sw1   = (const float*)d_in[17];
    const float* sw2   = (const float*)d_in[18];
    float* out = (float*)d_out;

    cudaFuncSetAttribute(mma_gemm_k,   cudaFuncAttributeMaxDynamicSharedMemorySize, GSMEM);
    cudaFuncSetAttribute(flash_k,      cudaFuncAttributeMaxDynamicSharedMemorySize, FSMEM);
    cudaFuncSetAttribute(local_attn_k, cudaFuncAttributeMaxDynamicSharedMemorySize, LSMEM);

    __half *pSeg, *pWH, *pWL, *pB1, *pM, *pCT, *pA;
    float *pBias, *pH2;
    cudaGetSymbolAddress((void**)&pSeg, g_seg);
    cudaGetSymbolAddress((void**)&pWH, g_WH);
    cudaGetSymbolAddress((void**)&pWL, g_WL);
    cudaGetSymbolAddress((void**)&pB1, g_B1);
    cudaGetSymbolAddress((void**)&pM,  g_M);
    cudaGetSymbolAddress((void**)&pCT, g_CT);
    cudaGetSymbolAddress((void**)&pA,  g_A);
    cudaGetSymbolAddress((void**)&pBias, g_biasC);
    cudaGetSymbolAddress((void**)&pH2, g_H2);

    // prepasses
    cvt_k<<<1024, 256>>>(seg, pSeg, BLD);
    wtile_k<<<512, 256>>>(hw1, pWH + OFF_HW1, pWL + OFF_HW1, 512, 0, 262144L, 786432L);
    wtile_k<<<512, 256>>>(hw3, pWH + OFF_HW3, pWL + OFF_HW3, 512, 0, 262144L, 786432L);
    wtile_k<<<1024, 256>>>(lcW, pWH + OFF_LCV, pWL + OFF_LCV, 1024, 0, 786432L, 3145728L);
    wtile_k<<<512, 256>>>(lvW, pWH + OFF_LCV, pWL + OFF_LCV, 512, 1024, 786432L, 1572864L);
    wtile_k<<<512, 256>>>(gcW, pWH + OFF_GCV, pWL + OFF_GCV, 1024, 0, 786432L, 1048576L);
    wtile_k<<<512, 256>>>(gvW, pWH + OFF_GCV, pWL + OFF_GCV, 512, 1024, 786432L, 524288L);
    biascat_k<<<8, 256>>>(lcb, lvb, gcb, gvb);

    // 1) h2
    h2_k<<<Bb * Nn, Dd>>>(se, hw2, hb2);

    // 2) h1 = relu(seg @ w1 + b1) * h2
    mgemm(pSeg, pWH + OFF_HW1, pWL + OFF_HW1, hb1, pH2, pB1,
          512, 512, 512, 512, Nn, 0, 262144L, BLD, 512, 2 | 8);

    // 3) m = relu(h1m @ w3 + b3)
    mgemm(pB1, pWH + OFF_HW3, pWL + OFF_HW3, hb3, nullptr, pM,
          512, 512, 512, 512, Nn, BLD, 262144L, BLD, 512, 2);

    // 4) local NL: fused [cW|vW] projection + tiled banded attention
    for (int s = 0; s < 2; s++) {
        mgemm(pM, pWH + OFF_LCV + (long)s * 786432, pWL + OFF_LCV + (long)s * 786432,
              pBias + s * 1536, nullptr, pCT,
              1536, 512, 512, 1536, Nn, BLD, 2L * 786432, CTN, 3072, 0);
        local_attn_k<<<dim3(4, Bb * Hh, Nn), 256, LSMEM>>>(mask);
    }

    // 5) segment attention weights
    satt_k<<<Bb, AH>>>(se, sw1, sw2, out + BLD);

    // 6) aggregate
    agg_k<<<2048, 256>>>();

    // 7) global NL: fused projection + flash attention
    for (int s = 0; s < 2; s++) {
        mgemm(pA, pWH + OFF_GCV + (long)s * 786432, pWL + OFF_GCV + (long)s * 786432,
              pBias + (6 + s) * 1536, nullptr, pCT,
              1536, 512, 512, 1536, 1, 0, 0, 0, 0, 0);
        flash_k<<<dim3(4, Bb * Hh), 256, FSMEM>>>(mask, (s == 1) ? out : nullptr);
    }
}

// round 9
// speedup vs baseline: 2.7782x; 1.1739x over previous
#include <cuda_runtime.h>
#include <cuda_fp16.h>
#include <math.h>
#include <stdint.h>

#define Bb 16
#define Ll 512
#define Dd 512
#define Nn 3
#define Hh 8
#define DH 64
#define AH 256
#define KHALF 7

#define BLD 4194304L        // Bb*Ll*Dd
#define CTN 12582912L       // 8192*1536 per n
#define CTSZ 37748736L      // 3 * CTN

// ---------------- scratch ------------------------------------------------------
__device__ __half g_seg[BLD];
__device__ __half g_WH[7864320], g_WL[7864320];   // fp16 hi/lo, tiled 32x128 blocks
__device__ __half g_B1[3*BLD];
__device__ __half g_M [3*BLD];
__device__ __half g_CT[CTSZ];                     // [n][8192][1536] mq|mv|mk
__device__ __half g_A [BLD];
__device__ float g_H2[Bb*Nn*Dd];
__device__ float g_SW[Bb*Nn];
__device__ float g_biasC[8*1536];

#define OFF_HW1 0L
#define OFF_HW3 786432L
#define OFF_LCV 1572864L
#define OFF_GCV 6291456L

// ---------------- PTX helpers --------------------------------------------------
__device__ __forceinline__ uint32_t smem_u32(const void* p) {
    uint32_t a;
    asm("{ .reg .u64 t; cvta.to.shared.u64 t, %1; cvt.u32.u64 %0, t; }" : "=r"(a) : "l"(p));
    return a;
}
#define CPA16(dst, src) asm volatile( \
    "cp.async.ca.shared.global [%0], [%1], 16;" :: "r"(dst), "l"(__cvta_generic_to_global(src)))
#define CPA_COMMIT() asm volatile("cp.async.commit_group;" ::: "memory")
#define CPA_WAIT1()  asm volatile("cp.async.wait_group 1;" ::: "memory")

#define BULK(dst, src, sz, mb) asm volatile( \
    "cp.async.bulk.shared::cta.global.mbarrier::complete_tx::bytes [%0], [%1], %2, [%3];" \
    :: "r"(dst), "l"(__cvta_generic_to_global(src)), "r"((uint32_t)(sz)), "r"(mb) : "memory")

#define MBAR_INIT(mb, c)   asm volatile("mbarrier.init.shared.b64 [%0], %1;" :: "r"(mb), "r"((uint32_t)(c)) : "memory")
#define MBAR_EXPECT(mb, tx) asm volatile("mbarrier.arrive.expect_tx.shared.b64 _, [%0], %1;" :: "r"(mb), "r"((uint32_t)(tx)) : "memory")
#define FENCE_ASYNC_SHARED() asm volatile("fence.proxy.async.shared::cta;" ::: "memory")
#define MBAR_WAIT(mb, ph) do { \
    uint32_t _m = (mb), _p = (ph), _d; \
    asm volatile("{\n\t.reg .pred p;\n\tmbarrier.try_wait.parity.acquire.cta.shared::cta.b64 p, [%1], %2;\n\tselp.b32 %0, 1, 0, p;\n\t}" \
        : "=r"(_d) : "r"(_m), "r"(_p) : "memory"); \
    if (!_d) { \
        asm volatile("{\n\t.reg .pred P1;\n\tWL_%=:\n\tmbarrier.try_wait.parity.acquire.cta.shared::cta.b64 P1, [%0], %1, 0x989680;\n\t@P1 bra.uni WD_%=;\n\tbra.uni WL_%=;\n\tWD_%=:\n\t}" \
            :: "r"(_m), "r"(_p) : "memory"); \
    } } while (0)

#define LDM_X4(r, a) asm volatile( \
    "ldmatrix.sync.aligned.m8n8.x4.shared.b16 {%0,%1,%2,%3}, [%4];" \
    : "=r"((r)[0]),"=r"((r)[1]),"=r"((r)[2]),"=r"((r)[3]) : "r"(a))
#define LDM_X4T(r, a) asm volatile( \
    "ldmatrix.sync.aligned.m8n8.x4.trans.shared.b16 {%0,%1,%2,%3}, [%4];" \
    : "=r"((r)[0]),"=r"((r)[1]),"=r"((r)[2]),"=r"((r)[3]) : "r"(a))
#define MMAF16(d, a, b) asm volatile( \
    "mma.sync.aligned.m16n8k16.row.col.f32.f16.f16.f32 " \
    "{%0,%1,%2,%3}, {%4,%5,%6,%7}, {%8,%9}, {%0,%1,%2,%3};" \
    : "+f"((d)[0]),"+f"((d)[1]),"+f"((d)[2]),"+f"((d)[3]) \
    : "r"((a)[0]),"r"((a)[1]),"r"((a)[2]),"r"((a)[3]), "r"((b)[0]),"r"((b)[1]))

__device__ __forceinline__ uint32_t packh2(float a, float b) {
    __half2 t = __floats2half2_rn(a, b);
    return *reinterpret_cast<uint32_t*>(&t);
}

// ---------------- prepasses ----------------------------------------------------
__global__ void cvt_k(const float* __restrict__ s, __half* __restrict__ d, long n)
{
    for (long i = ((long)blockIdx.x * blockDim.x + threadIdx.x) * 4; i < n;
         i += (long)gridDim.x * blockDim.x * 4) {
        float4 v = *reinterpret_cast<const float4*>(s + i);
        uint2 o;
        o.x = packh2(v.x, v.y);
        o.y = packh2(v.z, v.w);
        *reinterpret_cast<uint2*>(d + i) = o;
    }
}

// all weight tiling in ONE launch; hi/lo for segments 0-1, hi-only for 2-5
__global__ void wtile_all_k(const float* __restrict__ hw1, const float* __restrict__ hw3,
                            const float* __restrict__ lcW, const float* __restrict__ lvW,
                            const float* __restrict__ gcW, const float* __restrict__ gvW)
{
    const float* srcs[6] = {hw1, hw3, lcW, lvW, gcW, gvW};
    const long  woff[6]  = {OFF_HW1, OFF_HW3, OFF_LCV, OFF_LCV, OFF_GCV, OFF_GCV};
    const int   C1s[6]   = {512, 512, 1024, 512, 1024, 512};
    const int   coff[6]  = {0, 0, 0, 1024, 0, 1024};
    const long  dss[6]   = {262144L, 262144L, 786432L, 786432L, 786432L, 786432L};
    const long  tots[6]  = {786432L, 786432L, 3145728L, 1572864L, 1048576L, 524288L};

    long gstride = (long)gridDim.x * blockDim.x * 4;
    #pragma unroll 1
    for (int sg = 0; sg < 6; sg++) {
        const float* s = srcs[sg];
        int C1 = C1s[sg];
        long sS = 512L * C1;
        bool wl = (sg < 2);
        for (long i = ((long)blockIdx.x * blockDim.x + threadIdx.x) * 4; i < tots[sg];
             i += gstride) {
            float4 v = *reinterpret_cast<const float4*>(s + i);
            long sl = i / sS;
            long rem = i - sl * sS;
            int k = (int)(rem / C1), c = (int)(rem - (long)(rem / C1) * C1);
            int n = coff[sg] + c;
            long d = woff[sg] + sl * dss[sg] + ((long)((n >> 7) * 16 + (k >> 5))) * 4096
                   + (k & 31) * 128 + ((((n & 127) >> 3) ^ (k & 7)) << 3) + (n & 7);
            float vv[4] = {v.x, v.y, v.z, v.w};
            #pragma unroll
            for (int e = 0; e < 4; e++) {
                __half hh = __float2half_rn(vv[e]);
                g_WH[d + e] = hh;
                if (wl) g_WL[d + e] = __float2half_rn(vv[e] - __half2float(hh));
            }
        }
    }
}

__global__ void biascat_k(const float* __restrict__ lcb, const float* __restrict__ lvb,
                          const float* __restrict__ gcb, const float* __restrict__ gvb)
{
    int slot = blockIdx.x;
    for (int c = threadIdx.x; c < 1536; c += blockDim.x) {
        float v;
        if (slot < 6) v = (c < 1024) ? lcb[slot * 1024 + c] : lvb[slot * 512 + c - 1024];
        else {
            int s = slot - 6;
            v = (c < 1024) ? gcb[s * 1024 + c] : gvb[s * 512 + c - 1024];
        }
        g_biasC[slot * 1536 + c] = v;
    }
}

// ---------------- GEMM: fp16 A x fp16 W (hi[,lo]), BN=256 ----------------------
// DUAL=1: W = WH + WL (2 MMAs); DUAL=0: W = WH (1 MMA)
// flags: 2=relu, 8=mul by H2
template<int DUAL>
__global__ void __launch_bounds__(256, 1) mma_gemm_k(
    const __half* __restrict__ A, const __half* __restrict__ WH,
    const __half* __restrict__ WL, const float* __restrict__ bias,
    const float* __restrict__ H2, __half* __restrict__ C,
    int K, int lda, int ldc,
    long sAi, long sBi, long sCi, long sBias, int flags)
{
    constexpr int LDS = 40;
    constexpr int A_BYTES = 128 * LDS * 2;     // 10240
    constexpr int BHI = 16384;                 // hi region (two 128-col blocks)
    constexpr int B_STAGE = DUAL ? 2 * BHI : BHI;
    constexpr int STAGE = A_BYTES + B_STAGE;
    extern __shared__ char dsm[];
    uint32_t sb0 = smem_u32(dsm);
    uint32_t mbar0 = sb0 + 3 * STAGE;

    int z = blockIdx.z;
    A  += z * sAi;
    WH += z * sBi;  WL += z * sBi;
    C  += z * sCi;
    if (bias) bias += z * sBias;

    int tid = threadIdx.x, lane = tid & 31, wid = tid >> 5;
    int wm = wid & 1, wn = wid >> 1;
    int m0 = blockIdx.y * 128;
    int bx = blockIdx.x, n0 = bx * 256;
    int nc = K / 32;

    if (tid == 0) {
        MBAR_INIT(mbar0, 1); MBAR_INIT(mbar0 + 8, 1); MBAR_INIT(mbar0 + 16, 1);
        FENCE_ASYNC_SHARED();
    }
    __syncthreads();

    auto fillA = [&](int c) {
        int k0 = c * 32;
        uint32_t st = sb0 + (c % 3) * STAGE;
        #pragma unroll
        for (int it = 0; it < 2; it++) {
            int idx = tid + it * 256;
            int row = idx >> 2, u = idx & 3;
            CPA16(st + row * 80 + u * 16, A + (long)(m0 + row) * lda + k0 + u * 8);
        }
    };
    auto fillB = [&](int c) {
        uint32_t st = sb0 + (c % 3) * STAGE + A_BYTES;
        uint32_t mb = mbar0 + (c % 3) * 8;
        MBAR_EXPECT(mb, DUAL ? 32768u : 16384u);
        long off0 = ((long)(bx * 2) * nc + c) * 4096;
        long off1 = ((long)(bx * 2 + 1) * nc + c) * 4096;
        BULK(st,        WH + off0, 8192, mb);
        BULK(st + 8192, WH + off1, 8192, mb);
        if (DUAL) {
            BULK(st + BHI,        WL + off0, 8192, mb);
            BULK(st + BHI + 8192, WL + off1, 8192, mb);
        }
    };

    float acc[4][8][4] = {};

    fillA(0); CPA_COMMIT();
    fillA(1); CPA_COMMIT();
    if (tid == 0) { fillB(0); fillB(1); }

    int alr = lane & 15, alc = (lane >> 4) << 3;
    int btr = (lane & 7) + (((lane >> 3) & 1) << 3);
    int btcc = (lane >> 4) & 1;

    for (int c = 0; c < nc; c++) {
        CPA_WAIT1();
        MBAR_WAIT(mbar0 + (c % 3) * 8, (c / 3) & 1);
        __syncthreads();
        if (c + 2 < nc) { fillA(c + 2); if (tid == 0) fillB(c + 2); }
        CPA_COMMIT();

        uint32_t base = sb0 + (c % 3) * STAGE;
        uint32_t aA = base + ((wm * 64 + alr) * LDS + alc) * 2;
        uint32_t bB = base + A_BYTES + (wn >> 1) * 8192;

        #pragma unroll
        for (int kk = 0; kk < 2; kk++) {
            uint32_t ah[4][4], bh[8][2], bl[8][2];
            #pragma unroll
            for (int mt = 0; mt < 4; mt++)
                LDM_X4(ah[mt], aA + (uint32_t)((mt * 16 * LDS + kk * 16) * 2));
            int krow = kk * 16 + btr;
            #pragma unroll
            for (int p = 0; p < 4; p++) {
                int c16 = (wn & 1) * 8 + p * 2 + btcc;
                uint32_t ad = bB + (uint32_t)(krow * 256 + ((c16 ^ (krow & 7)) << 4));
                uint32_t r[4];
                LDM_X4T(r, ad);
                bh[2*p][0]=r[0]; bh[2*p][1]=r[1]; bh[2*p+1][0]=r[2]; bh[2*p+1][1]=r[3];
                if (DUAL) {
                    LDM_X4T(r, ad + BHI);
                    bl[2*p][0]=r[0]; bl[2*p][1]=r[1]; bl[2*p+1][0]=r[2]; bl[2*p+1][1]=r[3];
                }
            }
            #pragma unroll
            for (int mt = 0; mt < 4; mt++)
                #pragma unroll
                for (int nt = 0; nt < 8; nt++) {
                    MMAF16(acc[mt][nt], ah[mt], bh[nt]);
                    if (DUAL) MMAF16(acc[mt][nt], ah[mt], bl[nt]);
                }
        }
    }

    const float* H2b = (flags & 8) ? (H2 + ((long)(m0 >> 9) * Nn + z) * 512) : nullptr;

    #pragma unroll
    for (int mt = 0; mt < 4; mt++) {
        int row = m0 + wm * 64 + mt * 16 + (lane >> 2);
        #pragma unroll
        for (int nt = 0; nt < 8; nt++) {
            int col = n0 + wn * 64 + nt * 8 + (lane & 3) * 2;
            float d0 = acc[mt][nt][0], d1 = acc[mt][nt][1];
            float d2 = acc[mt][nt][2], d3 = acc[mt][nt][3];
            if (bias) {
                float b0 = bias[col], b1 = bias[col + 1];
                d0 += b0; d1 += b1; d2 += b0; d3 += b1;
            }
            if (flags & 2) {
                d0 = fmaxf(d0, 0.f); d1 = fmaxf(d1, 0.f);
                d2 = fmaxf(d2, 0.f); d3 = fmaxf(d3, 0.f);
            }
            if (H2b) {
                float f0 = H2b[col], f1 = H2b[col + 1];
                d0 *= f0; d1 *= f1; d2 *= f0; d3 *= f1;
            }
            long o0 = (long)row * ldc + col;
            long o1 = o0 + (long)8 * ldc;
            *reinterpret_cast<uint32_t*>(C + o0) = packh2(d0, d1);
            *reinterpret_cast<uint32_t*>(C + o1) = packh2(d2, d3);
        }
    }
}

// ---------------- flash global attention ---------------------------------------
#define FQ 0
#define FK 18432
#define FV 36864
#define FMSK 55296
#define FSMEM 57344
#define FLDQ 72

__global__ void __launch_bounds__(256, 1) flash_k(const float* __restrict__ mask,
                                                  float* __restrict__ outp)
{
    extern __shared__ char sm[];
    uint32_t sb = smem_u32(sm);
    float* mbias = reinterpret_cast<float*>(sm + FMSK);
    int tid = threadIdx.x, lane = tid & 31, w = tid >> 5;
    int b = blockIdx.y >> 3, h = blockIdx.y & 7;
    int l0 = blockIdx.x * 128;
    long base = (long)b * 512 * 1536;

    for (int i = tid; i < 1024; i += 256) {
        int row = i >> 3, u = i & 7;
        *reinterpret_cast<uint4*>(sm + FQ + row * 144 + u * 16) =
            *reinterpret_cast<const uint4*>(g_CT + base + (long)(l0 + row) * 1536 + 1024 + h * DH + u * 8);
    }
    for (int i = tid; i < 512; i += 256)
        mbias[i] = (mask[(long)b * 512 + i] != 0.f) ? 0.f : -1e9f;

    float O[8][4];
    #pragma unroll
    for (int i = 0; i < 8; i++)
        #pragma unroll
        for (int e = 0; e < 4; e++) O[i][e] = 0.f;
    float mrow[2] = {-1e30f, -1e30f}, lrow[2] = {0.f, 0.f};

    int alr = lane & 15, alc = (lane >> 4) << 3;
    int blr = (lane & 7) + (((lane >> 4) & 1) << 3), blc = ((lane >> 3) & 1) << 3;
    int btr = (lane & 7) + (((lane >> 3) & 1) << 3), btc = ((lane >> 4) & 1) << 3;
    int c0 = (lane & 3) * 2;

    for (int mi = 0; mi < 4; mi++) {
        int m0 = mi * 128;
        __syncthreads();
        for (int i = tid; i < 1024; i += 256) {
            int row = i >> 3, u = i & 7;
            long gq = base + (long)(m0 + row) * 1536 + h * DH + u * 8;
            *reinterpret_cast<uint4*>(sm + FK + row * 144 + u * 16) =
                *reinterpret_cast<const uint4*>(g_CT + gq);
            *reinterpret_cast<uint4*>(sm + FV + row * 144 + u * 16) =
                *reinterpret_cast<const uint4*>(g_CT + gq + 512);
        }
        __syncthreads();

        float S[16][4];
        #pragma unroll
        for (int i = 0; i < 16; i++)
            #pragma unroll
            for (int e = 0; e < 4; e++) S[i][e] = 0.f;

        #pragma unroll
        for (int kc = 0; kc < 4; kc++) {
            uint32_t q[4];
            LDM_X4(q, sb + FQ + (uint32_t)(((w * 16 + alr) * FLDQ + kc * 16 + alc) * 2));
            #pragma unroll
            for (int p = 0; p < 8; p++) {
                uint32_t kf[4];
                LDM_X4(kf, sb + FK + (uint32_t)(((p * 16 + blr) * FLDQ + kc * 16 + blc) * 2));
                uint32_t b0[2] = {kf[0], kf[1]}, b1[2] = {kf[2], kf[3]};
                MMAF16(S[2*p],   q, b0);
                MMAF16(S[2*p+1], q, b1);
            }
        }

        float cmax[2] = {-1e30f, -1e30f};
        #pragma unroll
        for (int nt = 0; nt < 16; nt++)
            #pragma unroll
            for (int e = 0; e < 4; e++) {
                int col = m0 + nt * 8 + c0 + (e & 1);
                float v = S[nt][e] * 0.125f + mbias[col];
                S[nt][e] = v;
                cmax[e >> 1] = fmaxf(cmax[e >> 1], v);
            }
        #pragma unroll
        for (int o = 1; o <= 2; o <<= 1) {
            cmax[0] = fmaxf(cmax[0], __shfl_xor_sync(0xffffffffu, cmax[0], o));
            cmax[1] = fmaxf(cmax[1], __shfl_xor_sync(0xffffffffu, cmax[1], o));
        }
        float mn0 = fmaxf(mrow[0], cmax[0]), mn1 = fmaxf(mrow[1], cmax[1]);
        float a0 = __expf(mrow[0] - mn0), a1 = __expf(mrow[1] - mn1);
        mrow[0] = mn0; mrow[1] = mn1;
        lrow[0] *= a0; lrow[1] *= a1;
        #pragma unroll
        for (int i = 0; i < 8; i++) {
            O[i][0] *= a0; O[i][1] *= a0; O[i][2] *= a1; O[i][3] *= a1;
        }
        #pragma unroll
        for (int nt = 0; nt < 16; nt++)
            #pragma unroll
            for (int e = 0; e < 4; e++) {
                float p = __expf(S[nt][e] - ((e < 2) ? mn0 : mn1));
                S[nt][e] = p;
                lrow[e >> 1] += p;
            }

        #pragma unroll
        for (int kc = 0; kc < 8; kc++) {
            uint32_t ph[4];
            ph[0] = packh2(S[2*kc][0],   S[2*kc][1]);
            ph[1] = packh2(S[2*kc][2],   S[2*kc][3]);
            ph[2] = packh2(S[2*kc+1][0], S[2*kc+1][1]);
            ph[3] = packh2(S[2*kc+1][2], S[2*kc+1][3]);
            #pragma unroll
            for (int p = 0; p < 4; p++) {
                uint32_t vh[4];
                LDM_X4T(vh, sb + FV + (uint32_t)(((kc * 16 + btr) * FLDQ + p * 16 + btc) * 2));
                uint32_t b0[2] = {vh[0], vh[1]}, b1[2] = {vh[2], vh[3]};
                MMAF16(O[2*p],   ph, b0);
                MMAF16(O[2*p+1], ph, b1);
            }
        }
    }

    #pragma unroll
    for (int o = 1; o <= 2; o <<= 1) {
        lrow[0] += __shfl_xor_sync(0xffffffffu, lrow[0], o);
        lrow[1] += __shfl_xor_sync(0xffffffffu, lrow[1], o);
    }
    float inv0 = 1.f / lrow[0], inv1 = 1.f / lrow[1];

    int r0g = l0 + w * 16 + (lane >> 2);
    #pragma unroll
    for (int nt = 0; nt < 8; nt++) {
        int col = h * DH + nt * 8 + c0;
        long o0 = ((long)b * 512 + r0g) * 512 + col;
        long o1 = o0 + 8 * 512;
        __half2 x0 = *reinterpret_cast<const __half2*>(g_A + o0);
        __half2 x1 = *reinterpret_cast<const __half2*>(g_A + o1);
        float d0 = __low2float(x0) + O[nt][0] * inv0;
        float d1 = __high2float(x0) + O[nt][1] * inv0;
        float d2 = __low2float(x1) + O[nt][2] * inv1;
        float d3 = __high2float(x1) + O[nt][3] * inv1;
        if (outp) {
            *reinterpret_cast<float2*>(outp + o0) = make_float2(d0, d1);
            *reinterpret_cast<float2*>(outp + o1) = make_float2(d2, d3);
        } else {
            *reinterpret_cast<uint32_t*>(g_A + o0) = packh2(d0, d1);
            *reinterpret_cast<uint32_t*>(g_A + o1) = packh2(d2, d3);
        }
    }
}

// ---------------- tiled banded local attention ---------------------------------
#define LSM_MQ 16384
#define LSM_MV 34816
#define LSM_BI 53248
#define LSMEM 53824

__global__ void __launch_bounds__(256, 1) local_attn_k(const float* __restrict__ mask)
{
    extern __shared__ char sm[];
    float* sBias = reinterpret_cast<float*>(sm + LSM_BI);
    int tid = threadIdx.x, lane = tid & 31, w = tid >> 5;
    int b = blockIdx.y >> 3, h = blockIdx.y & 7;
    int n = blockIdx.z;
    int l0 = blockIdx.x * 128;
    long base = (long)n * CTN + (long)b * 512 * 1536;

    for (int i = tid; i < 1024; i += 256) {
        int row = i >> 3, u = i & 7;
        *reinterpret_cast<uint4*>(sm + row * 128 + u * 16) =
            *reinterpret_cast<const uint4*>(g_CT + base + (long)(l0 + row) * 1536 + 1024 + h * DH + u * 8);
    }
    for (int i = tid; i < 142 * 8; i += 256) {
        int r = i >> 3, u = i & 7;
        int m = l0 - 7 + r;
        if (m >= 0 && m < 512) {
            long g = base + (long)m * 1536 + h * DH + u * 8;
            *reinterpret_cast<uint4*>(sm + LSM_MQ + r * 128 + u * 16) =
                *reinterpret_cast<const uint4*>(g_CT + g);
            *reinterpret_cast<uint4*>(sm + LSM_MV + r * 128 + u * 16) =
                *reinterpret_cast<const uint4*>(g_CT + g + 512);
        }
    }
    for (int i = tid; i < 142; i += 256) {
        int m = l0 - 7 + i;
        sBias[i] = (m >= 0 && m < 512) ? mask[(long)b * 512 + m] : 0.f;
    }
    __syncthreads();

    for (int j = 0; j < 16; j++) {
        int l = l0 + w * 16 + j;
        int lr = l - l0;
        __half2 kv = *reinterpret_cast<const __half2*>(sm + lr * 128 + lane * 4);
        float k0f = __low2float(kv), k1f = __high2float(kv);

        float sc[15];
        #pragma unroll
        for (int jj = 0; jj < 15; jj++) {
            int r = lr + jj;
            float s = -1e30f;
            if (sBias[r] != 0.f) {
                __half2 q = *reinterpret_cast<const __half2*>(sm + LSM_MQ + r * 128 + lane * 4);
                float d = k0f * __low2float(q) + k1f * __high2float(q);
                #pragma unroll
                for (int o = 16; o; o >>= 1) d += __shfl_xor_sync(0xffffffffu, d, o);
                s = d * 0.125f;
            }
            sc[jj] = s;
        }
        float mx = -1e30f;
        #pragma unroll
        for (int jj = 0; jj < 15; jj++) mx = fmaxf(mx, sc[jj]);
        float wgt[15], sum = 0.f;
        #pragma unroll
        for (int jj = 0; jj < 15; jj++) {
            wgt[jj] = (sc[jj] > -1e29f) ? expf(sc[jj] - mx) : 0.f;
            sum += wgt[jj];
        }
        float inv = 1.f / sum;
        float o0 = 0.f, o1 = 0.f;
        #pragma unroll
        for (int jj = 0; jj < 15; jj++) {
            if (wgt[jj] != 0.f) {
                int r = lr + jj;
                __half2 v = *reinterpret_cast<const __half2*>(sm + LSM_MV + r * 128 + lane * 4);
                float ww = wgt[jj] * inv;
                o0 = fmaf(ww, __low2float(v), o0);
                o1 = fmaf(ww, __high2float(v), o1);
            }
        }
        long xo = (long)n * BLD + ((long)b * 512 + l) * 512 + h * DH + lane * 2;
        __half2 xv = *reinterpret_cast<const __half2*>(g_M + xo);
        *reinterpret_cast<uint32_t*>(g_M + xo) =
            packh2(__low2float(xv) + o0, __high2float(xv) + o1);
    }
}

// ---------------- small kernels ------------------------------------------------
__global__ void h2_k(const float* __restrict__ se, const float* __restrict__ w2,
                     const float* __restrict__ b2)
{
    int bn = blockIdx.x;
    int n = bn % Nn;
    int h = threadIdx.x;
    const float* x = se + (long)bn * Dd;
    const float* w = w2 + (long)n * Dd * Dd;
    float acc = b2[n * Dd + h];
    for (int d = 0; d < Dd; d++) acc = fmaf(x[d], w[(long)d * Dd + h], acc);
    g_H2[(long)bn * Dd + h] = fmaxf(acc, 0.f);
}

__global__ void satt_k(const float* __restrict__ se, const float* __restrict__ w1,
                       const float* __restrict__ w2, float* __restrict__ out_tail)
{
    int b = blockIdx.x, t = threadIdx.x;
    __shared__ float red[256];
    __shared__ float alpha[Nn];
    for (int n = 0; n < Nn; n++) {
        const float* x = se + ((long)b * Nn + n) * Dd;
        float acc = 0.f;
        for (int d = 0; d < Dd; d++) acc = fmaf(x[d], w1[(long)d * AH + t], acc);
        red[t] = tanhf(acc) * w2[t];
        __syncthreads();
        for (int o = 128; o; o >>= 1) { if (t < o) red[t] += red[t + o]; __syncthreads(); }
        if (t == 0) alpha[n] = red[0];
        __syncthreads();
    }
    if (t == 0) {
        float mx = fmaxf(alpha[0], fmaxf(alpha[1], alpha[2]));
        float e[Nn], sum = 0.f;
        for (int n = 0; n < Nn; n++) { e[n] = expf(alpha[n] - mx); sum += e[n]; }
        for (int n = 0; n < Nn; n++) {
            float w = e[n] / sum;
            g_SW[b * Nn + n] = w;
            out_tail[b * Nn + n] = w;
        }
    }
}

__global__ void agg_k()
{
    long half_total = BLD / 2;
    long stride = (long)Ll * Dd / 2;
    for (long i = (long)blockIdx.x * blockDim.x + threadIdx.x; i < half_total;
         i += (long)gridDim.x * blockDim.x) {
        int b = (int)(i / stride);
        float a0 = 0.f, a1 = 0.f;
        #pragma unroll
        for (int n = 0; n < Nn; n++) {
            float sw = g_SW[b * Nn + n];
            __half2 v = *reinterpret_cast<const __half2*>(g_M + (long)n * BLD + i * 2);
            a0 = fmaf(sw, __low2float(v), a0);
            a1 = fmaf(sw, __high2float(v), a1);
        }
        *reinterpret_cast<uint32_t*>(g_A + i * 2) = packh2(a0, a1);
    }
}

// ---------------- host orchestration ------------------------------------------
#define GSMEM_D 129056
#define GSMEM_S 79904

static void mgemm(int dual, const __half* A, const __half* WH, const __half* WL,
                  const float* bias, const float* H2, __half* C,
                  int N, int K, int lda, int ldc, int batches,
                  long sAi, long sBi, long sCi, long sBias, int flags)
{
    dim3 grid(N / 256, 64, batches);
    if (dual)
        mma_gemm_k<1><<<grid, 256, GSMEM_D>>>(A, WH, WL, bias, H2, C, K,
                                              lda, ldc, sAi, sBi, sCi, sBias, flags);
    else
        mma_gemm_k<0><<<grid, 256, GSMEM_S>>>(A, WH, WL, bias, H2, C, K,
                                              lda, ldc, sAi, sBi, sCi, sBias, flags);
}

extern "C" void kernel_launch(void* const* d_in, const int* in_sizes, int n_in,
                              void* d_out, int out_size)
{
    const float* seg   = (const float*)d_in[0];
    const float* mask  = (const float*)d_in[1];
    const float* se    = (const float*)d_in[2];
    const float* hw1   = (const float*)d_in[3];
    const float* hb1   = (const float*)d_in[4];
    const float* hw2   = (const float*)d_in[5];
    const float* hb2   = (const float*)d_in[6];
    const float* hw3   = (const float*)d_in[7];
    const float* hb3   = (const float*)d_in[8];
    const float* lcW   = (const float*)d_in[9];
    const float* lcb   = (const float*)d_in[10];
    const float* lvW   = (const float*)d_in[11];
    const float* lvb   = (const float*)d_in[12];
    const float* gcW   = (const float*)d_in[13];
    const float* gcb   = (const float*)d_in[14];
    const float* gvW   = (const float*)d_in[15];
    const float* gvb   = (const float*)d_in[16];
    const float* sw1   = (const float*)d_in[17];
    const float* sw2   = (const float*)d_in[18];
    float* out = (float*)d_out;

    cudaFuncSetAttribute(mma_gemm_k<1>, cudaFuncAttributeMaxDynamicSharedMemorySize, GSMEM_D);
    cudaFuncSetAttribute(mma_gemm_k<0>, cudaFuncAttributeMaxDynamicSharedMemorySize, GSMEM_S);
    cudaFuncSetAttribute(flash_k,       cudaFuncAttributeMaxDynamicSharedMemorySize, FSMEM);
    cudaFuncSetAttribute(local_attn_k,  cudaFuncAttributeMaxDynamicSharedMemorySize, LSMEM);

    __half *pSeg, *pWH, *pWL, *pB1, *pM, *pCT, *pA;
    float *pBias, *pH2;
    cudaGetSymbolAddress((void**)&pSeg, g_seg);
    cudaGetSymbolAddress((void**)&pWH, g_WH);
    cudaGetSymbolAddress((void**)&pWL, g_WL);
    cudaGetSymbolAddress((void**)&pB1, g_B1);
    cudaGetSymbolAddress((void**)&pM,  g_M);
    cudaGetSymbolAddress((void**)&pCT, g_CT);
    cudaGetSymbolAddress((void**)&pA,  g_A);
    cudaGetSymbolAddress((void**)&pBias, g_biasC);
    cudaGetSymbolAddress((void**)&pH2, g_H2);

    // prepasses (3 launches)
    cvt_k<<<1024, 256>>>(seg, pSeg, BLD);
    wtile_all_k<<<1024, 256>>>(hw1, hw3, lcW, lvW, gcW, gvW);
    biascat_k<<<8, 256>>>(lcb, lvb, gcb, gvb);

    // 1) h2
    h2_k<<<Bb * Nn, Dd>>>(se, hw2, hb2);

    // 2) h1 = relu(seg @ w1 + b1) * h2   (hi/lo weights)
    mgemm(1, pSeg, pWH + OFF_HW1, pWL + OFF_HW1, hb1, pH2, pB1,
          512, 512, 512, 512, Nn, 0, 262144L, BLD, 512, 2 | 8);

    // 3) m = relu(h1m @ w3 + b3)   (hi/lo weights)
    mgemm(1, pB1, pWH + OFF_HW3, pWL + OFF_HW3, hb3, nullptr, pM,
          512, 512, 512, 512, Nn, BLD, 262144L, BLD, 512, 2);

    // 4) local NL: single-fp16-weight projection + tiled banded attention
    for (int s = 0; s < 2; s++) {
        mgemm(0, pM, pWH + OFF_LCV + (long)s * 786432, pWL, pBias + s * 1536, nullptr, pCT,
              1536, 512, 512, 1536, Nn, BLD, 2L * 786432, CTN, 3072, 0);
        local_attn_k<<<dim3(4, Bb * Hh, Nn), 256, LSMEM>>>(mask);
    }

    // 5) segment attention weights
    satt_k<<<Bb, AH>>>(se, sw1, sw2, out + BLD);

    // 6) aggregate
    agg_k<<<2048, 256>>>();

    // 7) global NL: single-fp16-weight projection + flash attention
    for (int s = 0; s < 2; s++) {
        mgemm(0, pA, pWH + OFF_GCV + (long)s * 786432, pWL, pBias + (6 + s) * 1536, nullptr, pCT,
              1536, 512, 512, 1536, 1, 0, 0, 0, 0, 0);
        flash_k<<<dim3(4, Bb * Hh), 256, FSMEM>>>(mask, (s == 1) ? out : nullptr);
    }
}

// round 10
// speedup vs baseline: 2.8810x; 1.0370x over previous
#include <cuda_runtime.h>
#include <cuda_fp16.h>
#include <math.h>
#include <stdint.h>

#define Bb 16
#define Ll 512
#define Dd 512
#define Nn 3
#define Hh 8
#define DH 64
#define AH 256
#define KHALF 7

#define BLD 4194304L        // Bb*Ll*Dd
#define CTN 12582912L       // 8192*1536 per n
#define CTSZ 37748736L      // 3 * CTN

// ---------------- scratch ------------------------------------------------------
__device__ __half g_seg[BLD];
__device__ __half g_WH[7864320];                  // fp16, tiled 32x128 blocks
__device__ __half g_B1[3*BLD];
__device__ __half g_M [3*BLD];
__device__ __half g_CT[CTSZ];                     // [n][8192][1536] mq|mv|mk
__device__ __half g_A [BLD];
__device__ float g_H2[Bb*Nn*Dd];
__device__ float g_SW[Bb*Nn];
__device__ float g_biasC[8*1536];

#define OFF_HW1 0L
#define OFF_HW3 786432L
#define OFF_LCV 1572864L
#define OFF_GCV 6291456L

// ---------------- PTX helpers --------------------------------------------------
__device__ __forceinline__ uint32_t smem_u32(const void* p) {
    uint32_t a;
    asm("{ .reg .u64 t; cvta.to.shared.u64 t, %1; cvt.u32.u64 %0, t; }" : "=r"(a) : "l"(p));
    return a;
}
#define CPA16(dst, src) asm volatile( \
    "cp.async.ca.shared.global [%0], [%1], 16;" :: "r"(dst), "l"(__cvta_generic_to_global(src)))
#define CPA_COMMIT() asm volatile("cp.async.commit_group;" ::: "memory")
#define CPA_WAIT1()  asm volatile("cp.async.wait_group 1;" ::: "memory")

#define BULK(dst, src, sz, mb) asm volatile( \
    "cp.async.bulk.shared::cta.global.mbarrier::complete_tx::bytes [%0], [%1], %2, [%3];" \
    :: "r"(dst), "l"(__cvta_generic_to_global(src)), "r"((uint32_t)(sz)), "r"(mb) : "memory")

#define MBAR_INIT(mb, c)   asm volatile("mbarrier.init.shared.b64 [%0], %1;" :: "r"(mb), "r"((uint32_t)(c)) : "memory")
#define MBAR_EXPECT(mb, tx) asm volatile("mbarrier.arrive.expect_tx.shared.b64 _, [%0], %1;" :: "r"(mb), "r"((uint32_t)(tx)) : "memory")
#define FENCE_ASYNC_SHARED() asm volatile("fence.proxy.async.shared::cta;" ::: "memory")
#define MBAR_WAIT(mb, ph) do { \
    uint32_t _m = (mb), _p = (ph), _d; \
    asm volatile("{\n\t.reg .pred p;\n\tmbarrier.try_wait.parity.acquire.cta.shared::cta.b64 p, [%1], %2;\n\tselp.b32 %0, 1, 0, p;\n\t}" \
        : "=r"(_d) : "r"(_m), "r"(_p) : "memory"); \
    if (!_d) { \
        asm volatile("{\n\t.reg .pred P1;\n\tWL_%=:\n\tmbarrier.try_wait.parity.acquire.cta.shared::cta.b64 P1, [%0], %1, 0x989680;\n\t@P1 bra.uni WD_%=;\n\tbra.uni WL_%=;\n\tWD_%=:\n\t}" \
            :: "r"(_m), "r"(_p) : "memory"); \
    } } while (0)

#define LDM_X4(r, a) asm volatile( \
    "ldmatrix.sync.aligned.m8n8.x4.shared.b16 {%0,%1,%2,%3}, [%4];" \
    : "=r"((r)[0]),"=r"((r)[1]),"=r"((r)[2]),"=r"((r)[3]) : "r"(a))
#define LDM_X4T(r, a) asm volatile( \
    "ldmatrix.sync.aligned.m8n8.x4.trans.shared.b16 {%0,%1,%2,%3}, [%4];" \
    : "=r"((r)[0]),"=r"((r)1),"=r"((r)[2]),"=r"((r)[3]) : "r"(a))
#undef LDM_X4T
#define LDM_X4T(r, a) asm volatile( \
    "ldmatrix.sync.aligned.m8n8.x4.trans.shared.b16 {%0,%1,%2,%3}, [%4];" \
    : "=r"((r)[0]),"=r"((r)[1]),"=r"((r)[2]),"=r"((r)[3]) : "r"(a))
#define MMAF16(d, a, b) asm volatile( \
    "mma.sync.aligned.m16n8k16.row.col.f32.f16.f16.f32 " \
    "{%0,%1,%2,%3}, {%4,%5,%6,%7}, {%8,%9}, {%0,%1,%2,%3};" \
    : "+f"((d)[0]),"+f"((d)[1]),"+f"((d)[2]),"+f"((d)[3]) \
    : "r"((a)[0]),"r"((a)[1]),"r"((a)[2]),"r"((a)[3]), "r"((b)[0]),"r"((b)[1]))

__device__ __forceinline__ uint32_t packh2(float a, float b) {
    __half2 t = __floats2half2_rn(a, b);
    return *reinterpret_cast<uint32_t*>(&t);
}

// ---------------- prepasses ----------------------------------------------------
__global__ void cvt_k(const float* __restrict__ s, __half* __restrict__ d, long n)
{
    for (long i = ((long)blockIdx.x * blockDim.x + threadIdx.x) * 4; i < n;
         i += (long)gridDim.x * blockDim.x * 4) {
        float4 v = *reinterpret_cast<const float4*>(s + i);
        uint2 o;
        o.x = packh2(v.x, v.y);
        o.y = packh2(v.z, v.w);
        *reinterpret_cast<uint2*>(d + i) = o;
    }
}

// all weight tiling in ONE launch; fp16 single
__global__ void wtile_all_k(const float* __restrict__ hw1, const float* __restrict__ hw3,
                            const float* __restrict__ lcW, const float* __restrict__ lvW,
                            const float* __restrict__ gcW, const float* __restrict__ gvW)
{
    const float* srcs[6] = {hw1, hw3, lcW, lvW, gcW, gvW};
    const long  woff[6]  = {OFF_HW1, OFF_HW3, OFF_LCV, OFF_LCV, OFF_GCV, OFF_GCV};
    const int   C1s[6]   = {512, 512, 1024, 512, 1024, 512};
    const int   coff[6]  = {0, 0, 0, 1024, 0, 1024};
    const long  dss[6]   = {262144L, 262144L, 786432L, 786432L, 786432L, 786432L};
    const long  tots[6]  = {786432L, 786432L, 3145728L, 1572864L, 1048576L, 524288L};

    long gstride = (long)gridDim.x * blockDim.x * 4;
    #pragma unroll 1
    for (int sg = 0; sg < 6; sg++) {
        const float* s = srcs[sg];
        int C1 = C1s[sg];
        long sS = 512L * C1;
        for (long i = ((long)blockIdx.x * blockDim.x + threadIdx.x) * 4; i < tots[sg];
             i += gstride) {
            float4 v = *reinterpret_cast<const float4*>(s + i);
            long sl = i / sS;
            long rem = i - sl * sS;
            int k = (int)(rem / C1), c = (int)(rem - (long)(rem / C1) * C1);
            int n = coff[sg] + c;
            long d = woff[sg] + sl * dss[sg] + ((long)((n >> 7) * 16 + (k >> 5))) * 4096
                   + (k & 31) * 128 + ((((n & 127) >> 3) ^ (k & 7)) << 3) + (n & 7);
            float vv[4] = {v.x, v.y, v.z, v.w};
            #pragma unroll
            for (int e = 0; e < 4; e++)
                g_WH[d + e] = __float2half_rn(vv[e]);
        }
    }
}

__global__ void biascat_k(const float* __restrict__ lcb, const float* __restrict__ lvb,
                          const float* __restrict__ gcb, const float* __restrict__ gvb)
{
    int slot = blockIdx.x;
    for (int c = threadIdx.x; c < 1536; c += blockDim.x) {
        float v;
        if (slot < 6) v = (c < 1024) ? lcb[slot * 1024 + c] : lvb[slot * 512 + c - 1024];
        else {
            int s = slot - 6;
            v = (c < 1024) ? gcb[s * 1024 + c] : gvb[s * 512 + c - 1024];
        }
        g_biasC[slot * 1536 + c] = v;
    }
}

// ---------------- GEMM: fp16 A x fp16 W, 1 MMA/k16, BN=256 ---------------------
// flags: 2=relu, 8=mul by H2
#define GSMEM 79904
__global__ void __launch_bounds__(256, 1) mma_gemm_k(
    const __half* __restrict__ A, const __half* __restrict__ WH,
    const float* __restrict__ bias, const float* __restrict__ H2,
    __half* __restrict__ C,
    int K, int lda, int ldc,
    long sAi, long sBi, long sCi, long sBias, int flags)
{
    constexpr int LDS = 40;
    constexpr int A_BYTES = 128 * LDS * 2;     // 10240
    constexpr int BHI = 16384;
    constexpr int STAGE = A_BYTES + BHI;       // 26624
    extern __shared__ char dsm[];
    uint32_t sb0 = smem_u32(dsm);
    uint32_t mbar0 = sb0 + 3 * STAGE;

    int z = blockIdx.z;
    A  += z * sAi;
    WH += z * sBi;
    C  += z * sCi;
    if (bias) bias += z * sBias;

    int tid = threadIdx.x, lane = tid & 31, wid = tid >> 5;
    int wm = wid & 1, wn = wid >> 1;
    int m0 = blockIdx.y * 128;
    int bx = blockIdx.x, n0 = bx * 256;
    int nc = K / 32;

    if (tid == 0) {
        MBAR_INIT(mbar0, 1); MBAR_INIT(mbar0 + 8, 1); MBAR_INIT(mbar0 + 16, 1);
        FENCE_ASYNC_SHARED();
    }
    __syncthreads();

    auto fillA = [&](int c) {
        int k0 = c * 32;
        uint32_t st = sb0 + (c % 3) * STAGE;
        #pragma unroll
        for (int it = 0; it < 2; it++) {
            int idx = tid + it * 256;
            int row = idx >> 2, u = idx & 3;
            CPA16(st + row * 80 + u * 16, A + (long)(m0 + row) * lda + k0 + u * 8);
        }
    };
    auto fillB = [&](int c) {
        uint32_t st = sb0 + (c % 3) * STAGE + A_BYTES;
        uint32_t mb = mbar0 + (c % 3) * 8;
        MBAR_EXPECT(mb, 16384u);
        long off0 = ((long)(bx * 2) * nc + c) * 4096;
        long off1 = ((long)(bx * 2 + 1) * nc + c) * 4096;
        BULK(st,        WH + off0, 8192, mb);
        BULK(st + 8192, WH + off1, 8192, mb);
    };

    float acc[4][8][4] = {};

    fillA(0); CPA_COMMIT();
    fillA(1); CPA_COMMIT();
    if (tid == 0) { fillB(0); fillB(1); }

    int alr = lane & 15, alc = (lane >> 4) << 3;
    int btr = (lane & 7) + (((lane >> 3) & 1) << 3);
    int btcc = (lane >> 4) & 1;

    for (int c = 0; c < nc; c++) {
        CPA_WAIT1();
        MBAR_WAIT(mbar0 + (c % 3) * 8, (c / 3) & 1);
        __syncthreads();
        if (c + 2 < nc) { fillA(c + 2); if (tid == 0) fillB(c + 2); }
        CPA_COMMIT();

        uint32_t base = sb0 + (c % 3) * STAGE;
        uint32_t aA = base + ((wm * 64 + alr) * LDS + alc) * 2;
        uint32_t bB = base + A_BYTES + (wn >> 1) * 8192;

        #pragma unroll
        for (int kk = 0; kk < 2; kk++) {
            uint32_t ah[4][4], bh[8][2];
            #pragma unroll
            for (int mt = 0; mt < 4; mt++)
                LDM_X4(ah[mt], aA + (uint32_t)((mt * 16 * LDS + kk * 16) * 2));
            int krow = kk * 16 + btr;
            #pragma unroll
            for (int p = 0; p < 4; p++) {
                int c16 = (wn & 1) * 8 + p * 2 + btcc;
                uint32_t ad = bB + (uint32_t)(krow * 256 + ((c16 ^ (krow & 7)) << 4));
                uint32_t r[4];
                LDM_X4T(r, ad);
                bh[2*p][0]=r[0]; bh[2*p][1]=r[1]; bh[2*p+1][0]=r[2]; bh[2*p+1][1]=r[3];
            }
            #pragma unroll
            for (int mt = 0; mt < 4; mt++)
                #pragma unroll
                for (int nt = 0; nt < 8; nt++)
                    MMAF16(acc[mt][nt], ah[mt], bh[nt]);
        }
    }

    const float* H2b = (flags & 8) ? (H2 + ((long)(m0 >> 9) * Nn + z) * 512) : nullptr;

    #pragma unroll
    for (int mt = 0; mt < 4; mt++) {
        int row = m0 + wm * 64 + mt * 16 + (lane >> 2);
        #pragma unroll
        for (int nt = 0; nt < 8; nt++) {
            int col = n0 + wn * 64 + nt * 8 + (lane & 3) * 2;
            float d0 = acc[mt][nt][0], d1 = acc[mt][nt][1];
            float d2 = acc[mt][nt][2], d3 = acc[mt][nt][3];
            if (bias) {
                float b0 = bias[col], b1 = bias[col + 1];
                d0 += b0; d1 += b1; d2 += b0; d3 += b1;
            }
            if (flags & 2) {
                d0 = fmaxf(d0, 0.f); d1 = fmaxf(d1, 0.f);
                d2 = fmaxf(d2, 0.f); d3 = fmaxf(d3, 0.f);
            }
            if (H2b) {
                float f0 = H2b[col], f1 = H2b[col + 1];
                d0 *= f0; d1 *= f1; d2 *= f0; d3 *= f1;
            }
            long o0 = (long)row * ldc + col;
            long o1 = o0 + (long)8 * ldc;
            *reinterpret_cast<uint32_t*>(C + o0) = packh2(d0, d1);
            *reinterpret_cast<uint32_t*>(C + o1) = packh2(d2, d3);
        }
    }
}

// ---------------- flash global attention ---------------------------------------
#define FQ 0
#define FK 18432
#define FV 36864
#define FMSK 55296
#define FSMEM 57344
#define FLDQ 72

__global__ void __launch_bounds__(256, 1) flash_k(const float* __restrict__ mask,
                                                  float* __restrict__ outp)
{
    extern __shared__ char sm[];
    uint32_t sb = smem_u32(sm);
    float* mbias = reinterpret_cast<float*>(sm + FMSK);
    int tid = threadIdx.x, lane = tid & 31, w = tid >> 5;
    int b = blockIdx.y >> 3, h = blockIdx.y & 7;
    int l0 = blockIdx.x * 128;
    long base = (long)b * 512 * 1536;

    for (int i = tid; i < 1024; i += 256) {
        int row = i >> 3, u = i & 7;
        *reinterpret_cast<uint4*>(sm + FQ + row * 144 + u * 16) =
            *reinterpret_cast<const uint4*>(g_CT + base + (long)(l0 + row) * 1536 + 1024 + h * DH + u * 8);
    }
    for (int i = tid; i < 512; i += 256)
        mbias[i] = (mask[(long)b * 512 + i] != 0.f) ? 0.f : -1e9f;

    float O[8][4];
    #pragma unroll
    for (int i = 0; i < 8; i++)
        #pragma unroll
        for (int e = 0; e < 4; e++) O[i][e] = 0.f;
    float mrow[2] = {-1e30f, -1e30f}, lrow[2] = {0.f, 0.f};

    int alr = lane & 15, alc = (lane >> 4) << 3;
    int blr = (lane & 7) + (((lane >> 4) & 1) << 3), blc = ((lane >> 3) & 1) << 3;
    int btr = (lane & 7) + (((lane >> 3) & 1) << 3), btc = ((lane >> 4) & 1) << 3;
    int c0 = (lane & 3) * 2;

    for (int mi = 0; mi < 4; mi++) {
        int m0 = mi * 128;
        __syncthreads();
        for (int i = tid; i < 1024; i += 256) {
            int row = i >> 3, u = i & 7;
            long gq = base + (long)(m0 + row) * 1536 + h * DH + u * 8;
            *reinterpret_cast<uint4*>(sm + FK + row * 144 + u * 16) =
                *reinterpret_cast<const uint4*>(g_CT + gq);
            *reinterpret_cast<uint4*>(sm + FV + row * 144 + u * 16) =
                *reinterpret_cast<const uint4*>(g_CT + gq + 512);
        }
        __syncthreads();

        float S[16][4];
        #pragma unroll
        for (int i = 0; i < 16; i++)
            #pragma unroll
            for (int e = 0; e < 4; e++) S[i][e] = 0.f;

        #pragma unroll
        for (int kc = 0; kc < 4; kc++) {
            uint32_t q[4];
            LDM_X4(q, sb + FQ + (uint32_t)(((w * 16 + alr) * FLDQ + kc * 16 + alc) * 2));
            #pragma unroll
            for (int p = 0; p < 8; p++) {
                uint32_t kf[4];
                LDM_X4(kf, sb + FK + (uint32_t)(((p * 16 + blr) * FLDQ + kc * 16 + blc) * 2));
                uint32_t b0[2] = {kf[0], kf[1]}, b1[2] = {kf[2], kf[3]};
                MMAF16(S[2*p],   q, b0);
                MMAF16(S[2*p+1], q, b1);
            }
        }

        float cmax[2] = {-1e30f, -1e30f};
        #pragma unroll
        for (int nt = 0; nt < 16; nt++)
            #pragma unroll
            for (int e = 0; e < 4; e++) {
                int col = m0 + nt * 8 + c0 + (e & 1);
                float v = S[nt][e] * 0.125f + mbias[col];
                S[nt][e] = v;
                cmax[e >> 1] = fmaxf(cmax[e >> 1], v);
            }
        #pragma unroll
        for (int o = 1; o <= 2; o <<= 1) {
            cmax[0] = fmaxf(cmax[0], __shfl_xor_sync(0xffffffffu, cmax[0], o));
            cmax[1] = fmaxf(cmax[1], __shfl_xor_sync(0xffffffffu, cmax[1], o));
        }
        float mn0 = fmaxf(mrow[0], cmax[0]), mn1 = fmaxf(mrow[1], cmax[1]);
        float a0 = __expf(mrow[0] - mn0), a1 = __expf(mrow[1] - mn1);
        mrow[0] = mn0; mrow[1] = mn1;
        lrow[0] *= a0; lrow[1] *= a1;
        #pragma unroll
        for (int i = 0; i < 8; i++) {
            O[i][0] *= a0; O[i][1] *= a0; O[i][2] *= a1; O[i][3] *= a1;
        }
        #pragma unroll
        for (int nt = 0; nt < 16; nt++)
            #pragma unroll
            for (int e = 0; e < 4; e++) {
                float p = __expf(S[nt][e] - ((e < 2) ? mn0 : mn1));
                S[nt][e] = p;
                lrow[e >> 1] += p;
            }

        #pragma unroll
        for (int kc = 0; kc < 8; kc++) {
            uint32_t ph[4];
            ph[0] = packh2(S[2*kc][0],   S[2*kc][1]);
            ph[1] = packh2(S[2*kc][2],   S[2*kc][3]);
            ph[2] = packh2(S[2*kc+1][0], S[2*kc+1][1]);
            ph[3] = packh2(S[2*kc+1][2], S[2*kc+1][3]);
            #pragma unroll
            for (int p = 0; p < 4; p++) {
                uint32_t vh[4];
                LDM_X4T(vh, sb + FV + (uint32_t)(((kc * 16 + btr) * FLDQ + p * 16 + btc) * 2));
                uint32_t b0[2] = {vh[0], vh[1]}, b1[2] = {vh[2], vh[3]};
                MMAF16(O[2*p],   ph, b0);
                MMAF16(O[2*p+1], ph, b1);
            }
        }
    }

    #pragma unroll
    for (int o = 1; o <= 2; o <<= 1) {
        lrow[0] += __shfl_xor_sync(0xffffffffu, lrow[0], o);
        lrow[1] += __shfl_xor_sync(0xffffffffu, lrow[1], o);
    }
    float inv0 = 1.f / lrow[0], inv1 = 1.f / lrow[1];

    int r0g = l0 + w * 16 + (lane >> 2);
    #pragma unroll
    for (int nt = 0; nt < 8; nt++) {
        int col = h * DH + nt * 8 + c0;
        long o0 = ((long)b * 512 + r0g) * 512 + col;
        long o1 = o0 + 8 * 512;
        __half2 x0 = *reinterpret_cast<const __half2*>(g_A + o0);
        __half2 x1 = *reinterpret_cast<const __half2*>(g_A + o1);
        float d0 = __low2float(x0) + O[nt][0] * inv0;
        float d1 = __high2float(x0) + O[nt][1] * inv0;
        float d2 = __low2float(x1) + O[nt][2] * inv1;
        float d3 = __high2float(x1) + O[nt][3] * inv1;
        if (outp) {
            *reinterpret_cast<float2*>(outp + o0) = make_float2(d0, d1);
            *reinterpret_cast<float2*>(outp + o1) = make_float2(d2, d3);
        } else {
            *reinterpret_cast<uint32_t*>(g_A + o0) = packh2(d0, d1);
            *reinterpret_cast<uint32_t*>(g_A + o1) = packh2(d2, d3);
        }
    }
}

// ---------------- tiled banded local attention ---------------------------------
#define LSM_MQ 16384
#define LSM_MV 34816
#define LSM_BI 53248
#define LSMEM 53824

__global__ void __launch_bounds__(256, 1) local_attn_k(const float* __restrict__ mask)
{
    extern __shared__ char sm[];
    float* sBias = reinterpret_cast<float*>(sm + LSM_BI);
    int tid = threadIdx.x, lane = tid & 31, w = tid >> 5;
    int b = blockIdx.y >> 3, h = blockIdx.y & 7;
    int n = blockIdx.z;
    int l0 = blockIdx.x * 128;
    long base = (long)n * CTN + (long)b * 512 * 1536;

    for (int i = tid; i < 1024; i += 256) {
        int row = i >> 3, u = i & 7;
        *reinterpret_cast<uint4*>(sm + row * 128 + u * 16) =
            *reinterpret_cast<const uint4*>(g_CT + base + (long)(l0 + row) * 1536 + 1024 + h * DH + u * 8);
    }
    for (int i = tid; i < 142 * 8; i += 256) {
        int r = i >> 3, u = i & 7;
        int m = l0 - 7 + r;
        if (m >= 0 && m < 512) {
            long g = base + (long)m * 1536 + h * DH + u * 8;
            *reinterpret_cast<uint4*>(sm + LSM_MQ + r * 128 + u * 16) =
                *reinterpret_cast<const uint4*>(g_CT + g);
            *reinterpret_cast<uint4*>(sm + LSM_MV + r * 128 + u * 16) =
                *reinterpret_cast<const uint4*>(g_CT + g + 512);
        }
    }
    for (int i = tid; i < 142; i += 256) {
        int m = l0 - 7 + i;
        sBias[i] = (m >= 0 && m < 512) ? mask[(long)b * 512 + m] : 0.f;
    }
    __syncthreads();

    for (int j = 0; j < 16; j++) {
        int l = l0 + w * 16 + j;
        int lr = l - l0;
        __half2 kv = *reinterpret_cast<const __half2*>(sm + lr * 128 + lane * 4);
        float k0f = __low2float(kv), k1f = __high2float(kv);

        float sc[15];
        #pragma unroll
        for (int jj = 0; jj < 15; jj++) {
            int r = lr + jj;
            float s = -1e30f;
            if (sBias[r] != 0.f) {
                __half2 q = *reinterpret_cast<const __half2*>(sm + LSM_MQ + r * 128 + lane * 4);
                float d = k0f * __low2float(q) + k1f * __high2float(q);
                #pragma unroll
                for (int o = 16; o; o >>= 1) d += __shfl_xor_sync(0xffffffffu, d, o);
                s = d * 0.125f;
            }
            sc[jj] = s;
        }
        float mx = -1e30f;
        #pragma unroll
        for (int jj = 0; jj < 15; jj++) mx = fmaxf(mx, sc[jj]);
        float wgt[15], sum = 0.f;
        #pragma unroll
        for (int jj = 0; jj < 15; jj++) {
            wgt[jj] = (sc[jj] > -1e29f) ? expf(sc[jj] - mx) : 0.f;
            sum += wgt[jj];
        }
        float inv = 1.f / sum;
        float o0 = 0.f, o1 = 0.f;
        #pragma unroll
        for (int jj = 0; jj < 15; jj++) {
            if (wgt[jj] != 0.f) {
                int r = lr + jj;
                __half2 v = *reinterpret_cast<const __half2*>(sm + LSM_MV + r * 128 + lane * 4);
                float ww = wgt[jj] * inv;
                o0 = fmaf(ww, __low2float(v), o0);
                o1 = fmaf(ww, __high2float(v), o1);
            }
        }
        long xo = (long)n * BLD + ((long)b * 512 + l) * 512 + h * DH + lane * 2;
        __half2 xv = *reinterpret_cast<const __half2*>(g_M + xo);
        *reinterpret_cast<uint32_t*>(g_M + xo) =
            packh2(__low2float(xv) + o0, __high2float(xv) + o1);
    }
}

// ---------------- small kernels ------------------------------------------------
// h2 with 8 independent accumulators for MLP
__global__ void h2_k(const float* __restrict__ se, const float* __restrict__ w2,
                     const float* __restrict__ b2)
{
    int bn = blockIdx.x;
    int n = bn % Nn;
    int h = threadIdx.x;
    const float* x = se + (long)bn * Dd;
    const float* w = w2 + (long)n * Dd * Dd + h;
    float a0 = 0.f, a1 = 0.f, a2 = 0.f, a3 = 0.f;
    float a4 = 0.f, a5 = 0.f, a6 = 0.f, a7 = 0.f;
    #pragma unroll 8
    for (int d = 0; d < Dd; d += 8) {
        a0 = fmaf(x[d],     w[(long)d * Dd],           a0);
        a1 = fmaf(x[d + 1], w[(long)(d + 1) * Dd],     a1);
        a2 = fmaf(x[d + 2], w[(long)(d + 2) * Dd],     a2);
        a3 = fmaf(x[d + 3], w[(long)(d + 3) * Dd],     a3);
        a4 = fmaf(x[d + 4], w[(long)(d + 4) * Dd],     a4);
        a5 = fmaf(x[d + 5], w[(long)(d + 5) * Dd],     a5);
        a6 = fmaf(x[d + 6], w[(long)(d + 6) * Dd],     a6);
        a7 = fmaf(x[d + 7], w[(long)(d + 7) * Dd],     a7);
    }
    float acc = b2[n * Dd + h] + ((a0 + a1) + (a2 + a3)) + ((a4 + a5) + (a6 + a7));
    g_H2[(long)bn * Dd + h] = fmaxf(acc, 0.f);
}

__global__ void satt_k(const float* __restrict__ se, const float* __restrict__ w1,
                       const float* __restrict__ w2, float* __restrict__ out_tail)
{
    int b = blockIdx.x, t = threadIdx.x;
    __shared__ float red[256];
    __shared__ float alpha[Nn];
    for (int n = 0; n < Nn; n++) {
        const float* x = se + ((long)b * Nn + n) * Dd;
        float acc = 0.f;
        for (int d = 0; d < Dd; d++) acc = fmaf(x[d], w1[(long)d * AH + t], acc);
        red[t] = tanhf(acc) * w2[t];
        __syncthreads();
        for (int o = 128; o; o >>= 1) { if (t < o) red[t] += red[t + o]; __syncthreads(); }
        if (t == 0) alpha[n] = red[0];
        __syncthreads();
    }
    if (t == 0) {
        float mx = fmaxf(alpha[0], fmaxf(alpha[1], alpha[2]));
        float e[Nn], sum = 0.f;
        for (int n = 0; n < Nn; n++) { e[n] = expf(alpha[n] - mx); sum += e[n]; }
        for (int n = 0; n < Nn; n++) {
            float w = e[n] / sum;
            g_SW[b * Nn + n] = w;
            out_tail[b * Nn + n] = w;
        }
    }
}

__global__ void agg_k()
{
    long half_total = BLD / 2;
    long stride = (long)Ll * Dd / 2;
    for (long i = (long)blockIdx.x * blockDim.x + threadIdx.x; i < half_total;
         i += (long)gridDim.x * blockDim.x) {
        int b = (int)(i / stride);
        float a0 = 0.f, a1 = 0.f;
        #pragma unroll
        for (int n = 0; n < Nn; n++) {
            float sw = g_SW[b * Nn + n];
            __half2 v = *reinterpret_cast<const __half2*>(g_M + (long)n * BLD + i * 2);
            a0 = fmaf(sw, __low2float(v), a0);
            a1 = fmaf(sw, __high2float(v), a1);
        }
        *reinterpret_cast<uint32_t*>(g_A + i * 2) = packh2(a0, a1);
    }
}

// ---------------- host orchestration ------------------------------------------
static void mgemm(const __half* A, const __half* WH,
                  const float* bias, const float* H2, __half* C,
                  int N, int K, int lda, int ldc, int batches,
                  long sAi, long sBi, long sCi, long sBias, int flags)
{
    dim3 grid(N / 256, 64, batches);
    mma_gemm_k<<<grid, 256, GSMEM>>>(A, WH, bias, H2, C, K,
                                     lda, ldc, sAi, sBi, sCi, sBias, flags);
}

extern "C" void kernel_launch(void* const* d_in, const int* in_sizes, int n_in,
                              void* d_out, int out_size)
{
    const float* seg   = (const float*)d_in[0];
    const float* mask  = (const float*)d_in[1];
    const float* se    = (const float*)d_in[2];
    const float* hw1   = (const float*)d_in[3];
    const float* hb1   = (const float*)d_in[4];
    const float* hw2   = (const float*)d_in[5];
    const float* hb2   = (const float*)d_in[6];
    const float* hw3   = (const float*)d_in[7];
    const float* hb3   = (const float*)d_in[8];
    const float* lcW   = (const float*)d_in[9];
    const float* lcb   = (const float*)d_in[10];
    const float* lvW   = (const float*)d_in[11];
    const float* lvb   = (const float*)d_in[12];
    const float* gcW   = (const float*)d_in[13];
    const float* gcb   = (const float*)d_in[14];
    const float* gvW   = (const float*)d_in[15];
    const float* gvb   = (const float*)d_in[16];
    const float* sw1   = (const float*)d_in[17];
    const float* sw2   = (const float*)d_in[18];
    float* out = (float*)d_out;

    cudaFuncSetAttribute(mma_gemm_k,   cudaFuncAttributeMaxDynamicSharedMemorySize, GSMEM);
    cudaFuncSetAttribute(flash_k,      cudaFuncAttributeMaxDynamicSharedMemorySize, FSMEM);
    cudaFuncSetAttribute(local_attn_k, cudaFuncAttributeMaxDynamicSharedMemorySize, LSMEM);

    __half *pSeg, *pWH, *pB1, *pM, *pCT, *pA;
    float *pBias, *pH2;
    cudaGetSymbolAddress((void**)&pSeg, g_seg);
    cudaGetSymbolAddress((void**)&pWH, g_WH);
    cudaGetSymbolAddress((void**)&pB1, g_B1);
    cudaGetSymbolAddress((void**)&pM,  g_M);
    cudaGetSymbolAddress((void**)&pCT, g_CT);
    cudaGetSymbolAddress((void**)&pA,  g_A);
    cudaGetSymbolAddress((void**)&pBias, g_biasC);
    cudaGetSymbolAddress((void**)&pH2, g_H2);

    // prepasses
    cvt_k<<<1024, 256>>>(seg, pSeg, BLD);
    wtile_all_k<<<1024, 256>>>(hw1, hw3, lcW, lvW, gcW, gvW);
    biascat_k<<<8, 256>>>(lcb, lvb, gcb, gvb);

    // 1) h2
    h2_k<<<Bb * Nn, Dd>>>(se, hw2, hb2);

    // 2) h1 = relu(seg @ w1 + b1) * h2
    mgemm(pSeg, pWH + OFF_HW1, hb1, pH2, pB1,
          512, 512, 512, 512, Nn, 0, 262144L, BLD, 512, 2 | 8);

    // 3) m = relu(h1m @ w3 + b3)
    mgemm(pB1, pWH + OFF_HW3, hb3, nullptr, pM,
          512, 512, 512, 512, Nn, BLD, 262144L, BLD, 512, 2);

    // 4) local NL: projection + tiled banded attention
    for (int s = 0; s < 2; s++) {
        mgemm(pM, pWH + OFF_LCV + (long)s * 786432, pBias + s * 1536, nullptr, pCT,
              1536, 512, 512, 1536, Nn, BLD, 2L * 786432, CTN, 3072, 0);
        local_attn_k<<<dim3(4, Bb * Hh, Nn), 256, LSMEM>>>(mask);
    }

    // 5) segment attention weights
    satt_k<<<Bb, AH>>>(se, sw1, sw2, out + BLD);

    // 6) aggregate
    agg_k<<<2048, 256>>>();

    // 7) global NL: projection + flash attention
    for (int s = 0; s < 2; s++) {
        mgemm(pA, pWH + OFF_GCV + (long)s * 786432, pBias + (6 + s) * 1536, nullptr, pCT,
              1536, 512, 512, 1536, 1, 0, 0, 0, 0, 0);
        flash_k<<<dim3(4, Bb * Hh), 256, FSMEM>>>(mask, (s == 1) ? out : nullptr);
    }
}

// round 11
// speedup vs baseline: 3.1129x; 1.0805x over previous
#include <cuda_runtime.h>
#include <cuda_fp16.h>
#include <math.h>
#include <stdint.h>

#define Bb 16
#define Ll 512
#define Dd 512
#define Nn 3
#define Hh 8
#define DH 64
#define AH 256
#define KHALF 7

#define BLD 4194304L        // Bb*Ll*Dd
#define CTN 12582912L       // 8192*1536 per n
#define CTSZ 37748736L      // 3 * CTN

// ---------------- scratch ------------------------------------------------------
__device__ __half g_seg[BLD];
__device__ __half g_WH[7864320];                  // fp16, tiled 32x128 blocks
__device__ __half g_B1[3*BLD];
__device__ __half g_M [3*BLD];
__device__ __half g_CT[CTSZ];                     // [n][8192][1536] mq|mv|mk
__device__ __half g_A [BLD];
__device__ float g_H2[Bb*Nn*Dd];
__device__ float g_SW[Bb*Nn];
__device__ float g_biasC[8*1536];

#define OFF_HW1 0L
#define OFF_HW3 786432L
#define OFF_LCV 1572864L
#define OFF_GCV 6291456L

// ---------------- PTX helpers --------------------------------------------------
__device__ __forceinline__ uint32_t smem_u32(const void* p) {
    uint32_t a;
    asm("{ .reg .u64 t; cvta.to.shared.u64 t, %1; cvt.u32.u64 %0, t; }" : "=r"(a) : "l"(p));
    return a;
}
#define CPA16(dst, src) asm volatile( \
    "cp.async.ca.shared.global [%0], [%1], 16;" :: "r"(dst), "l"(__cvta_generic_to_global(src)))
#define CPA_COMMIT() asm volatile("cp.async.commit_group;" ::: "memory")
#define CPA_WAIT1()  asm volatile("cp.async.wait_group 1;" ::: "memory")

#define BULK(dst, src, sz, mb) asm volatile( \
    "cp.async.bulk.shared::cta.global.mbarrier::complete_tx::bytes [%0], [%1], %2, [%3];" \
    :: "r"(dst), "l"(__cvta_generic_to_global(src)), "r"((uint32_t)(sz)), "r"(mb) : "memory")

#define MBAR_INIT(mb, c)   asm volatile("mbarrier.init.shared.b64 [%0], %1;" :: "r"(mb), "r"((uint32_t)(c)) : "memory")
#define MBAR_EXPECT(mb, tx) asm volatile("mbarrier.arrive.expect_tx.shared.b64 _, [%0], %1;" :: "r"(mb), "r"((uint32_t)(tx)) : "memory")
#define FENCE_ASYNC_SHARED() asm volatile("fence.proxy.async.shared::cta;" ::: "memory")
#define MBAR_WAIT(mb, ph) do { \
    uint32_t _m = (mb), _p = (ph), _d; \
    asm volatile("{\n\t.reg .pred p;\n\tmbarrier.try_wait.parity.acquire.cta.shared::cta.b64 p, [%1], %2;\n\tselp.b32 %0, 1, 0, p;\n\t}" \
        : "=r"(_d) : "r"(_m), "r"(_p) : "memory"); \
    if (!_d) { \
        asm volatile("{\n\t.reg .pred P1;\n\tWL_%=:\n\tmbarrier.try_wait.parity.acquire.cta.shared::cta.b64 P1, [%0], %1, 0x989680;\n\t@P1 bra.uni WD_%=;\n\tbra.uni WL_%=;\n\tWD_%=:\n\t}" \
            :: "r"(_m), "r"(_p) : "memory"); \
    } } while (0)

#define LDM_X4(r, a) asm volatile( \
    "ldmatrix.sync.aligned.m8n8.x4.shared.b16 {%0,%1,%2,%3}, [%4];" \
    : "=r"((r)[0]),"=r"((r)[1]),"=r"((r)[2]),"=r"((r)[3]) : "r"(a))
#define LDM_X4T(r, a) asm volatile( \
    "ldmatrix.sync.aligned.m8n8.x4.trans.shared.b16 {%0,%1,%2,%3}, [%4];" \
    : "=r"((r)[0]),"=r"((r)[1]),"=r"((r)[2]),"=r"((r)[3]) : "r"(a))
#define MMAF16(d, a, b) asm volatile( \
    "mma.sync.aligned.m16n8k16.row.col.f32.f16.f16.f32 " \
    "{%0,%1,%2,%3}, {%4,%5,%6,%7}, {%8,%9}, {%0,%1,%2,%3};" \
    : "+f"((d)[0]),"+f"((d)[1]),"+f"((d)[2]),"+f"((d)[3]) \
    : "r"((a)[0]),"r"((a)[1]),"r"((a)[2]),"r"((a)[3]), "r"((b)[0]),"r"((b)[1]))

__device__ __forceinline__ uint32_t packh2(float a, float b) {
    __half2 t = __floats2half2_rn(a, b);
    return *reinterpret_cast<uint32_t*>(&t);
}

// ---------------- prepasses ----------------------------------------------------
__global__ void cvt_k(const float* __restrict__ s, __half* __restrict__ d, long n)
{
    for (long i = ((long)blockIdx.x * blockDim.x + threadIdx.x) * 4; i < n;
         i += (long)gridDim.x * blockDim.x * 4) {
        float4 v = *reinterpret_cast<const float4*>(s + i);
        uint2 o;
        o.x = packh2(v.x, v.y);
        o.y = packh2(v.z, v.w);
        *reinterpret_cast<uint2*>(d + i) = o;
    }
}

// all weight tiling in ONE launch; fp16 single
__global__ void wtile_all_k(const float* __restrict__ hw1, const float* __restrict__ hw3,
                            const float* __restrict__ lcW, const float* __restrict__ lvW,
                            const float* __restrict__ gcW, const float* __restrict__ gvW)
{
    const float* srcs[6] = {hw1, hw3, lcW, lvW, gcW, gvW};
    const long  woff[6]  = {OFF_HW1, OFF_HW3, OFF_LCV, OFF_LCV, OFF_GCV, OFF_GCV};
    const int   C1s[6]   = {512, 512, 1024, 512, 1024, 512};
    const int   coff[6]  = {0, 0, 0, 1024, 0, 1024};
    const long  dss[6]   = {262144L, 262144L, 786432L, 786432L, 786432L, 786432L};
    const long  tots[6]  = {786432L, 786432L, 3145728L, 1572864L, 1048576L, 524288L};

    long gstride = (long)gridDim.x * blockDim.x * 4;
    #pragma unroll 1
    for (int sg = 0; sg < 6; sg++) {
        const float* s = srcs[sg];
        int C1 = C1s[sg];
        long sS = 512L * C1;
        for (long i = ((long)blockIdx.x * blockDim.x + threadIdx.x) * 4; i < tots[sg];
             i += gstride) {
            float4 v = *reinterpret_cast<const float4*>(s + i);
            long sl = i / sS;
            long rem = i - sl * sS;
            int k = (int)(rem / C1), c = (int)(rem - (long)(rem / C1) * C1);
            int n = coff[sg] + c;
            long d = woff[sg] + sl * dss[sg] + ((long)((n >> 7) * 16 + (k >> 5))) * 4096
                   + (k & 31) * 128 + ((((n & 127) >> 3) ^ (k & 7)) << 3) + (n & 7);
            float vv[4] = {v.x, v.y, v.z, v.w};
            #pragma unroll
            for (int e = 0; e < 4; e++)
                g_WH[d + e] = __float2half_rn(vv[e]);
        }
    }
}

__global__ void biascat_k(const float* __restrict__ lcb, const float* __restrict__ lvb,
                          const float* __restrict__ gcb, const float* __restrict__ gvb)
{
    int slot = blockIdx.x;
    for (int c = threadIdx.x; c < 1536; c += blockDim.x) {
        float v;
        if (slot < 6) v = (c < 1024) ? lcb[slot * 1024 + c] : lvb[slot * 512 + c - 1024];
        else {
            int s = slot - 6;
            v = (c < 1024) ? gcb[s * 1024 + c] : gvb[s * 512 + c - 1024];
        }
        g_biasC[slot * 1536 + c] = v;
    }
}

// ---------------- GEMM: fp16 A x fp16 W, 1 MMA/k16, BN=256 ---------------------
// flags: 2=relu, 8=mul by H2
#define GSMEM 79904
__global__ void __launch_bounds__(256, 1) mma_gemm_k(
    const __half* __restrict__ A, const __half* __restrict__ WH,
    const float* __restrict__ bias, const float* __restrict__ H2,
    __half* __restrict__ C,
    int K, int lda, int ldc,
    long sAi, long sBi, long sCi, long sBias, int flags)
{
    constexpr int LDS = 40;
    constexpr int A_BYTES = 128 * LDS * 2;     // 10240
    constexpr int BHI = 16384;
    constexpr int STAGE = A_BYTES + BHI;       // 26624
    extern __shared__ char dsm[];
    uint32_t sb0 = smem_u32(dsm);
    uint32_t mbar0 = sb0 + 3 * STAGE;

    int z = blockIdx.z;
    A  += z * sAi;
    WH += z * sBi;
    C  += z * sCi;
    if (bias) bias += z * sBias;

    int tid = threadIdx.x, lane = tid & 31, wid = tid >> 5;
    int wm = wid & 1, wn = wid >> 1;
    int m0 = blockIdx.y * 128;
    int bx = blockIdx.x, n0 = bx * 256;
    int nc = K / 32;

    if (tid == 0) {
        MBAR_INIT(mbar0, 1); MBAR_INIT(mbar0 + 8, 1); MBAR_INIT(mbar0 + 16, 1);
        FENCE_ASYNC_SHARED();
    }
    __syncthreads();

    auto fillA = [&](int c) {
        int k0 = c * 32;
        uint32_t st = sb0 + (c % 3) * STAGE;
        #pragma unroll
        for (int it = 0; it < 2; it++) {
            int idx = tid + it * 256;
            int row = idx >> 2, u = idx & 3;
            CPA16(st + row * 80 + u * 16, A + (long)(m0 + row) * lda + k0 + u * 8);
        }
    };
    auto fillB = [&](int c) {
        uint32_t st = sb0 + (c % 3) * STAGE + A_BYTES;
        uint32_t mb = mbar0 + (c % 3) * 8;
        MBAR_EXPECT(mb, 16384u);
        long off0 = ((long)(bx * 2) * nc + c) * 4096;
        long off1 = ((long)(bx * 2 + 1) * nc + c) * 4096;
        BULK(st,        WH + off0, 8192, mb);
        BULK(st + 8192, WH + off1, 8192, mb);
    };

    float acc[4][8][4] = {};

    fillA(0); CPA_COMMIT();
    fillA(1); CPA_COMMIT();
    if (tid == 0) { fillB(0); fillB(1); }

    int alr = lane & 15, alc = (lane >> 4) << 3;
    int btr = (lane & 7) + (((lane >> 3) & 1) << 3);
    int btcc = (lane >> 4) & 1;

    for (int c = 0; c < nc; c++) {
        CPA_WAIT1();
        MBAR_WAIT(mbar0 + (c % 3) * 8, (c / 3) & 1);
        __syncthreads();
        if (c + 2 < nc) { fillA(c + 2); if (tid == 0) fillB(c + 2); }
        CPA_COMMIT();

        uint32_t base = sb0 + (c % 3) * STAGE;
        uint32_t aA = base + ((wm * 64 + alr) * LDS + alc) * 2;
        uint32_t bB = base + A_BYTES + (wn >> 1) * 8192;

        #pragma unroll
        for (int kk = 0; kk < 2; kk++) {
            uint32_t ah[4][4], bh[8][2];
            #pragma unroll
            for (int mt = 0; mt < 4; mt++)
                LDM_X4(ah[mt], aA + (uint32_t)((mt * 16 * LDS + kk * 16) * 2));
            int krow = kk * 16 + btr;
            #pragma unroll
            for (int p = 0; p < 4; p++) {
                int c16 = (wn & 1) * 8 + p * 2 + btcc;
                uint32_t ad = bB + (uint32_t)(krow * 256 + ((c16 ^ (krow & 7)) << 4));
                uint32_t r[4];
                LDM_X4T(r, ad);
                bh[2*p][0]=r[0]; bh[2*p][1]=r[1]; bh[2*p+1][0]=r[2]; bh[2*p+1][1]=r[3];
            }
            #pragma unroll
            for (int mt = 0; mt < 4; mt++)
                #pragma unroll
                for (int nt = 0; nt < 8; nt++)
                    MMAF16(acc[mt][nt], ah[mt], bh[nt]);
        }
    }

    const float* H2b = (flags & 8) ? (H2 + ((long)(m0 >> 9) * Nn + z) * 512) : nullptr;

    #pragma unroll
    for (int mt = 0; mt < 4; mt++) {
        int row = m0 + wm * 64 + mt * 16 + (lane >> 2);
        #pragma unroll
        for (int nt = 0; nt < 8; nt++) {
            int col = n0 + wn * 64 + nt * 8 + (lane & 3) * 2;
            float d0 = acc[mt][nt][0], d1 = acc[mt][nt][1];
            float d2 = acc[mt][nt][2], d3 = acc[mt][nt][3];
            if (bias) {
                float b0 = bias[col], b1 = bias[col + 1];
                d0 += b0; d1 += b1; d2 += b0; d3 += b1;
            }
            if (flags & 2) {
                d0 = fmaxf(d0, 0.f); d1 = fmaxf(d1, 0.f);
                d2 = fmaxf(d2, 0.f); d3 = fmaxf(d3, 0.f);
            }
            if (H2b) {
                float f0 = H2b[col], f1 = H2b[col + 1];
                d0 *= f0; d1 *= f1; d2 *= f0; d3 *= f1;
            }
            long o0 = (long)row * ldc + col;
            long o1 = o0 + (long)8 * ldc;
            *reinterpret_cast<uint32_t*>(C + o0) = packh2(d0, d1);
            *reinterpret_cast<uint32_t*>(C + o1) = packh2(d2, d3);
        }
    }
}

// ---------------- flash global attention ---------------------------------------
#define FQ 0
#define FK 18432
#define FV 36864
#define FMSK 55296
#define FSMEM 57344
#define FLDQ 72

__global__ void __launch_bounds__(256, 1) flash_k(const float* __restrict__ mask,
                                                  float* __restrict__ outp)
{
    extern __shared__ char sm[];
    uint32_t sb = smem_u32(sm);
    float* mbias = reinterpret_cast<float*>(sm + FMSK);
    int tid = threadIdx.x, lane = tid & 31, w = tid >> 5;
    int b = blockIdx.y >> 3, h = blockIdx.y & 7;
    int l0 = blockIdx.x * 128;
    long base = (long)b * 512 * 1536;

    for (int i = tid; i < 1024; i += 256) {
        int row = i >> 3, u = i & 7;
        *reinterpret_cast<uint4*>(sm + FQ + row * 144 + u * 16) =
            *reinterpret_cast<const uint4*>(g_CT + base + (long)(l0 + row) * 1536 + 1024 + h * DH + u * 8);
    }
    for (int i = tid; i < 512; i += 256)
        mbias[i] = (mask[(long)b * 512 + i] != 0.f) ? 0.f : -1e9f;

    float O[8][4];
    #pragma unroll
    for (int i = 0; i < 8; i++)
        #pragma unroll
        for (int e = 0; e < 4; e++) O[i][e] = 0.f;
    float mrow[2] = {-1e30f, -1e30f}, lrow[2] = {0.f, 0.f};

    int alr = lane & 15, alc = (lane >> 4) << 3;
    int blr = (lane & 7) + (((lane >> 4) & 1) << 3), blc = ((lane >> 3) & 1) << 3;
    int btr = (lane & 7) + (((lane >> 3) & 1) << 3), btc = ((lane >> 4) & 1) << 3;
    int c0 = (lane & 3) * 2;

    for (int mi = 0; mi < 4; mi++) {
        int m0 = mi * 128;
        __syncthreads();
        for (int i = tid; i < 1024; i += 256) {
            int row = i >> 3, u = i & 7;
            long gq = base + (long)(m0 + row) * 1536 + h * DH + u * 8;
            *reinterpret_cast<uint4*>(sm + FK + row * 144 + u * 16) =
                *reinterpret_cast<const uint4*>(g_CT + gq);
            *reinterpret_cast<uint4*>(sm + FV + row * 144 + u * 16) =
                *reinterpret_cast<const uint4*>(g_CT + gq + 512);
        }
        __syncthreads();

        float S[16][4];
        #pragma unroll
        for (int i = 0; i < 16; i++)
            #pragma unroll
            for (int e = 0; e < 4; e++) S[i][e] = 0.f;

        #pragma unroll
        for (int kc = 0; kc < 4; kc++) {
            uint32_t q[4];
            LDM_X4(q, sb + FQ + (uint32_t)(((w * 16 + alr) * FLDQ + kc * 16 + alc) * 2));
            #pragma unroll
            for (int p = 0; p < 8; p++) {
                uint32_t kf[4];
                LDM_X4(kf, sb + FK + (uint32_t)(((p * 16 + blr) * FLDQ + kc * 16 + blc) * 2));
                uint32_t b0[2] = {kf[0], kf[1]}, b1[2] = {kf[2], kf[3]};
                MMAF16(S[2*p],   q, b0);
                MMAF16(S[2*p+1], q, b1);
            }
        }

        float cmax[2] = {-1e30f, -1e30f};
        #pragma unroll
        for (int nt = 0; nt < 16; nt++)
            #pragma unroll
            for (int e = 0; e < 4; e++) {
                int col = m0 + nt * 8 + c0 + (e & 1);
                float v = S[nt][e] * 0.125f + mbias[col];
                S[nt][e] = v;
                cmax[e >> 1] = fmaxf(cmax[e >> 1], v);
            }
        #pragma unroll
        for (int o = 1; o <= 2; o <<= 1) {
            cmax[0] = fmaxf(cmax[0], __shfl_xor_sync(0xffffffffu, cmax[0], o));
            cmax[1] = fmaxf(cmax[1], __shfl_xor_sync(0xffffffffu, cmax[1], o));
        }
        float mn0 = fmaxf(mrow[0], cmax[0]), mn1 = fmaxf(mrow[1], cmax[1]);
        float a0 = __expf(mrow[0] - mn0), a1 = __expf(mrow[1] - mn1);
        mrow[0] = mn0; mrow[1] = mn1;
        lrow[0] *= a0; lrow[1] *= a1;
        #pragma unroll
        for (int i = 0; i < 8; i++) {
            O[i][0] *= a0; O[i][1] *= a0; O[i][2] *= a1; O[i][3] *= a1;
        }
        #pragma unroll
        for (int nt = 0; nt < 16; nt++)
            #pragma unroll
            for (int e = 0; e < 4; e++) {
                float p = __expf(S[nt][e] - ((e < 2) ? mn0 : mn1));
                S[nt][e] = p;
                lrow[e >> 1] += p;
            }

        #pragma unroll
        for (int kc = 0; kc < 8; kc++) {
            uint32_t ph[4];
            ph[0] = packh2(S[2*kc][0],   S[2*kc][1]);
            ph[1] = packh2(S[2*kc][2],   S[2*kc][3]);
            ph[2] = packh2(S[2*kc+1][0], S[2*kc+1][1]);
            ph[3] = packh2(S[2*kc+1][2], S[2*kc+1][3]);
            #pragma unroll
            for (int p = 0; p < 4; p++) {
                uint32_t vh[4];
                LDM_X4T(vh, sb + FV + (uint32_t)(((kc * 16 + btr) * FLDQ + p * 16 + btc) * 2));
                uint32_t b0[2] = {vh[0], vh[1]}, b1[2] = {vh[2], vh[3]};
                MMAF16(O[2*p],   ph, b0);
                MMAF16(O[2*p+1], ph, b1);
            }
        }
    }

    #pragma unroll
    for (int o = 1; o <= 2; o <<= 1) {
        lrow[0] += __shfl_xor_sync(0xffffffffu, lrow[0], o);
        lrow[1] += __shfl_xor_sync(0xffffffffu, lrow[1], o);
    }
    float inv0 = 1.f / lrow[0], inv1 = 1.f / lrow[1];

    int r0g = l0 + w * 16 + (lane >> 2);
    #pragma unroll
    for (int nt = 0; nt < 8; nt++) {
        int col = h * DH + nt * 8 + c0;
        long o0 = ((long)b * 512 + r0g) * 512 + col;
        long o1 = o0 + 8 * 512;
        __half2 x0 = *reinterpret_cast<const __half2*>(g_A + o0);
        __half2 x1 = *reinterpret_cast<const __half2*>(g_A + o1);
        float d0 = __low2float(x0) + O[nt][0] * inv0;
        float d1 = __high2float(x0) + O[nt][1] * inv0;
        float d2 = __low2float(x1) + O[nt][2] * inv1;
        float d3 = __high2float(x1) + O[nt][3] * inv1;
        if (outp) {
            *reinterpret_cast<float2*>(outp + o0) = make_float2(d0, d1);
            *reinterpret_cast<float2*>(outp + o1) = make_float2(d2, d3);
        } else {
            *reinterpret_cast<uint32_t*>(g_A + o0) = packh2(d0, d1);
            *reinterpret_cast<uint32_t*>(g_A + o1) = packh2(d2, d3);
        }
    }
}

// ---------------- tiled banded local attention ---------------------------------
#define LSM_MQ 16384
#define LSM_MV 34816
#define LSM_BI 53248
#define LSMEM 53824

__global__ void __launch_bounds__(256, 1) local_attn_k(const float* __restrict__ mask)
{
    extern __shared__ char sm[];
    float* sBias = reinterpret_cast<float*>(sm + LSM_BI);
    int tid = threadIdx.x, lane = tid & 31, w = tid >> 5;
    int b = blockIdx.y >> 3, h = blockIdx.y & 7;
    int n = blockIdx.z;
    int l0 = blockIdx.x * 128;
    long base = (long)n * CTN + (long)b * 512 * 1536;

    for (int i = tid; i < 1024; i += 256) {
        int row = i >> 3, u = i & 7;
        *reinterpret_cast<uint4*>(sm + row * 128 + u * 16) =
            *reinterpret_cast<const uint4*>(g_CT + base + (long)(l0 + row) * 1536 + 1024 + h * DH + u * 8);
    }
    for (int i = tid; i < 142 * 8; i += 256) {
        int r = i >> 3, u = i & 7;
        int m = l0 - 7 + r;
        if (m >= 0 && m < 512) {
            long g = base + (long)m * 1536 + h * DH + u * 8;
            *reinterpret_cast<uint4*>(sm + LSM_MQ + r * 128 + u * 16) =
                *reinterpret_cast<const uint4*>(g_CT + g);
            *reinterpret_cast<uint4*>(sm + LSM_MV + r * 128 + u * 16) =
                *reinterpret_cast<const uint4*>(g_CT + g + 512);
        }
    }
    for (int i = tid; i < 142; i += 256) {
        int m = l0 - 7 + i;
        sBias[i] = (m >= 0 && m < 512) ? mask[(long)b * 512 + m] : 0.f;
    }
    __syncthreads();

    for (int j = 0; j < 16; j++) {
        int l = l0 + w * 16 + j;
        int lr = l - l0;
        __half2 kv = *reinterpret_cast<const __half2*>(sm + lr * 128 + lane * 4);
        float k0f = __low2float(kv), k1f = __high2float(kv);

        float sc[15];
        #pragma unroll
        for (int jj = 0; jj < 15; jj++) {
            int r = lr + jj;
            float s = -1e30f;
            if (sBias[r] != 0.f) {
                __half2 q = *reinterpret_cast<const __half2*>(sm + LSM_MQ + r * 128 + lane * 4);
                float d = k0f * __low2float(q) + k1f * __high2float(q);
                #pragma unroll
                for (int o = 16; o; o >>= 1) d += __shfl_xor_sync(0xffffffffu, d, o);
                s = d * 0.125f;
            }
            sc[jj] = s;
        }
        float mx = -1e30f;
        #pragma unroll
        for (int jj = 0; jj < 15; jj++) mx = fmaxf(mx, sc[jj]);
        float wgt[15], sum = 0.f;
        #pragma unroll
        for (int jj = 0; jj < 15; jj++) {
            wgt[jj] = (sc[jj] > -1e29f) ? expf(sc[jj] - mx) : 0.f;
            sum += wgt[jj];
        }
        float inv = 1.f / sum;
        float o0 = 0.f, o1 = 0.f;
        #pragma unroll
        for (int jj = 0; jj < 15; jj++) {
            if (wgt[jj] != 0.f) {
                int r = lr + jj;
                __half2 v = *reinterpret_cast<const __half2*>(sm + LSM_MV + r * 128 + lane * 4);
                float ww = wgt[jj] * inv;
                o0 = fmaf(ww, __low2float(v), o0);
                o1 = fmaf(ww, __high2float(v), o1);
            }
        }
        long xo = (long)n * BLD + ((long)b * 512 + l) * 512 + h * DH + lane * 2;
        __half2 xv = *reinterpret_cast<const __half2*>(g_M + xo);
        *reinterpret_cast<uint32_t*>(g_M + xo) =
            packh2(__low2float(xv) + o0, __high2float(xv) + o1);
    }
}

// ---------------- small kernels ------------------------------------------------
// h2: grid (Bb*Nn, 4), block (128, 8); d-split partials + smem reduce
__global__ void h2_k(const float* __restrict__ se, const float* __restrict__ w2,
                     const float* __restrict__ b2)
{
    __shared__ float red[8][128];
    int bn = blockIdx.x;
    int n = bn % Nn;
    int h = blockIdx.y * 128 + threadIdx.x;
    int ty = threadIdx.y;
    const float* x = se + (long)bn * Dd;
    const float* w = w2 + (long)n * Dd * Dd + h;
    int d0 = ty * 64;
    float a0 = 0.f, a1 = 0.f, a2 = 0.f, a3 = 0.f;
    #pragma unroll 4
    for (int d = d0; d < d0 + 64; d += 4) {
        a0 = fmaf(x[d],     w[(long)d * Dd],       a0);
        a1 = fmaf(x[d + 1], w[(long)(d + 1) * Dd], a1);
        a2 = fmaf(x[d + 2], w[(long)(d + 2) * Dd], a2);
        a3 = fmaf(x[d + 3], w[(long)(d + 3) * Dd], a3);
    }
    red[ty][threadIdx.x] = (a0 + a1) + (a2 + a3);
    __syncthreads();
    if (ty == 0) {
        float acc = b2[n * Dd + h];
        #pragma unroll
        for (int e = 0; e < 8; e++) acc += red[e][threadIdx.x];
        g_H2[(long)bn * Dd + h] = fmaxf(acc, 0.f);
    }
}

// satt: grid Bb, block (256, 4); d-split partials + smem reduce
__global__ void satt_k(const float* __restrict__ se, const float* __restrict__ w1,
                       const float* __restrict__ w2, float* __restrict__ out_tail)
{
    __shared__ float red[4][256];
    __shared__ float s1[256];
    __shared__ float alpha[Nn];
    int b = blockIdx.x, t = threadIdx.x, y = threadIdx.y;
    for (int n = 0; n < Nn; n++) {
        const float* x = se + ((long)b * Nn + n) * Dd;
        int d0 = y * 128;
        float a0 = 0.f, a1 = 0.f, a2 = 0.f, a3 = 0.f;
        #pragma unroll 4
        for (int d = d0; d < d0 + 128; d += 4) {
            a0 = fmaf(x[d],     w1[(long)d * AH + t],       a0);
            a1 = fmaf(x[d + 1], w1[(long)(d + 1) * AH + t], a1);
            a2 = fmaf(x[d + 2], w1[(long)(d + 2) * AH + t], a2);
            a3 = fmaf(x[d + 3], w1[(long)(d + 3) * AH + t], a3);
        }
        red[y][t] = (a0 + a1) + (a2 + a3);
        __syncthreads();
        if (y == 0) {
            float dot = red[0][t] + red[1][t] + red[2][t] + red[3][t];
            s1[t] = tanhf(dot) * w2[t];
        }
        __syncthreads();
        for (int o = 128; o; o >>= 1) {
            if (y == 0 && t < o) s1[t] += s1[t + o];
            __syncthreads();
        }
        if (y == 0 && t == 0) alpha[n] = s1[0];
        __syncthreads();
    }
    if (y == 0 && t == 0) {
        float mx = fmaxf(alpha[0], fmaxf(alpha[1], alpha[2]));
        float e[Nn], sum = 0.f;
        for (int n = 0; n < Nn; n++) { e[n] = expf(alpha[n] - mx); sum += e[n]; }
        for (int n = 0; n < Nn; n++) {
            float w = e[n] / sum;
            g_SW[b * Nn + n] = w;
            out_tail[b * Nn + n] = w;
        }
    }
}

__global__ void agg_k()
{
    long half_total = BLD / 2;
    long stride = (long)Ll * Dd / 2;
    for (long i = (long)blockIdx.x * blockDim.x + threadIdx.x; i < half_total;
         i += (long)gridDim.x * blockDim.x) {
        int b = (int)(i / stride);
        float a0 = 0.f, a1 = 0.f;
        #pragma unroll
        for (int n = 0; n < Nn; n++) {
            float sw = g_SW[b * Nn + n];
            __half2 v = *reinterpret_cast<const __half2*>(g_M + (long)n * BLD + i * 2);
            a0 = fmaf(sw, __low2float(v), a0);
            a1 = fmaf(sw, __high2float(v), a1);
        }
        *reinterpret_cast<uint32_t*>(g_A + i * 2) = packh2(a0, a1);
    }
}

// ---------------- host orchestration ------------------------------------------
static void mgemm(const __half* A, const __half* WH,
                  const float* bias, const float* H2, __half* C,
                  int N, int K, int lda, int ldc, int batches,
                  long sAi, long sBi, long sCi, long sBias, int flags)
{
    dim3 grid(N / 256, 64, batches);
    mma_gemm_k<<<grid, 256, GSMEM>>>(A, WH, bias, H2, C, K,
                                     lda, ldc, sAi, sBi, sCi, sBias, flags);
}

extern "C" void kernel_launch(void* const* d_in, const int* in_sizes, int n_in,
                              void* d_out, int out_size)
{
    const float* seg   = (const float*)d_in[0];
    const float* mask  = (const float*)d_in[1];
    const float* se    = (const float*)d_in[2];
    const float* hw1   = (const float*)d_in[3];
    const float* hb1   = (const float*)d_in[4];
    const float* hw2   = (const float*)d_in[5];
    const float* hb2   = (const float*)d_in[6];
    const float* hw3   = (const float*)d_in[7];
    const float* hb3   = (const float*)d_in[8];
    const float* lcW   = (const float*)d_in[9];
    const float* lcb   = (const float*)d_in[10];
    const float* lvW   = (const float*)d_in[11];
    const float* lvb   = (const float*)d_in[12];
    const float* gcW   = (const float*)d_in[13];
    const float* gcb   = (const float*)d_in[14];
    const float* gvW   = (const float*)d_in[15];
    const float* gvb   = (const float*)d_in[16];
    const float* sw1   = (const float*)d_in[17];
    const float* sw2   = (const float*)d_in[18];
    float* out = (float*)d_out;

    cudaFuncSetAttribute(mma_gemm_k,   cudaFuncAttributeMaxDynamicSharedMemorySize, GSMEM);
    cudaFuncSetAttribute(flash_k,      cudaFuncAttributeMaxDynamicSharedMemorySize, FSMEM);
    cudaFuncSetAttribute(local_attn_k, cudaFuncAttributeMaxDynamicSharedMemorySize, LSMEM);

    __half *pSeg, *pWH, *pB1, *pM, *pCT, *pA;
    float *pBias, *pH2;
    cudaGetSymbolAddress((void**)&pSeg, g_seg);
    cudaGetSymbolAddress((void**)&pWH, g_WH);
    cudaGetSymbolAddress((void**)&pB1, g_B1);
    cudaGetSymbolAddress((void**)&pM,  g_M);
    cudaGetSymbolAddress((void**)&pCT, g_CT);
    cudaGetSymbolAddress((void**)&pA,  g_A);
    cudaGetSymbolAddress((void**)&pBias, g_biasC);
    cudaGetSymbolAddress((void**)&pH2, g_H2);

    // prepasses
    cvt_k<<<1024, 256>>>(seg, pSeg, BLD);
    wtile_all_k<<<1024, 256>>>(hw1, hw3, lcW, lvW, gcW, gvW);
    biascat_k<<<8, 256>>>(lcb, lvb, gcb, gvb);

    // 1) h2
    h2_k<<<dim3(Bb * Nn, 4), dim3(128, 8)>>>(se, hw2, hb2);

    // 2) h1 = relu(seg @ w1 + b1) * h2
    mgemm(pSeg, pWH + OFF_HW1, hb1, pH2, pB1,
          512, 512, 512, 512, Nn, 0, 262144L, BLD, 512, 2 | 8);

    // 3) m = relu(h1m @ w3 + b3)
    mgemm(pB1, pWH + OFF_HW3, hb3, nullptr, pM,
          512, 512, 512, 512, Nn, BLD, 262144L, BLD, 512, 2);

    // 4) local NL: projection + tiled banded attention
    for (int s = 0; s < 2; s++) {
        mgemm(pM, pWH + OFF_LCV + (long)s * 786432, pBias + s * 1536, nullptr, pCT,
              1536, 512, 512, 1536, Nn, BLD, 2L * 786432, CTN, 3072, 0);
        local_attn_k<<<dim3(4, Bb * Hh, Nn), 256, LSMEM>>>(mask);
    }

    // 5) segment attention weights
    satt_k<<<Bb, dim3(256, 4)>>>(se, sw1, sw2, out + BLD);

    // 6) aggregate
    agg_k<<<2048, 256>>>();

    // 7) global NL: projection + flash attention
    for (int s = 0; s < 2; s++) {
        mgemm(pA, pWH + OFF_GCV + (long)s * 786432, pBias + (6 + s) * 1536, nullptr, pCT,
              1536, 512, 512, 1536, 1, 0, 0, 0, 0, 0);
        flash_k<<<dim3(4, Bb * Hh), 256, FSMEM>>>(mask, (s == 1) ? out : nullptr);
    }
}

// round 12
// speedup vs baseline: 3.7539x; 1.2059x over previous
#include <cuda_runtime.h>
#include <cuda_fp16.h>
#include <math.h>
#include <stdint.h>

#define Bb 16
#define Ll 512
#define Dd 512
#define Nn 3
#define Hh 8
#define DH 64
#define AH 256
#define KHALF 7

#define BLD 4194304L        // Bb*Ll*Dd
#define CTN 12582912L       // 8192*1536 per n
#define CTSZ 37748736L      // 3 * CTN

// ---------------- scratch ------------------------------------------------------
__device__ __half g_seg[BLD];
__device__ __half g_WH[7864320];                  // fp16, tiled 32x128 blocks
__device__ __half g_B1[3*BLD];
__device__ __half g_M [3*BLD];
__device__ __half g_CT[CTSZ];                     // [n][8192][1536] mq|mv|mk
__device__ __half g_A [BLD];
__device__ float g_H2[Bb*Nn*Dd];
__device__ float g_SW[Bb*Nn];
__device__ float g_biasC[8*1536];

#define OFF_HW1 0L
#define OFF_HW3 786432L
#define OFF_LCV 1572864L
#define OFF_GCV 6291456L

// ---------------- PTX helpers --------------------------------------------------
__device__ __forceinline__ uint32_t smem_u32(const void* p) {
    uint32_t a;
    asm("{ .reg .u64 t; cvta.to.shared.u64 t, %1; cvt.u32.u64 %0, t; }" : "=r"(a) : "l"(p));
    return a;
}
#define CPA16(dst, src) asm volatile( \
    "cp.async.ca.shared.global [%0], [%1], 16;" :: "r"(dst), "l"(__cvta_generic_to_global(src)))
#define CPA_COMMIT() asm volatile("cp.async.commit_group;" ::: "memory")
#define CPA_WAIT1()  asm volatile("cp.async.wait_group 1;" ::: "memory")

#define BULK(dst, src, sz, mb) asm volatile( \
    "cp.async.bulk.shared::cta.global.mbarrier::complete_tx::bytes [%0], [%1], %2, [%3];" \
    :: "r"(dst), "l"(__cvta_generic_to_global(src)), "r"((uint32_t)(sz)), "r"(mb) : "memory")

#define MBAR_INIT(mb, c)   asm volatile("mbarrier.init.shared.b64 [%0], %1;" :: "r"(mb), "r"((uint32_t)(c)) : "memory")
#define MBAR_EXPECT(mb, tx) asm volatile("mbarrier.arrive.expect_tx.shared.b64 _, [%0], %1;" :: "r"(mb), "r"((uint32_t)(tx)) : "memory")
#define FENCE_ASYNC_SHARED() asm volatile("fence.proxy.async.shared::cta;" ::: "memory")
#define MBAR_WAIT(mb, ph) do { \
    uint32_t _m = (mb), _p = (ph), _d; \
    asm volatile("{\n\t.reg .pred p;\n\tmbarrier.try_wait.parity.acquire.cta.shared::cta.b64 p, [%1], %2;\n\tselp.b32 %0, 1, 0, p;\n\t}" \
        : "=r"(_d) : "r"(_m), "r"(_p) : "memory"); \
    if (!_d) { \
        asm volatile("{\n\t.reg .pred P1;\n\tWL_%=:\n\tmbarrier.try_wait.parity.acquire.cta.shared::cta.b64 P1, [%0], %1, 0x989680;\n\t@P1 bra.uni WD_%=;\n\tbra.uni WL_%=;\n\tWD_%=:\n\t}" \
            :: "r"(_m), "r"(_p) : "memory"); \
    } } while (0)

#define LDM_X4(r, a) asm volatile( \
    "ldmatrix.sync.aligned.m8n8.x4.shared.b16 {%0,%1,%2,%3}, [%4];" \
    : "=r"((r)[0]),"=r"((r)[1]),"=r"((r)[2]),"=r"((r)[3]) : "r"(a))
#define LDM_X4T(r, a) asm volatile( \
    "ldmatrix.sync.aligned.m8n8.x4.trans.shared.b16 {%0,%1,%2,%3}, [%4];" \
    : "=r"((r)[0]),"=r"((r)[1]),"=r"((r)[2]),"=r"((r)[3]) : "r"(a))
#define MMAF16(d, a, b) asm volatile( \
    "mma.sync.aligned.m16n8k16.row.col.f32.f16.f16.f32 " \
    "{%0,%1,%2,%3}, {%4,%5,%6,%7}, {%8,%9}, {%0,%1,%2,%3};" \
    : "+f"((d)[0]),"+f"((d)[1]),"+f"((d)[2]),"+f"((d)[3]) \
    : "r"((a)[0]),"r"((a)[1]),"r"((a)[2]),"r"((a)[3]), "r"((b)[0]),"r"((b)[1]))

__device__ __forceinline__ uint32_t packh2(float a, float b) {
    __half2 t = __floats2half2_rn(a, b);
    return *reinterpret_cast<uint32_t*>(&t);
}

// ---------------- prepasses ----------------------------------------------------
__global__ void cvt_k(const float* __restrict__ s, __half* __restrict__ d, long n)
{
    for (long i = ((long)blockIdx.x * blockDim.x + threadIdx.x) * 4; i < n;
         i += (long)gridDim.x * blockDim.x * 4) {
        float4 v = *reinterpret_cast<const float4*>(s + i);
        uint2 o;
        o.x = packh2(v.x, v.y);
        o.y = packh2(v.z, v.w);
        *reinterpret_cast<uint2*>(d + i) = o;
    }
}

__global__ void wtile_all_k(const float* __restrict__ hw1, const float* __restrict__ hw3,
                            const float* __restrict__ lcW, const float* __restrict__ lvW,
                            const float* __restrict__ gcW, const float* __restrict__ gvW)
{
    const float* srcs[6] = {hw1, hw3, lcW, lvW, gcW, gvW};
    const long  woff[6]  = {OFF_HW1, OFF_HW3, OFF_LCV, OFF_LCV, OFF_GCV, OFF_GCV};
    const int   C1s[6]   = {512, 512, 1024, 512, 1024, 512};
    const int   coff[6]  = {0, 0, 0, 1024, 0, 1024};
    const long  dss[6]   = {262144L, 262144L, 786432L, 786432L, 786432L, 786432L};
    const long  tots[6]  = {786432L, 786432L, 3145728L, 1572864L, 1048576L, 524288L};

    long gstride = (long)gridDim.x * blockDim.x * 4;
    #pragma unroll 1
    for (int sg = 0; sg < 6; sg++) {
        const float* s = srcs[sg];
        int C1 = C1s[sg];
        long sS = 512L * C1;
        for (long i = ((long)blockIdx.x * blockDim.x + threadIdx.x) * 4; i < tots[sg];
             i += gstride) {
            float4 v = *reinterpret_cast<const float4*>(s + i);
            long sl = i / sS;
            long rem = i - sl * sS;
            int k = (int)(rem / C1), c = (int)(rem - (long)(rem / C1) * C1);
            int n = coff[sg] + c;
            long d = woff[sg] + sl * dss[sg] + ((long)((n >> 7) * 16 + (k >> 5))) * 4096
                   + (k & 31) * 128 + ((((n & 127) >> 3) ^ (k & 7)) << 3) + (n & 7);
            float vv[4] = {v.x, v.y, v.z, v.w};
            #pragma unroll
            for (int e = 0; e < 4; e++)
                g_WH[d + e] = __float2half_rn(vv[e]);
        }
    }
}

__global__ void biascat_k(const float* __restrict__ lcb, const float* __restrict__ lvb,
                          const float* __restrict__ gcb, const float* __restrict__ gvb)
{
    int slot = blockIdx.x;
    for (int c = threadIdx.x; c < 1536; c += blockDim.x) {
        float v;
        if (slot < 6) v = (c < 1024) ? lcb[slot * 1024 + c] : lvb[slot * 512 + c - 1024];
        else {
            int s = slot - 6;
            v = (c < 1024) ? gcb[s * 1024 + c] : gvb[s * 512 + c - 1024];
        }
        g_biasC[slot * 1536 + c] = v;
    }
}

// ---------------- GEMM: fp16 A x fp16 W, 1 MMA/k16, BN=256 ---------------------
#define GSMEM 79904
__global__ void __launch_bounds__(256, 1) mma_gemm_k(
    const __half* __restrict__ A, const __half* __restrict__ WH,
    const float* __restrict__ bias, const float* __restrict__ H2,
    __half* __restrict__ C,
    int K, int lda, int ldc,
    long sAi, long sBi, long sCi, long sBias, int flags)
{
    constexpr int LDS = 40;
    constexpr int A_BYTES = 128 * LDS * 2;
    constexpr int BHI = 16384;
    constexpr int STAGE = A_BYTES + BHI;
    extern __shared__ char dsm[];
    uint32_t sb0 = smem_u32(dsm);
    uint32_t mbar0 = sb0 + 3 * STAGE;

    int z = blockIdx.z;
    A  += z * sAi;
    WH += z * sBi;
    C  += z * sCi;
    if (bias) bias += z * sBias;

    int tid = threadIdx.x, lane = tid & 31, wid = tid >> 5;
    int wm = wid & 1, wn = wid >> 1;
    int m0 = blockIdx.y * 128;
    int bx = blockIdx.x, n0 = bx * 256;
    int nc = K / 32;

    if (tid == 0) {
        MBAR_INIT(mbar0, 1); MBAR_INIT(mbar0 + 8, 1); MBAR_INIT(mbar0 + 16, 1);
        FENCE_ASYNC_SHARED();
    }
    __syncthreads();

    auto fillA = [&](int c) {
        int k0 = c * 32;
        uint32_t st = sb0 + (c % 3) * STAGE;
        #pragma unroll
        for (int it = 0; it < 2; it++) {
            int idx = tid + it * 256;
            int row = idx >> 2, u = idx & 3;
            CPA16(st + row * 80 + u * 16, A + (long)(m0 + row) * lda + k0 + u * 8);
        }
    };
    auto fillB = [&](int c) {
        uint32_t st = sb0 + (c % 3) * STAGE + A_BYTES;
        uint32_t mb = mbar0 + (c % 3) * 8;
        MBAR_EXPECT(mb, 16384u);
        long off0 = ((long)(bx * 2) * nc + c) * 4096;
        long off1 = ((long)(bx * 2 + 1) * nc + c) * 4096;
        BULK(st,        WH + off0, 8192, mb);
        BULK(st + 8192, WH + off1, 8192, mb);
    };

    float acc[4][8][4] = {};

    fillA(0); CPA_COMMIT();
    fillA(1); CPA_COMMIT();
    if (tid == 0) { fillB(0); fillB(1); }

    int alr = lane & 15, alc = (lane >> 4) << 3;
    int btr = (lane & 7) + (((lane >> 3) & 1) << 3);
    int btcc = (lane >> 4) & 1;

    for (int c = 0; c < nc; c++) {
        CPA_WAIT1();
        MBAR_WAIT(mbar0 + (c % 3) * 8, (c / 3) & 1);
        __syncthreads();
        if (c + 2 < nc) { fillA(c + 2); if (tid == 0) fillB(c + 2); }
        CPA_COMMIT();

        uint32_t base = sb0 + (c % 3) * STAGE;
        uint32_t aA = base + ((wm * 64 + alr) * LDS + alc) * 2;
        uint32_t bB = base + A_BYTES + (wn >> 1) * 8192;

        #pragma unroll
        for (int kk = 0; kk < 2; kk++) {
            uint32_t ah[4][4], bh[8][2];
            #pragma unroll
            for (int mt = 0; mt < 4; mt++)
                LDM_X4(ah[mt], aA + (uint32_t)((mt * 16 * LDS + kk * 16) * 2));
            int krow = kk * 16 + btr;
            #pragma unroll
            for (int p = 0; p < 4; p++) {
                int c16 = (wn & 1) * 8 + p * 2 + btcc;
                uint32_t ad = bB + (uint32_t)(krow * 256 + ((c16 ^ (krow & 7)) << 4));
                uint32_t r[4];
                LDM_X4T(r, ad);
                bh[2*p][0]=r[0]; bh[2*p][1]=r[1]; bh[2*p+1][0]=r[2]; bh[2*p+1][1]=r[3];
            }
            #pragma unroll
            for (int mt = 0; mt < 4; mt++)
                #pragma unroll
                for (int nt = 0; nt < 8; nt++)
                    MMAF16(acc[mt][nt], ah[mt], bh[nt]);
        }
    }

    const float* H2b = (flags & 8) ? (H2 + ((long)(m0 >> 9) * Nn + z) * 512) : nullptr;

    #pragma unroll
    for (int mt = 0; mt < 4; mt++) {
        int row = m0 + wm * 64 + mt * 16 + (lane >> 2);
        #pragma unroll
        for (int nt = 0; nt < 8; nt++) {
            int col = n0 + wn * 64 + nt * 8 + (lane & 3) * 2;
            float d0 = acc[mt][nt][0], d1 = acc[mt][nt][1];
            float d2 = acc[mt][nt][2], d3 = acc[mt][nt][3];
            if (bias) {
                float b0 = bias[col], b1 = bias[col + 1];
                d0 += b0; d1 += b1; d2 += b0; d3 += b1;
            }
            if (flags & 2) {
                d0 = fmaxf(d0, 0.f); d1 = fmaxf(d1, 0.f);
                d2 = fmaxf(d2, 0.f); d3 = fmaxf(d3, 0.f);
            }
            if (H2b) {
                float f0 = H2b[col], f1 = H2b[col + 1];
                d0 *= f0; d1 *= f1; d2 *= f0; d3 *= f1;
            }
            long o0 = (long)row * ldc + col;
            long o1 = o0 + (long)8 * ldc;
            *reinterpret_cast<uint32_t*>(C + o0) = packh2(d0, d1);
            *reinterpret_cast<uint32_t*>(C + o1) = packh2(d2, d3);
        }
    }
}

// ---------------- flash global attention ---------------------------------------
#define FQ 0
#define FK 18432
#define FV 36864
#define FMSK 55296
#define FSMEM 57344
#define FLDQ 72

__global__ void __launch_bounds__(256, 1) flash_k(const float* __restrict__ mask,
                                                  float* __restrict__ outp)
{
    extern __shared__ char sm[];
    uint32_t sb = smem_u32(sm);
    float* mbias = reinterpret_cast<float*>(sm + FMSK);
    int tid = threadIdx.x, lane = tid & 31, w = tid >> 5;
    int b = blockIdx.y >> 3, h = blockIdx.y & 7;
    int l0 = blockIdx.x * 128;
    long base = (long)b * 512 * 1536;

    for (int i = tid; i < 1024; i += 256) {
        int row = i >> 3, u = i & 7;
        *reinterpret_cast<uint4*>(sm + FQ + row * 144 + u * 16) =
            *reinterpret_cast<const uint4*>(g_CT + base + (long)(l0 + row) * 1536 + 1024 + h * DH + u * 8);
    }
    for (int i = tid; i < 512; i += 256)
        mbias[i] = (mask[(long)b * 512 + i] != 0.f) ? 0.f : -1e9f;

    float O[8][4];
    #pragma unroll
    for (int i = 0; i < 8; i++)
        #pragma unroll
        for (int e = 0; e < 4; e++) O[i][e] = 0.f;
    float mrow[2] = {-1e30f, -1e30f}, lrow[2] = {0.f, 0.f};

    int alr = lane & 15, alc = (lane >> 4) << 3;
    int blr = (lane & 7) + (((lane >> 4) & 1) << 3), blc = ((lane >> 3) & 1) << 3;
    int btr = (lane & 7) + (((lane >> 3) & 1) << 3), btc = ((lane >> 4) & 1) << 3;
    int c0 = (lane & 3) * 2;

    for (int mi = 0; mi < 4; mi++) {
        int m0 = mi * 128;
        __syncthreads();
        for (int i = tid; i < 1024; i += 256) {
            int row = i >> 3, u = i & 7;
            long gq = base + (long)(m0 + row) * 1536 + h * DH + u * 8;
            *reinterpret_cast<uint4*>(sm + FK + row * 144 + u * 16) =
                *reinterpret_cast<const uint4*>(g_CT + gq);
            *reinterpret_cast<uint4*>(sm + FV + row * 144 + u * 16) =
                *reinterpret_cast<const uint4*>(g_CT + gq + 512);
        }
        __syncthreads();

        float S[16][4];
        #pragma unroll
        for (int i = 0; i < 16; i++)
            #pragma unroll
            for (int e = 0; e < 4; e++) S[i][e] = 0.f;

        #pragma unroll
        for (int kc = 0; kc < 4; kc++) {
            uint32_t q[4];
            LDM_X4(q, sb + FQ + (uint32_t)(((w * 16 + alr) * FLDQ + kc * 16 + alc) * 2));
            #pragma unroll
            for (int p = 0; p < 8; p++) {
                uint32_t kf[4];
                LDM_X4(kf, sb + FK + (uint32_t)(((p * 16 + blr) * FLDQ + kc * 16 + blc) * 2));
                uint32_t b0[2] = {kf[0], kf[1]}, b1[2] = {kf[2], kf[3]};
                MMAF16(S[2*p],   q, b0);
                MMAF16(S[2*p+1], q, b1);
            }
        }

        float cmax[2] = {-1e30f, -1e30f};
        #pragma unroll
        for (int nt = 0; nt < 16; nt++)
            #pragma unroll
            for (int e = 0; e < 4; e++) {
                int col = m0 + nt * 8 + c0 + (e & 1);
                float v = S[nt][e] * 0.125f + mbias[col];
                S[nt][e] = v;
                cmax[e >> 1] = fmaxf(cmax[e >> 1], v);
            }
        #pragma unroll
        for (int o = 1; o <= 2; o <<= 1) {
            cmax[0] = fmaxf(cmax[0], __shfl_xor_sync(0xffffffffu, cmax[0], o));
            cmax[1] = fmaxf(cmax[1], __shfl_xor_sync(0xffffffffu, cmax[1], o));
        }
        float mn0 = fmaxf(mrow[0], cmax[0]), mn1 = fmaxf(mrow[1], cmax[1]);
        float a0 = __expf(mrow[0] - mn0), a1 = __expf(mrow[1] - mn1);
        mrow[0] = mn0; mrow[1] = mn1;
        lrow[0] *= a0; lrow[1] *= a1;
        #pragma unroll
        for (int i = 0; i < 8; i++) {
            O[i][0] *= a0; O[i][1] *= a0; O[i][2] *= a1; O[i][3] *= a1;
        }
        #pragma unroll
        for (int nt = 0; nt < 16; nt++)
            #pragma unroll
            for (int e = 0; e < 4; e++) {
                float p = __expf(S[nt][e] - ((e < 2) ? mn0 : mn1));
                S[nt][e] = p;
                lrow[e >> 1] += p;
            }

        #pragma unroll
        for (int kc = 0; kc < 8; kc++) {
            uint32_t ph[4];
            ph[0] = packh2(S[2*kc][0],   S[2*kc][1]);
            ph[1] = packh2(S[2*kc][2],   S[2*kc][3]);
            ph[2] = packh2(S[2*kc+1][0], S[2*kc+1][1]);
            ph[3] = packh2(S[2*kc+1][2], S[2*kc+1][3]);
            #pragma unroll
            for (int p = 0; p < 4; p++) {
                uint32_t vh[4];
                LDM_X4T(vh, sb + FV + (uint32_t)(((kc * 16 + btr) * FLDQ + p * 16 + btc) * 2));
                uint32_t b0[2] = {vh[0], vh[1]}, b1[2] = {vh[2], vh[3]};
                MMAF16(O[2*p],   ph, b0);
                MMAF16(O[2*p+1], ph, b1);
            }
        }
    }

    #pragma unroll
    for (int o = 1; o <= 2; o <<= 1) {
        lrow[0] += __shfl_xor_sync(0xffffffffu, lrow[0], o);
        lrow[1] += __shfl_xor_sync(0xffffffffu, lrow[1], o);
    }
    float inv0 = 1.f / lrow[0], inv1 = 1.f / lrow[1];

    int r0g = l0 + w * 16 + (lane >> 2);
    #pragma unroll
    for (int nt = 0; nt < 8; nt++) {
        int col = h * DH + nt * 8 + c0;
        long o0 = ((long)b * 512 + r0g) * 512 + col;
        long o1 = o0 + 8 * 512;
        __half2 x0 = *reinterpret_cast<const __half2*>(g_A + o0);
        __half2 x1 = *reinterpret_cast<const __half2*>(g_A + o1);
        float d0 = __low2float(x0) + O[nt][0] * inv0;
        float d1 = __high2float(x0) + O[nt][1] * inv0;
        float d2 = __low2float(x1) + O[nt][2] * inv1;
        float d3 = __high2float(x1) + O[nt][3] * inv1;
        if (outp) {
            *reinterpret_cast<float2*>(outp + o0) = make_float2(d0, d1);
            *reinterpret_cast<float2*>(outp + o1) = make_float2(d2, d3);
        } else {
            *reinterpret_cast<uint32_t*>(g_A + o0) = packh2(d0, d1);
            *reinterpret_cast<uint32_t*>(g_A + o1) = packh2(d2, d3);
        }
    }
}

// ---------------- MMA-based banded local attention -----------------------------
// S(128x144) = mk[l0..l0+127] @ mq[l0-8..l0+135]^T; band+seg mask; softmax; P@V; +=g_M
#define LK2 0
#define LMQ2 18432
#define LMV2 39168
#define LBI2 59904
#define LSMEM 60480

__global__ void __launch_bounds__(256, 1) local_attn_k(const float* __restrict__ mask)
{
    extern __shared__ char sm[];
    uint32_t sb = smem_u32(sm);
    float* sBias = reinterpret_cast<float*>(sm + LBI2);
    int tid = threadIdx.x, lane = tid & 31, w = tid >> 5;
    int b = blockIdx.y >> 3, h = blockIdx.y & 7;
    int n = blockIdx.z;
    int l0 = blockIdx.x * 128;
    long base = (long)n * CTN + (long)b * 512 * 1536;

    // mk rows l0..l0+127
    for (int i = tid; i < 1024; i += 256) {
        int row = i >> 3, u = i & 7;
        *reinterpret_cast<uint4*>(sm + LK2 + row * 144 + u * 16) =
            *reinterpret_cast<const uint4*>(g_CT + base + (long)(l0 + row) * 1536 + 1024 + h * DH + u * 8);
    }
    // mq/mv rows m = l0-8+r, r = 0..143 (zero out-of-range)
    for (int i = tid; i < 1152; i += 256) {
        int r = i >> 3, u = i & 7;
        int m = l0 - 8 + r;
        if (m >= 0 && m < 512) {
            long g = base + (long)m * 1536 + h * DH + u * 8;
            *reinterpret_cast<uint4*>(sm + LMQ2 + r * 144 + u * 16) =
                *reinterpret_cast<const uint4*>(g_CT + g);
            *reinterpret_cast<uint4*>(sm + LMV2 + r * 144 + u * 16) =
                *reinterpret_cast<const uint4*>(g_CT + g + 512);
        } else {
            uint4 z = make_uint4(0, 0, 0, 0);
            *reinterpret_cast<uint4*>(sm + LMQ2 + r * 144 + u * 16) = z;
            *reinterpret_cast<uint4*>(sm + LMV2 + r * 144 + u * 16) = z;
        }
    }
    for (int i = tid; i < 144; i += 256) {
        int m = l0 - 8 + i;
        sBias[i] = (m >= 0 && m < 512 && mask[(long)b * 512 + m] != 0.f) ? 0.f : -1e9f;
    }
    __syncthreads();

    int alr = lane & 15, alc = (lane >> 4) << 3;
    int blr = (lane & 7) + (((lane >> 4) & 1) << 3), blc = ((lane >> 3) & 1) << 3;
    int btr = (lane & 7) + (((lane >> 3) & 1) << 3), btc = ((lane >> 4) & 1) << 3;
    int c0 = (lane & 3) * 2;
    int r0 = w * 16 + (lane >> 2);

    float S[18][4];
    #pragma unroll
    for (int i = 0; i < 18; i++)
        #pragma unroll
        for (int e = 0; e < 4; e++) S[i][e] = 0.f;

    // S = mk @ mq^T
    #pragma unroll
    for (int kc = 0; kc < 4; kc++) {
        uint32_t aq[4];
        LDM_X4(aq, sb + LK2 + (uint32_t)(((w * 16 + alr) * 72 + kc * 16 + alc) * 2));
        #pragma unroll
        for (int p = 0; p < 9; p++) {
            uint32_t kf[4];
            LDM_X4(kf, sb + LMQ2 + (uint32_t)(((p * 16 + blr) * 72 + kc * 16 + blc) * 2));
            uint32_t b0[2] = {kf[0], kf[1]}, b1[2] = {kf[2], kf[3]};
            MMAF16(S[2*p],   aq, b0);
            MMAF16(S[2*p+1], aq, b1);
        }
    }

    // band + seg mask, single-pass softmax (row = lr; valid cols [lr+1, lr+15])
    float mx0 = -1e30f, mx1 = -1e30f;
    #pragma unroll
    for (int nt = 0; nt < 18; nt++)
        #pragma unroll
        for (int e = 0; e < 4; e++) {
            int col = nt * 8 + c0 + (e & 1);
            int lr = (e < 2) ? r0 : (r0 + 8);
            float v = S[nt][e] * 0.125f + sBias[col];
            if (col < lr + 1 || col > lr + 15) v = -1e30f;
            S[nt][e] = v;
            if (e < 2) mx0 = fmaxf(mx0, v); else mx1 = fmaxf(mx1, v);
        }
    #pragma unroll
    for (int o = 1; o <= 2; o <<= 1) {
        mx0 = fmaxf(mx0, __shfl_xor_sync(0xffffffffu, mx0, o));
        mx1 = fmaxf(mx1, __shfl_xor_sync(0xffffffffu, mx1, o));
    }
    float s0 = 0.f, s1 = 0.f;
    #pragma unroll
    for (int nt = 0; nt < 18; nt++)
        #pragma unroll
        for (int e = 0; e < 4; e++) {
            float p = __expf(S[nt][e] - ((e < 2) ? mx0 : mx1));
            S[nt][e] = p;
            if (e < 2) s0 += p; else s1 += p;
        }
    #pragma unroll
    for (int o = 1; o <= 2; o <<= 1) {
        s0 += __shfl_xor_sync(0xffffffffu, s0, o);
        s1 += __shfl_xor_sync(0xffffffffu, s1, o);
    }
    float inv0 = 1.f / s0, inv1 = 1.f / s1;

    // O = P @ mv  (K = 144)
    float O[8][4];
    #pragma unroll
    for (int i = 0; i < 8; i++)
        #pragma unroll
        for (int e = 0; e < 4; e++) O[i][e] = 0.f;

    #pragma unroll
    for (int kc = 0; kc < 9; kc++) {
        uint32_t ph[4];
        ph[0] = packh2(S[2*kc][0],   S[2*kc][1]);
        ph[1] = packh2(S[2*kc][2],   S[2*kc][3]);
        ph[2] = packh2(S[2*kc+1][0], S[2*kc+1][1]);
        ph[3] = packh2(S[2*kc+1][2], S[2*kc+1][3]);
        #pragma unroll
        for (int p = 0; p < 4; p++) {
            uint32_t vh[4];
            LDM_X4T(vh, sb + LMV2 + (uint32_t)(((kc * 16 + btr) * 72 + p * 16 + btc) * 2));
            uint32_t b0[2] = {vh[0], vh[1]}, b1[2] = {vh[2], vh[3]};
            MMAF16(O[2*p],   ph, b0);
            MMAF16(O[2*p+1], ph, b1);
        }
    }

    // residual into g_M
    int gl = l0 + r0;
    #pragma unroll
    for (int nt = 0; nt < 8; nt++) {
        int col = h * DH + nt * 8 + c0;
        long o0 = (long)n * BLD + ((long)b * 512 + gl) * 512 + col;
        long o1 = o0 + 8 * 512;
        __half2 x0 = *reinterpret_cast<const __half2*>(g_M + o0);
        __half2 x1 = *reinterpret_cast<const __half2*>(g_M + o1);
        *reinterpret_cast<uint32_t*>(g_M + o0) =
            packh2(__low2float(x0) + O[nt][0] * inv0, __high2float(x0) + O[nt][1] * inv0);
        *reinterpret_cast<uint32_t*>(g_M + o1) =
            packh2(__low2float(x1) + O[nt][2] * inv1, __high2float(x1) + O[nt][3] * inv1);
    }
}

// ---------------- small kernels ------------------------------------------------
__global__ void h2_k(const float* __restrict__ se, const float* __restrict__ w2,
                     const float* __restrict__ b2)
{
    __shared__ float red[8][128];
    int bn = blockIdx.x;
    int n = bn % Nn;
    int h = blockIdx.y * 128 + threadIdx.x;
    int ty = threadIdx.y;
    const float* x = se + (long)bn * Dd;
    const float* w = w2 + (long)n * Dd * Dd + h;
    int d0 = ty * 64;
    float a0 = 0.f, a1 = 0.f, a2 = 0.f, a3 = 0.f;
    #pragma unroll 4
    for (int d = d0; d < d0 + 64; d += 4) {
        a0 = fmaf(x[d],     w[(long)d * Dd],       a0);
        a1 = fmaf(x[d + 1], w[(long)(d + 1) * Dd], a1);
        a2 = fmaf(x[d + 2], w[(long)(d + 2) * Dd], a2);
        a3 = fmaf(x[d + 3], w[(long)(d + 3) * Dd], a3);
    }
    red[ty][threadIdx.x] = (a0 + a1) + (a2 + a3);
    __syncthreads();
    if (ty == 0) {
        float acc = b2[n * Dd + h];
        #pragma unroll
        for (int e = 0; e < 8; e++) acc += red[e][threadIdx.x];
        g_H2[(long)bn * Dd + h] = fmaxf(acc, 0.f);
    }
}

__global__ void satt_k(const float* __restrict__ se, const float* __restrict__ w1,
                       const float* __restrict__ w2, float* __restrict__ out_tail)
{
    __shared__ float red[4][256];
    __shared__ float s1[256];
    __shared__ float alpha[Nn];
    int b = blockIdx.x, t = threadIdx.x, y = threadIdx.y;
    for (int n = 0; n < Nn; n++) {
        const float* x = se + ((long)b * Nn + n) * Dd;
        int d0 = y * 128;
        float a0 = 0.f, a1 = 0.f, a2 = 0.f, a3 = 0.f;
        #pragma unroll 4
        for (int d = d0; d < d0 + 128; d += 4) {
            a0 = fmaf(x[d],     w1[(long)d * AH + t],       a0);
            a1 = fmaf(x[d + 1], w1[(long)(d + 1) * AH + t], a1);
            a2 = fmaf(x[d + 2], w1[(long)(d + 2) * AH + t], a2);
            a3 = fmaf(x[d + 3], w1[(long)(d + 3) * AH + t], a3);
        }
        red[y][t] = (a0 + a1) + (a2 + a3);
        __syncthreads();
        if (y == 0) {
            float dot = red[0][t] + red[1][t] + red[2][t] + red[3][t];
            s1[t] = tanhf(dot) * w2[t];
        }
        __syncthreads();
        for (int o = 128; o; o >>= 1) {
            if (y == 0 && t < o) s1[t] += s1[t + o];
            __syncthreads();
        }
        if (y == 0 && t == 0) alpha[n] = s1[0];
        __syncthreads();
    }
    if (y == 0 && t == 0) {
        float mx = fmaxf(alpha[0], fmaxf(alpha[1], alpha[2]));
        float e[Nn], sum = 0.f;
        for (int n = 0; n < Nn; n++) { e[n] = expf(alpha[n] - mx); sum += e[n]; }
        for (int n = 0; n < Nn; n++) {
            float w = e[n] / sum;
            g_SW[b * Nn + n] = w;
            out_tail[b * Nn + n] = w;
        }
    }
}

__global__ void agg_k()
{
    long half_total = BLD / 2;
    long stride = (long)Ll * Dd / 2;
    for (long i = (long)blockIdx.x * blockDim.x + threadIdx.x; i < half_total;
         i += (long)gridDim.x * blockDim.x) {
        int b = (int)(i / stride);
        float a0 = 0.f, a1 = 0.f;
        #pragma unroll
        for (int n = 0; n < Nn; n++) {
            float sw = g_SW[b * Nn + n];
            __half2 v = *reinterpret_cast<const __half2*>(g_M + (long)n * BLD + i * 2);
            a0 = fmaf(sw, __low2float(v), a0);
            a1 = fmaf(sw, __high2float(v), a1);
        }
        *reinterpret_cast<uint32_t*>(g_A + i * 2) = packh2(a0, a1);
    }
}

// ---------------- host orchestration ------------------------------------------
static void mgemm(const __half* A, const __half* WH,
                  const float* bias, const float* H2, __half* C,
                  int N, int K, int lda, int ldc, int batches,
                  long sAi, long sBi, long sCi, long sBias, int flags)
{
    dim3 grid(N / 256, 64, batches);
    mma_gemm_k<<<grid, 256, GSMEM>>>(A, WH, bias, H2, C, K,
                                     lda, ldc, sAi, sBi, sCi, sBias, flags);
}

extern "C" void kernel_launch(void* const* d_in, const int* in_sizes, int n_in,
                              void* d_out, int out_size)
{
    const float* seg   = (const float*)d_in[0];
    const float* mask  = (const float*)d_in[1];
    const float* se    = (const float*)d_in[2];
    const float* hw1   = (const float*)d_in[3];
    const float* hb1   = (const float*)d_in[4];
    const float* hw2   = (const float*)d_in[5];
    const float* hb2   = (const float*)d_in[6];
    const float* hw3   = (const float*)d_in[7];
    const float* hb3   = (const float*)d_in[8];
    const float* lcW   = (const float*)d_in[9];
    const float* lcb   = (const float*)d_in[10];
    const float* lvW   = (const float*)d_in[11];
    const float* lvb   = (const float*)d_in[12];
    const float* gcW   = (const float*)d_in[13];
    const float* gcb   = (const float*)d_in[14];
    const float* gvW   = (const float*)d_in[15];
    const float* gvb   = (const float*)d_in[16];
    const float* sw1   = (const float*)d_in[17];
    const float* sw2   = (const float*)d_in[18];
    float* out = (float*)d_out;

    cudaFuncSetAttribute(mma_gemm_k,   cudaFuncAttributeMaxDynamicSharedMemorySize, GSMEM);
    cudaFuncSetAttribute(flash_k,      cudaFuncAttributeMaxDynamicSharedMemorySize, FSMEM);
    cudaFuncSetAttribute(local_attn_k, cudaFuncAttributeMaxDynamicSharedMemorySize, LSMEM);

    __half *pSeg, *pWH, *pB1, *pM, *pCT, *pA;
    float *pBias, *pH2;
    cudaGetSymbolAddress((void**)&pSeg, g_seg);
    cudaGetSymbolAddress((void**)&pWH, g_WH);
    cudaGetSymbolAddress((void**)&pB1, g_B1);
    cudaGetSymbolAddress((void**)&pM,  g_M);
    cudaGetSymbolAddress((void**)&pCT, g_CT);
    cudaGetSymbolAddress((void**)&pA,  g_A);
    cudaGetSymbolAddress((void**)&pBias, g_biasC);
    cudaGetSymbolAddress((void**)&pH2, g_H2);

    // prepasses
    cvt_k<<<1024, 256>>>(seg, pSeg, BLD);
    wtile_all_k<<<1024, 256>>>(hw1, hw3, lcW, lvW, gcW, gvW);
    biascat_k<<<8, 256>>>(lcb, lvb, gcb, gvb);

    // 1) h2
    h2_k<<<dim3(Bb * Nn, 4), dim3(128, 8)>>>(se, hw2, hb2);

    // 2) h1 = relu(seg @ w1 + b1) * h2
    mgemm(pSeg, pWH + OFF_HW1, hb1, pH2, pB1,
          512, 512, 512, 512, Nn, 0, 262144L, BLD, 512, 2 | 8);

    // 3) m = relu(h1m @ w3 + b3)
    mgemm(pB1, pWH + OFF_HW3, hb3, nullptr, pM,
          512, 512, 512, 512, Nn, BLD, 262144L, BLD, 512, 2);

    // 4) local NL: projection + MMA banded attention
    for (int s = 0; s < 2; s++) {
        mgemm(pM, pWH + OFF_LCV + (long)s * 786432, pBias + s * 1536, nullptr, pCT,
              1536, 512, 512, 1536, Nn, BLD, 2L * 786432, CTN, 3072, 0);
        local_attn_k<<<dim3(4, Bb * Hh, Nn), 256, LSMEM>>>(mask);
    }

    // 5) segment attention weights
    satt_k<<<Bb, dim3(256, 4)>>>(se, sw1, sw2, out + BLD);

    // 6) aggregate
    agg_k<<<2048, 256>>>();

    // 7) global NL: projection + flash attention
    for (int s = 0; s < 2; s++) {
        mgemm(pA, pWH + OFF_GCV + (long)s * 786432, pBias + (6 + s) * 1536, nullptr, pCT,
              1536, 512, 512, 1536, 1, 0, 0, 0, 0, 0);
        flash_k<<<dim3(4, Bb * Hh), 256, FSMEM>>>(mask, (s == 1) ? out : nullptr);
    }
}

// round 13
// speedup vs baseline: 4.2924x; 1.1435x over previous
#include <cuda_runtime.h>
#include <cuda_fp16.h>
#include <math.h>
#include <stdint.h>

#define Bb 16
#define Ll 512
#define Dd 512
#define Nn 3
#define Hh 8
#define DH 64
#define AH 256
#define KHALF 7

#define BLD 4194304L        // Bb*Ll*Dd
#define CTN 12582912L       // 8192*1536 per n
#define CTSZ 37748736L      // 3 * CTN

// ---------------- scratch ------------------------------------------------------
__device__ __half g_seg[BLD];
__device__ __half g_WH[7864320];                  // fp16, tiled 32x128 blocks
__device__ __half g_B1[3*BLD];
__device__ __half g_M [3*BLD];
__device__ __half g_CT[CTSZ];                     // [n][8192][1536] mq|mv|mk
__device__ __half g_A [BLD];
__device__ float g_H2[Bb*Nn*Dd];
__device__ float g_SW[Bb*Nn];
__device__ float g_biasC[8*1536];

#define OFF_HW1 0L
#define OFF_HW3 786432L
#define OFF_LCV 1572864L
#define OFF_GCV 6291456L

// ---------------- PTX helpers --------------------------------------------------
__device__ __forceinline__ uint32_t smem_u32(const void* p) {
    uint32_t a;
    asm("{ .reg .u64 t; cvta.to.shared.u64 t, %1; cvt.u32.u64 %0, t; }" : "=r"(a) : "l"(p));
    return a;
}
#define CPA16(dst, src) asm volatile( \
    "cp.async.ca.shared.global [%0], [%1], 16;" :: "r"(dst), "l"(__cvta_generic_to_global(src)))
#define CPA_COMMIT() asm volatile("cp.async.commit_group;" ::: "memory")
#define CPA_WAIT1()  asm volatile("cp.async.wait_group 1;" ::: "memory")

#define BULK(dst, src, sz, mb) asm volatile( \
    "cp.async.bulk.shared::cta.global.mbarrier::complete_tx::bytes [%0], [%1], %2, [%3];" \
    :: "r"(dst), "l"(__cvta_generic_to_global(src)), "r"((uint32_t)(sz)), "r"(mb) : "memory")

#define MBAR_INIT(mb, c)   asm volatile("mbarrier.init.shared.b64 [%0], %1;" :: "r"(mb), "r"((uint32_t)(c)) : "memory")
#define MBAR_EXPECT(mb, tx) asm volatile("mbarrier.arrive.expect_tx.shared.b64 _, [%0], %1;" :: "r"(mb), "r"((uint32_t)(tx)) : "memory")
#define FENCE_ASYNC_SHARED() asm volatile("fence.proxy.async.shared::cta;" ::: "memory")
#define MBAR_WAIT(mb, ph) do { \
    uint32_t _m = (mb), _p = (ph), _d; \
    asm volatile("{\n\t.reg .pred p;\n\tmbarrier.try_wait.parity.acquire.cta.shared::cta.b64 p, [%1], %2;\n\tselp.b32 %0, 1, 0, p;\n\t}" \
        : "=r"(_d) : "r"(_m), "r"(_p) : "memory"); \
    if (!_d) { \
        asm volatile("{\n\t.reg .pred P1;\n\tWL_%=:\n\tmbarrier.try_wait.parity.acquire.cta.shared::cta.b64 P1, [%0], %1, 0x989680;\n\t@P1 bra.uni WD_%=;\n\tbra.uni WL_%=;\n\tWD_%=:\n\t}" \
            :: "r"(_m), "r"(_p) : "memory"); \
    } } while (0)

#define LDM_X4(r, a) asm volatile( \
    "ldmatrix.sync.aligned.m8n8.x4.shared.b16 {%0,%1,%2,%3}, [%4];" \
    : "=r"((r)[0]),"=r"((r)[1]),"=r"((r)[2]),"=r"((r)[3]) : "r"(a))
#define LDM_X4T(r, a) asm volatile( \
    "ldmatrix.sync.aligned.m8n8.x4.trans.shared.b16 {%0,%1,%2,%3}, [%4];" \
    : "=r"((r)[0]),"=r"((r)[1]),"=r"((r)[2]),"=r"((r)[3]) : "r"(a))
#define MMAF16(d, a, b) asm volatile( \
    "mma.sync.aligned.m16n8k16.row.col.f32.f16.f16.f32 " \
    "{%0,%1,%2,%3}, {%4,%5,%6,%7}, {%8,%9}, {%0,%1,%2,%3};" \
    : "+f"((d)[0]),"+f"((d)[1]),"+f"((d)[2]),"+f"((d)[3]) \
    : "r"((a)[0]),"r"((a)[1]),"r"((a)[2]),"r"((a)[3]), "r"((b)[0]),"r"((b)[1]))

__device__ __forceinline__ uint32_t packh2(float a, float b) {
    __half2 t = __floats2half2_rn(a, b);
    return *reinterpret_cast<uint32_t*>(&t);
}

// ---------------- prepasses ----------------------------------------------------
__global__ void cvt_k(const float* __restrict__ s, __half* __restrict__ d, long n)
{
    for (long i = ((long)blockIdx.x * blockDim.x + threadIdx.x) * 4; i < n;
         i += (long)gridDim.x * blockDim.x * 4) {
        float4 v = *reinterpret_cast<const float4*>(s + i);
        uint2 o;
        o.x = packh2(v.x, v.y);
        o.y = packh2(v.z, v.w);
        *reinterpret_cast<uint2*>(d + i) = o;
    }
}

__global__ void wtile_all_k(const float* __restrict__ hw1, const float* __restrict__ hw3,
                            const float* __restrict__ lcW, const float* __restrict__ lvW,
                            const float* __restrict__ gcW, const float* __restrict__ gvW)
{
    const float* srcs[6] = {hw1, hw3, lcW, lvW, gcW, gvW};
    const long  woff[6]  = {OFF_HW1, OFF_HW3, OFF_LCV, OFF_LCV, OFF_GCV, OFF_GCV};
    const int   C1s[6]   = {512, 512, 1024, 512, 1024, 512};
    const int   coff[6]  = {0, 0, 0, 1024, 0, 1024};
    const long  dss[6]   = {262144L, 262144L, 786432L, 786432L, 786432L, 786432L};
    const long  tots[6]  = {786432L, 786432L, 3145728L, 1572864L, 1048576L, 524288L};

    long gstride = (long)gridDim.x * blockDim.x * 4;
    #pragma unroll 1
    for (int sg = 0; sg < 6; sg++) {
        const float* s = srcs[sg];
        int C1 = C1s[sg];
        long sS = 512L * C1;
        for (long i = ((long)blockIdx.x * blockDim.x + threadIdx.x) * 4; i < tots[sg];
             i += gstride) {
            float4 v = *reinterpret_cast<const float4*>(s + i);
            long sl = i / sS;
            long rem = i - sl * sS;
            int k = (int)(rem / C1), c = (int)(rem - (long)(rem / C1) * C1);
            int n = coff[sg] + c;
            long d = woff[sg] + sl * dss[sg] + ((long)((n >> 7) * 16 + (k >> 5))) * 4096
                   + (k & 31) * 128 + ((((n & 127) >> 3) ^ (k & 7)) << 3) + (n & 7);
            float vv[4] = {v.x, v.y, v.z, v.w};
            #pragma unroll
            for (int e = 0; e < 4; e++)
                g_WH[d + e] = __float2half_rn(vv[e]);
        }
    }
}

__global__ void biascat_k(const float* __restrict__ lcb, const float* __restrict__ lvb,
                          const float* __restrict__ gcb, const float* __restrict__ gvb)
{
    int slot = blockIdx.x;
    for (int c = threadIdx.x; c < 1536; c += blockDim.x) {
        float v;
        if (slot < 6) v = (c < 1024) ? lcb[slot * 1024 + c] : lvb[slot * 512 + c - 1024];
        else {
            int s = slot - 6;
            v = (c < 1024) ? gcb[s * 1024 + c] : gvb[s * 512 + c - 1024];
        }
        g_biasC[slot * 1536 + c] = v;
    }
}

// ---------------- GEMM: fp16 A x fp16 W, 1 MMA/k16, BN=256 ---------------------
#define GSMEM 79904
__global__ void __launch_bounds__(256, 1) mma_gemm_k(
    const __half* __restrict__ A, const __half* __restrict__ WH,
    const float* __restrict__ bias, const float* __restrict__ H2,
    __half* __restrict__ C,
    int K, int lda, int ldc,
    long sAi, long sBi, long sCi, long sBias, int flags)
{
    constexpr int LDS = 40;
    constexpr int A_BYTES = 128 * LDS * 2;
    constexpr int BHI = 16384;
    constexpr int STAGE = A_BYTES + BHI;
    extern __shared__ char dsm[];
    uint32_t sb0 = smem_u32(dsm);
    uint32_t mbar0 = sb0 + 3 * STAGE;

    int z = blockIdx.z;
    A  += z * sAi;
    WH += z * sBi;
    C  += z * sCi;
    if (bias) bias += z * sBias;

    int tid = threadIdx.x, lane = tid & 31, wid = tid >> 5;
    int wm = wid & 1, wn = wid >> 1;
    int m0 = blockIdx.y * 128;
    int bx = blockIdx.x, n0 = bx * 256;
    int nc = K / 32;

    if (tid == 0) {
        MBAR_INIT(mbar0, 1); MBAR_INIT(mbar0 + 8, 1); MBAR_INIT(mbar0 + 16, 1);
        FENCE_ASYNC_SHARED();
    }
    __syncthreads();

    auto fillA = [&](int c) {
        int k0 = c * 32;
        uint32_t st = sb0 + (c % 3) * STAGE;
        #pragma unroll
        for (int it = 0; it < 2; it++) {
            int idx = tid + it * 256;
            int row = idx >> 2, u = idx & 3;
            CPA16(st + row * 80 + u * 16, A + (long)(m0 + row) * lda + k0 + u * 8);
        }
    };
    auto fillB = [&](int c) {
        uint32_t st = sb0 + (c % 3) * STAGE + A_BYTES;
        uint32_t mb = mbar0 + (c % 3) * 8;
        MBAR_EXPECT(mb, 16384u);
        long off0 = ((long)(bx * 2) * nc + c) * 4096;
        long off1 = ((long)(bx * 2 + 1) * nc + c) * 4096;
        BULK(st,        WH + off0, 8192, mb);
        BULK(st + 8192, WH + off1, 8192, mb);
    };

    float acc[4][8][4] = {};

    fillA(0); CPA_COMMIT();
    fillA(1); CPA_COMMIT();
    if (tid == 0) { fillB(0); fillB(1); }

    int alr = lane & 15, alc = (lane >> 4) << 3;
    int btr = (lane & 7) + (((lane >> 3) & 1) << 3);
    int btcc = (lane >> 4) & 1;

    for (int c = 0; c < nc; c++) {
        CPA_WAIT1();
        MBAR_WAIT(mbar0 + (c % 3) * 8, (c / 3) & 1);
        __syncthreads();
        if (c + 2 < nc) { fillA(c + 2); if (tid == 0) fillB(c + 2); }
        CPA_COMMIT();

        uint32_t base = sb0 + (c % 3) * STAGE;
        uint32_t aA = base + ((wm * 64 + alr) * LDS + alc) * 2;
        uint32_t bB = base + A_BYTES + (wn >> 1) * 8192;

        #pragma unroll
        for (int kk = 0; kk < 2; kk++) {
            uint32_t ah[4][4], bh[8][2];
            #pragma unroll
            for (int mt = 0; mt < 4; mt++)
                LDM_X4(ah[mt], aA + (uint32_t)((mt * 16 * LDS + kk * 16) * 2));
            int krow = kk * 16 + btr;
            #pragma unroll
            for (int p = 0; p < 4; p++) {
                int c16 = (wn & 1) * 8 + p * 2 + btcc;
                uint32_t ad = bB + (uint32_t)(krow * 256 + ((c16 ^ (krow & 7)) << 4));
                uint32_t r[4];
                LDM_X4T(r, ad);
                bh[2*p][0]=r[0]; bh[2*p][1]=r[1]; bh[2*p+1][0]=r[2]; bh[2*p+1][1]=r[3];
            }
            #pragma unroll
            for (int mt = 0; mt < 4; mt++)
                #pragma unroll
                for (int nt = 0; nt < 8; nt++)
                    MMAF16(acc[mt][nt], ah[mt], bh[nt]);
        }
    }

    const float* H2b = (flags & 8) ? (H2 + ((long)(m0 >> 9) * Nn + z) * 512) : nullptr;

    #pragma unroll
    for (int mt = 0; mt < 4; mt++) {
        int row = m0 + wm * 64 + mt * 16 + (lane >> 2);
        #pragma unroll
        for (int nt = 0; nt < 8; nt++) {
            int col = n0 + wn * 64 + nt * 8 + (lane & 3) * 2;
            float d0 = acc[mt][nt][0], d1 = acc[mt][nt][1];
            float d2 = acc[mt][nt][2], d3 = acc[mt][nt][3];
            if (bias) {
                float b0 = bias[col], b1 = bias[col + 1];
                d0 += b0; d1 += b1; d2 += b0; d3 += b1;
            }
            if (flags & 2) {
                d0 = fmaxf(d0, 0.f); d1 = fmaxf(d1, 0.f);
                d2 = fmaxf(d2, 0.f); d3 = fmaxf(d3, 0.f);
            }
            if (H2b) {
                float f0 = H2b[col], f1 = H2b[col + 1];
                d0 *= f0; d1 *= f1; d2 *= f0; d3 *= f1;
            }
            long o0 = (long)row * ldc + col;
            long o1 = o0 + (long)8 * ldc;
            *reinterpret_cast<uint32_t*>(C + o0) = packh2(d0, d1);
            *reinterpret_cast<uint32_t*>(C + o1) = packh2(d2, d3);
        }
    }
}

// ---------------- flash global attention ---------------------------------------
#define FQ 0
#define FK 18432
#define FV 36864
#define FMSK 55296
#define FSMEM 57344
#define FLDQ 72

__global__ void __launch_bounds__(256, 1) flash_k(const float* __restrict__ mask,
                                                  float* __restrict__ outp)
{
    extern __shared__ char sm[];
    uint32_t sb = smem_u32(sm);
    float* mbias = reinterpret_cast<float*>(sm + FMSK);
    int tid = threadIdx.x, lane = tid & 31, w = tid >> 5;
    int b = blockIdx.y >> 3, h = blockIdx.y & 7;
    int l0 = blockIdx.x * 128;
    long base = (long)b * 512 * 1536;

    for (int i = tid; i < 1024; i += 256) {
        int row = i >> 3, u = i & 7;
        *reinterpret_cast<uint4*>(sm + FQ + row * 144 + u * 16) =
            *reinterpret_cast<const uint4*>(g_CT + base + (long)(l0 + row) * 1536 + 1024 + h * DH + u * 8);
    }
    for (int i = tid; i < 512; i += 256)
        mbias[i] = (mask[(long)b * 512 + i] != 0.f) ? 0.f : -1e9f;

    float O[8][4];
    #pragma unroll
    for (int i = 0; i < 8; i++)
        #pragma unroll
        for (int e = 0; e < 4; e++) O[i][e] = 0.f;
    float mrow[2] = {-1e30f, -1e30f}, lrow[2] = {0.f, 0.f};

    int alr = lane & 15, alc = (lane >> 4) << 3;
    int blr = (lane & 7) + (((lane >> 4) & 1) << 3), blc = ((lane >> 3) & 1) << 3;
    int btr = (lane & 7) + (((lane >> 3) & 1) << 3), btc = ((lane >> 4) & 1) << 3;
    int c0 = (lane & 3) * 2;

    for (int mi = 0; mi < 4; mi++) {
        int m0 = mi * 128;
        __syncthreads();
        for (int i = tid; i < 1024; i += 256) {
            int row = i >> 3, u = i & 7;
            long gq = base + (long)(m0 + row) * 1536 + h * DH + u * 8;
            *reinterpret_cast<uint4*>(sm + FK + row * 144 + u * 16) =
                *reinterpret_cast<const uint4*>(g_CT + gq);
            *reinterpret_cast<uint4*>(sm + FV + row * 144 + u * 16) =
                *reinterpret_cast<const uint4*>(g_CT + gq + 512);
        }
        __syncthreads();

        float S[16][4];
        #pragma unroll
        for (int i = 0; i < 16; i++)
            #pragma unroll
            for (int e = 0; e < 4; e++) S[i][e] = 0.f;

        #pragma unroll
        for (int kc = 0; kc < 4; kc++) {
            uint32_t q[4];
            LDM_X4(q, sb + FQ + (uint32_t)(((w * 16 + alr) * FLDQ + kc * 16 + alc) * 2));
            #pragma unroll
            for (int p = 0; p < 8; p++) {
                uint32_t kf[4];
                LDM_X4(kf, sb + FK + (uint32_t)(((p * 16 + blr) * FLDQ + kc * 16 + blc) * 2));
                uint32_t b0[2] = {kf[0], kf[1]}, b1[2] = {kf[2], kf[3]};
                MMAF16(S[2*p],   q, b0);
                MMAF16(S[2*p+1], q, b1);
            }
        }

        float cmax[2] = {-1e30f, -1e30f};
        #pragma unroll
        for (int nt = 0; nt < 16; nt++)
            #pragma unroll
            for (int e = 0; e < 4; e++) {
                int col = m0 + nt * 8 + c0 + (e & 1);
                float v = S[nt][e] * 0.125f + mbias[col];
                S[nt][e] = v;
                cmax[e >> 1] = fmaxf(cmax[e >> 1], v);
            }
        #pragma unroll
        for (int o = 1; o <= 2; o <<= 1) {
            cmax[0] = fmaxf(cmax[0], __shfl_xor_sync(0xffffffffu, cmax[0], o));
            cmax[1] = fmaxf(cmax[1], __shfl_xor_sync(0xffffffffu, cmax[1], o));
        }
        float mn0 = fmaxf(mrow[0], cmax[0]), mn1 = fmaxf(mrow[1], cmax[1]);
        float a0 = __expf(mrow[0] - mn0), a1 = __expf(mrow[1] - mn1);
        mrow[0] = mn0; mrow[1] = mn1;
        lrow[0] *= a0; lrow[1] *= a1;
        #pragma unroll
        for (int i = 0; i < 8; i++) {
            O[i][0] *= a0; O[i][1] *= a0; O[i][2] *= a1; O[i][3] *= a1;
        }
        #pragma unroll
        for (int nt = 0; nt < 16; nt++)
            #pragma unroll
            for (int e = 0; e < 4; e++) {
                float p = __expf(S[nt][e] - ((e < 2) ? mn0 : mn1));
                S[nt][e] = p;
                lrow[e >> 1] += p;
            }

        #pragma unroll
        for (int kc = 0; kc < 8; kc++) {
            uint32_t ph[4];
            ph[0] = packh2(S[2*kc][0],   S[2*kc][1]);
            ph[1] = packh2(S[2*kc][2],   S[2*kc][3]);
            ph[2] = packh2(S[2*kc+1][0], S[2*kc+1][1]);
            ph[3] = packh2(S[2*kc+1][2], S[2*kc+1][3]);
            #pragma unroll
            for (int p = 0; p < 4; p++) {
                uint32_t vh[4];
                LDM_X4T(vh, sb + FV + (uint32_t)(((kc * 16 + btr) * FLDQ + p * 16 + btc) * 2));
                uint32_t b0[2] = {vh[0], vh[1]}, b1[2] = {vh[2], vh[3]};
                MMAF16(O[2*p],   ph, b0);
                MMAF16(O[2*p+1], ph, b1);
            }
        }
    }

    #pragma unroll
    for (int o = 1; o <= 2; o <<= 1) {
        lrow[0] += __shfl_xor_sync(0xffffffffu, lrow[0], o);
        lrow[1] += __shfl_xor_sync(0xffffffffu, lrow[1], o);
    }
    float inv0 = 1.f / lrow[0], inv1 = 1.f / lrow[1];

    int r0g = l0 + w * 16 + (lane >> 2);
    #pragma unroll
    for (int nt = 0; nt < 8; nt++) {
        int col = h * DH + nt * 8 + c0;
        long o0 = ((long)b * 512 + r0g) * 512 + col;
        long o1 = o0 + 8 * 512;
        __half2 x0 = *reinterpret_cast<const __half2*>(g_A + o0);
        __half2 x1 = *reinterpret_cast<const __half2*>(g_A + o1);
        float d0 = __low2float(x0) + O[nt][0] * inv0;
        float d1 = __high2float(x0) + O[nt][1] * inv0;
        float d2 = __low2float(x1) + O[nt][2] * inv1;
        float d3 = __high2float(x1) + O[nt][3] * inv1;
        if (outp) {
            *reinterpret_cast<float2*>(outp + o0) = make_float2(d0, d1);
            *reinterpret_cast<float2*>(outp + o1) = make_float2(d2, d3);
        } else {
            *reinterpret_cast<uint32_t*>(g_A + o0) = packh2(d0, d1);
            *reinterpret_cast<uint32_t*>(g_A + o1) = packh2(d2, d3);
        }
    }
}

// ---------------- MMA banded local attention (band-pruned) ----------------------
// Warp w rows r in [16w,16w+15]; valid cols c in [r+1, r+15] ⊂ blocks {w, w+1}.
#define LK2 0
#define LMQ2 18432
#define LMV2 39168
#define LBI2 59904
#define LSMEM 60480

__global__ void __launch_bounds__(256, 1) local_attn_k(const float* __restrict__ mask)
{
    extern __shared__ char sm[];
    uint32_t sb = smem_u32(sm);
    float* sBias = reinterpret_cast<float*>(sm + LBI2);
    int tid = threadIdx.x, lane = tid & 31, w = tid >> 5;
    int b = blockIdx.y >> 3, h = blockIdx.y & 7;
    int n = blockIdx.z;
    int l0 = blockIdx.x * 128;
    long base = (long)n * CTN + (long)b * 512 * 1536;

    for (int i = tid; i < 1024; i += 256) {
        int row = i >> 3, u = i & 7;
        *reinterpret_cast<uint4*>(sm + LK2 + row * 144 + u * 16) =
            *reinterpret_cast<const uint4*>(g_CT + base + (long)(l0 + row) * 1536 + 1024 + h * DH + u * 8);
    }
    for (int i = tid; i < 1152; i += 256) {
        int r = i >> 3, u = i & 7;
        int m = l0 - 8 + r;
        if (m >= 0 && m < 512) {
            long g = base + (long)m * 1536 + h * DH + u * 8;
            *reinterpret_cast<uint4*>(sm + LMQ2 + r * 144 + u * 16) =
                *reinterpret_cast<const uint4*>(g_CT + g);
            *reinterpret_cast<uint4*>(sm + LMV2 + r * 144 + u * 16) =
                *reinterpret_cast<const uint4*>(g_CT + g + 512);
        } else {
            uint4 z = make_uint4(0, 0, 0, 0);
            *reinterpret_cast<uint4*>(sm + LMQ2 + r * 144 + u * 16) = z;
            *reinterpret_cast<uint4*>(sm + LMV2 + r * 144 + u * 16) = z;
        }
    }
    for (int i = tid; i < 144; i += 256) {
        int m = l0 - 8 + i;
        sBias[i] = (m >= 0 && m < 512 && mask[(long)b * 512 + m] != 0.f) ? 0.f : -1e9f;
    }
    __syncthreads();

    int alr = lane & 15, alc = (lane >> 4) << 3;
    int blr = (lane & 7) + (((lane >> 4) & 1) << 3), blc = ((lane >> 3) & 1) << 3;
    int btr = (lane & 7) + (((lane >> 3) & 1) << 3), btc = ((lane >> 4) & 1) << 3;
    int c0 = (lane & 3) * 2;
    int r0 = w * 16 + (lane >> 2);

    // S over col-blocks p ∈ {w, w+1} only: S[pi*2 + sub][e]
    float S[4][4];
    #pragma unroll
    for (int i = 0; i < 4; i++)
        #pragma unroll
        for (int e = 0; e < 4; e++) S[i][e] = 0.f;

    #pragma unroll
    for (int kc = 0; kc < 4; kc++) {
        uint32_t aq[4];
        LDM_X4(aq, sb + LK2 + (uint32_t)(((w * 16 + alr) * 72 + kc * 16 + alc) * 2));
        #pragma unroll
        for (int pi = 0; pi < 2; pi++) {
            int p = w + pi;
            uint32_t kf[4];
            LDM_X4(kf, sb + LMQ2 + (uint32_t)(((p * 16 + blr) * 72 + kc * 16 + blc) * 2));
            uint32_t b0[2] = {kf[0], kf[1]}, b1[2] = {kf[2], kf[3]};
            MMAF16(S[2*pi],   aq, b0);
            MMAF16(S[2*pi+1], aq, b1);
        }
    }

    // band + seg mask, softmax
    float mx0 = -1e30f, mx1 = -1e30f;
    #pragma unroll
    for (int i = 0; i < 4; i++)
        #pragma unroll
        for (int e = 0; e < 4; e++) {
            int col = (w + (i >> 1)) * 16 + (i & 1) * 8 + c0 + (e & 1);
            int lr = (e < 2) ? r0 : (r0 + 8);
            float v = S[i][e] * 0.125f + sBias[col];
            if (col < lr + 1 || col > lr + 15) v = -1e30f;
            S[i][e] = v;
            if (e < 2) mx0 = fmaxf(mx0, v); else mx1 = fmaxf(mx1, v);
        }
    #pragma unroll
    for (int o = 1; o <= 2; o <<= 1) {
        mx0 = fmaxf(mx0, __shfl_xor_sync(0xffffffffu, mx0, o));
        mx1 = fmaxf(mx1, __shfl_xor_sync(0xffffffffu, mx1, o));
    }
    float s0 = 0.f, s1 = 0.f;
    #pragma unroll
    for (int i = 0; i < 4; i++)
        #pragma unroll
        for (int e = 0; e < 4; e++) {
            float p = __expf(S[i][e] - ((e < 2) ? mx0 : mx1));
            S[i][e] = p;
            if (e < 2) s0 += p; else s1 += p;
        }
    #pragma unroll
    for (int o = 1; o <= 2; o <<= 1) {
        s0 += __shfl_xor_sync(0xffffffffu, s0, o);
        s1 += __shfl_xor_sync(0xffffffffu, s1, o);
    }
    float inv0 = 1.f / s0, inv1 = 1.f / s1;

    // O = P @ mv over k-blocks kc ∈ {w, w+1} only
    float O[8][4];
    #pragma unroll
    for (int i = 0; i < 8; i++)
        #pragma unroll
        for (int e = 0; e < 4; e++) O[i][e] = 0.f;

    #pragma unroll
    for (int ki = 0; ki < 2; ki++) {
        int kc = w + ki;
        uint32_t ph[4];
        ph[0] = packh2(S[2*ki][0],   S[2*ki][1]);
        ph[1] = packh2(S[2*ki][2],   S[2*ki][3]);
        ph[2] = packh2(S[2*ki+1][0], S[2*ki+1][1]);
        ph[3] = packh2(S[2*ki+1][2], S[2*ki+1][3]);
        #pragma unroll
        for (int p = 0; p < 4; p++) {
            uint32_t vh[4];
            LDM_X4T(vh, sb + LMV2 + (uint32_t)(((kc * 16 + btr) * 72 + p * 16 + btc) * 2));
            uint32_t b0[2] = {vh[0], vh[1]}, b1[2] = {vh[2], vh[3]};
            MMAF16(O[2*p],   ph, b0);
            MMAF16(O[2*p+1], ph, b1);
        }
    }

    int gl = l0 + r0;
    #pragma unroll
    for (int nt = 0; nt < 8; nt++) {
        int col = h * DH + nt * 8 + c0;
        long o0 = (long)n * BLD + ((long)b * 512 + gl) * 512 + col;
        long o1 = o0 + 8 * 512;
        __half2 x0 = *reinterpret_cast<const __half2*>(g_M + o0);
        __half2 x1 = *reinterpret_cast<const __half2*>(g_M + o1);
        *reinterpret_cast<uint32_t*>(g_M + o0) =
            packh2(__low2float(x0) + O[nt][0] * inv0, __high2float(x0) + O[nt][1] * inv0);
        *reinterpret_cast<uint32_t*>(g_M + o1) =
            packh2(__low2float(x1) + O[nt][2] * inv1, __high2float(x1) + O[nt][3] * inv1);
    }
}

// ---------------- small kernels ------------------------------------------------
__global__ void h2_k(const float* __restrict__ se, const float* __restrict__ w2,
                     const float* __restrict__ b2)
{
    __shared__ float red[8][128];
    int bn = blockIdx.x;
    int n = bn % Nn;
    int h = blockIdx.y * 128 + threadIdx.x;
    int ty = threadIdx.y;
    const float* x = se + (long)bn * Dd;
    const float* w = w2 + (long)n * Dd * Dd + h;
    int d0 = ty * 64;
    float a0 = 0.f, a1 = 0.f, a2 = 0.f, a3 = 0.f;
    #pragma unroll 4
    for (int d = d0; d < d0 + 64; d += 4) {
        a0 = fmaf(x[d],     w[(long)d * Dd],       a0);
        a1 = fmaf(x[d + 1], w[(long)(d + 1) * Dd], a1);
        a2 = fmaf(x[d + 2], w[(long)(d + 2) * Dd], a2);
        a3 = fmaf(x[d + 3], w[(long)(d + 3) * Dd], a3);
    }
    red[ty][threadIdx.x] = (a0 + a1) + (a2 + a3);
    __syncthreads();
    if (ty == 0) {
        float acc = b2[n * Dd + h];
        #pragma unroll
        for (int e = 0; e < 8; e++) acc += red[e][threadIdx.x];
        g_H2[(long)bn * Dd + h] = fmaxf(acc, 0.f);
    }
}

__global__ void satt_k(const float* __restrict__ se, const float* __restrict__ w1,
                       const float* __restrict__ w2, float* __restrict__ out_tail)
{
    __shared__ float red[4][256];
    __shared__ float s1[256];
    __shared__ float alpha[Nn];
    int b = blockIdx.x, t = threadIdx.x, y = threadIdx.y;
    for (int n = 0; n < Nn; n++) {
        const float* x = se + ((long)b * Nn + n) * Dd;
        int d0 = y * 128;
        float a0 = 0.f, a1 = 0.f, a2 = 0.f, a3 = 0.f;
        #pragma unroll 4
        for (int d = d0; d < d0 + 128; d += 4) {
            a0 = fmaf(x[d],     w1[(long)d * AH + t],       a0);
            a1 = fmaf(x[d + 1], w1[(long)(d + 1) * AH + t], a1);
            a2 = fmaf(x[d + 2], w1[(long)(d + 2) * AH + t], a2);
            a3 = fmaf(x[d + 3], w1[(long)(d + 3) * AH + t], a3);
        }
        red[y][t] = (a0 + a1) + (a2 + a3);
        __syncthreads();
        if (y == 0) {
            float dot = red[0][t] + red[1][t] + red[2][t] + red[3][t];
            s1[t] = tanhf(dot) * w2[t];
        }
        __syncthreads();
        for (int o = 128; o; o >>= 1) {
            if (y == 0 && t < o) s1[t] += s1[t + o];
            __syncthreads();
        }
        if (y == 0 && t == 0) alpha[n] = s1[0];
        __syncthreads();
    }
    if (y == 0 && t == 0) {
        float mx = fmaxf(alpha[0], fmaxf(alpha[1], alpha[2]));
        float e[Nn], sum = 0.f;
        for (int n = 0; n < Nn; n++) { e[n] = expf(alpha[n] - mx); sum += e[n]; }
        for (int n = 0; n < Nn; n++) {
            float w = e[n] / sum;
            g_SW[b * Nn + n] = w;
            out_tail[b * Nn + n] = w;
        }
    }
}

__global__ void agg_k()
{
    long half_total = BLD / 2;
    long stride = (long)Ll * Dd / 2;
    for (long i = (long)blockIdx.x * blockDim.x + threadIdx.x; i < half_total;
         i += (long)gridDim.x * blockDim.x) {
        int b = (int)(i / stride);
        float a0 = 0.f, a1 = 0.f;
        #pragma unroll
        for (int n = 0; n < Nn; n++) {
            float sw = g_SW[b * Nn + n];
            __half2 v = *reinterpret_cast<const __half2*>(g_M + (long)n * BLD + i * 2);
            a0 = fmaf(sw, __low2float(v), a0);
            a1 = fmaf(sw, __high2float(v), a1);
        }
        *reinterpret_cast<uint32_t*>(g_A + i * 2) = packh2(a0, a1);
    }
}

// ---------------- host orchestration ------------------------------------------
static void mgemm(const __half* A, const __half* WH,
                  const float* bias, const float* H2, __half* C,
                  int N, int K, int lda, int ldc, int batches,
                  long sAi, long sBi, long sCi, long sBias, int flags)
{
    dim3 grid(N / 256, 64, batches);
    mma_gemm_k<<<grid, 256, GSMEM>>>(A, WH, bias, H2, C, K,
                                     lda, ldc, sAi, sBi, sCi, sBias, flags);
}

extern "C" void kernel_launch(void* const* d_in, const int* in_sizes, int n_in,
                              void* d_out, int out_size)
{
    const float* seg   = (const float*)d_in[0];
    const float* mask  = (const float*)d_in[1];
    const float* se    = (const float*)d_in[2];
    const float* hw1   = (const float*)d_in[3];
    const float* hb1   = (const float*)d_in[4];
    const float* hw2   = (const float*)d_in[5];
    const float* hb2   = (const float*)d_in[6];
    const float* hw3   = (const float*)d_in[7];
    const float* hb3   = (const float*)d_in[8];
    const float* lcW   = (const float*)d_in[9];
    const float* lcb   = (const float*)d_in[10];
    const float* lvW   = (const float*)d_in[11];
    const float* lvb   = (const float*)d_in[12];
    const float* gcW   = (const float*)d_in[13];
    const float* gcb   = (const float*)d_in[14];
    const float* gvW   = (const float*)d_in[15];
    const float* gvb   = (const float*)d_in[16];
    const float* sw1   = (const float*)d_in[17];
    const float* sw2   = (const float*)d_in[18];
    float* out = (float*)d_out;

    cudaFuncSetAttribute(mma_gemm_k,   cudaFuncAttributeMaxDynamicSharedMemorySize, GSMEM);
    cudaFuncSetAttribute(flash_k,      cudaFuncAttributeMaxDynamicSharedMemorySize, FSMEM);
    cudaFuncSetAttribute(local_attn_k, cudaFuncAttributeMaxDynamicSharedMemorySize, LSMEM);

    __half *pSeg, *pWH, *pB1, *pM, *pCT, *pA;
    float *pBias, *pH2;
    cudaGetSymbolAddress((void**)&pSeg, g_seg);
    cudaGetSymbolAddress((void**)&pWH, g_WH);
    cudaGetSymbolAddress((void**)&pB1, g_B1);
    cudaGetSymbolAddress((void**)&pM,  g_M);
    cudaGetSymbolAddress((void**)&pCT, g_CT);
    cudaGetSymbolAddress((void**)&pA,  g_A);
    cudaGetSymbolAddress((void**)&pBias, g_biasC);
    cudaGetSymbolAddress((void**)&pH2, g_H2);

    // prepasses
    cvt_k<<<1024, 256>>>(seg, pSeg, BLD);
    wtile_all_k<<<1024, 256>>>(hw1, hw3, lcW, lvW, gcW, gvW);
    biascat_k<<<8, 256>>>(lcb, lvb, gcb, gvb);

    // 1) h2
    h2_k<<<dim3(Bb * Nn, 4), dim3(128, 8)>>>(se, hw2, hb2);

    // 2) h1 = relu(seg @ w1 + b1) * h2
    mgemm(pSeg, pWH + OFF_HW1, hb1, pH2, pB1,
          512, 512, 512, 512, Nn, 0, 262144L, BLD, 512, 2 | 8);

    // 3) m = relu(h1m @ w3 + b3)
    mgemm(pB1, pWH + OFF_HW3, hb3, nullptr, pM,
          512, 512, 512, 512, Nn, BLD, 262144L, BLD, 512, 2);

    // 4) local NL: projection + band-pruned MMA attention
    for (int s = 0; s < 2; s++) {
        mgemm(pM, pWH + OFF_LCV + (long)s * 786432, pBias + s * 1536, nullptr, pCT,
              1536, 512, 512, 1536, Nn, BLD, 2L * 786432, CTN, 3072, 0);
        local_attn_k<<<dim3(4, Bb * Hh, Nn), 256, LSMEM>>>(mask);
    }

    // 5) segment attention weights
    satt_k<<<Bb, dim3(256, 4)>>>(se, sw1, sw2, out + BLD);

    // 6) aggregate
    agg_k<<<2048, 256>>>();

    // 7) global NL: projection + flash attention
    for (int s = 0; s < 2; s++) {
        mgemm(pA, pWH + OFF_GCV + (long)s * 786432, pBias + (6 + s) * 1536, nullptr, pCT,
              1536, 512, 512, 1536, 1, 0, 0, 0, 0, 0);
        flash_k<<<dim3(4, Bb * Hh), 256, FSMEM>>>(mask, (s == 1) ? out : nullptr);
    }
}

// round 14
// speedup vs baseline: 4.4068x; 1.0266x over previous
#include <cuda_runtime.h>
#include <cuda_fp16.h>
#include <math.h>
#include <stdint.h>

#define Bb 16
#define Ll 512
#define Dd 512
#define Nn 3
#define Hh 8
#define DH 64
#define AH 256
#define KHALF 7

#define BLD 4194304L        // Bb*Ll*Dd
#define CTN 12582912L       // 8192*1536 per n
#define CTSZ 37748736L      // 3 * CTN

// ---------------- scratch ------------------------------------------------------
__device__ __half g_seg[BLD];
__device__ __half g_WH[7864320];                  // fp16, tiled 32x128 blocks
__device__ __half g_B1[3*BLD];
__device__ __half g_M [3*BLD];
__device__ __half g_CT[CTSZ];                     // [n][8192][1536] mq|mv|mk
__device__ __half g_A [BLD];
__device__ float g_H2[Bb*Nn*Dd];
__device__ float g_SW[Bb*Nn];
__device__ float g_biasC[8*1536];

#define OFF_HW1 0L
#define OFF_HW3 786432L
#define OFF_LCV 1572864L
#define OFF_GCV 6291456L

// ---------------- PTX helpers --------------------------------------------------
__device__ __forceinline__ uint32_t smem_u32(const void* p) {
    uint32_t a;
    asm("{ .reg .u64 t; cvta.to.shared.u64 t, %1; cvt.u32.u64 %0, t; }" : "=r"(a) : "l"(p));
    return a;
}
#define CPA16(dst, src) asm volatile( \
    "cp.async.ca.shared.global [%0], [%1], 16;" :: "r"(dst), "l"(__cvta_generic_to_global(src)))
#define CPA_COMMIT() asm volatile("cp.async.commit_group;" ::: "memory")
#define CPA_WAIT1()  asm volatile("cp.async.wait_group 1;" ::: "memory")

#define BULK(dst, src, sz, mb) asm volatile( \
    "cp.async.bulk.shared::cta.global.mbarrier::complete_tx::bytes [%0], [%1], %2, [%3];" \
    :: "r"(dst), "l"(__cvta_generic_to_global(src)), "r"((uint32_t)(sz)), "r"(mb) : "memory")

#define MBAR_INIT(mb, c)   asm volatile("mbarrier.init.shared.b64 [%0], %1;" :: "r"(mb), "r"((uint32_t)(c)) : "memory")
#define MBAR_EXPECT(mb, tx) asm volatile("mbarrier.arrive.expect_tx.shared.b64 _, [%0], %1;" :: "r"(mb), "r"((uint32_t)(tx)) : "memory")
#define FENCE_ASYNC_SHARED() asm volatile("fence.proxy.async.shared::cta;" ::: "memory")
#define MBAR_WAIT(mb, ph) do { \
    uint32_t _m = (mb), _p = (ph), _d; \
    asm volatile("{\n\t.reg .pred p;\n\tmbarrier.try_wait.parity.acquire.cta.shared::cta.b64 p, [%1], %2;\n\tselp.b32 %0, 1, 0, p;\n\t}" \
        : "=r"(_d) : "r"(_m), "r"(_p) : "memory"); \
    if (!_d) { \
        asm volatile("{\n\t.reg .pred P1;\n\tWL_%=:\n\tmbarrier.try_wait.parity.acquire.cta.shared::cta.b64 P1, [%0], %1, 0x989680;\n\t@P1 bra.uni WD_%=;\n\tbra.uni WL_%=;\n\tWD_%=:\n\t}" \
            :: "r"(_m), "r"(_p) : "memory"); \
    } } while (0)

#define LDM_X4(r, a) asm volatile( \
    "ldmatrix.sync.aligned.m8n8.x4.shared.b16 {%0,%1,%2,%3}, [%4];" \
    : "=r"((r)[0]),"=r"((r)[1]),"=r"((r)[2]),"=r"((r)[3]) : "r"(a))
#define LDM_X4T(r, a) asm volatile( \
    "ldmatrix.sync.aligned.m8n8.x4.trans.shared.b16 {%0,%1,%2,%3}, [%4];" \
    : "=r"((r)[0]),"=r"((r)[1]),"=r"((r)[2]),"=r"((r)[3]) : "r"(a))
#define MMAF16(d, a, b) asm volatile( \
    "mma.sync.aligned.m16n8k16.row.col.f32.f16.f16.f32 " \
    "{%0,%1,%2,%3}, {%4,%5,%6,%7}, {%8,%9}, {%0,%1,%2,%3};" \
    : "+f"((d)[0]),"+f"((d)[1]),"+f"((d)[2]),"+f"((d)[3]) \
    : "r"((a)[0]),"r"((a)[1]),"r"((a)[2]),"r"((a)[3]), "r"((b)[0]),"r"((b)[1]))

__device__ __forceinline__ uint32_t packh2(float a, float b) {
    __half2 t = __floats2half2_rn(a, b);
    return *reinterpret_cast<uint32_t*>(&t);
}

// ---------------- merged prepass (seg cvt + weight tiling + bias concat) --------
__global__ void prep_all_k(const float* __restrict__ seg,
                           const float* __restrict__ hw1, const float* __restrict__ hw3,
                           const float* __restrict__ lcW, const float* __restrict__ lvW,
                           const float* __restrict__ gcW, const float* __restrict__ gvW,
                           const float* __restrict__ lcb, const float* __restrict__ lvb,
                           const float* __restrict__ gcb, const float* __restrict__ gvb)
{
    long gstride = (long)gridDim.x * blockDim.x * 4;
    // seg -> fp16
    for (long i = ((long)blockIdx.x * blockDim.x + threadIdx.x) * 4; i < BLD; i += gstride) {
        float4 v = *reinterpret_cast<const float4*>(seg + i);
        uint2 o;
        o.x = packh2(v.x, v.y);
        o.y = packh2(v.z, v.w);
        *reinterpret_cast<uint2*>(g_seg + i) = o;
    }
    // weights -> tiled fp16
    const float* srcs[6] = {hw1, hw3, lcW, lvW, gcW, gvW};
    const long  woff[6]  = {OFF_HW1, OFF_HW3, OFF_LCV, OFF_LCV, OFF_GCV, OFF_GCV};
    const int   C1s[6]   = {512, 512, 1024, 512, 1024, 512};
    const int   coff[6]  = {0, 0, 0, 1024, 0, 1024};
    const long  dss[6]   = {262144L, 262144L, 786432L, 786432L, 786432L, 786432L};
    const long  tots[6]  = {786432L, 786432L, 3145728L, 1572864L, 1048576L, 524288L};
    #pragma unroll 1
    for (int sg = 0; sg < 6; sg++) {
        const float* s = srcs[sg];
        int C1 = C1s[sg];
        long sS = 512L * C1;
        for (long i = ((long)blockIdx.x * blockDim.x + threadIdx.x) * 4; i < tots[sg];
             i += gstride) {
            float4 v = *reinterpret_cast<const float4*>(s + i);
            long sl = i / sS;
            long rem = i - sl * sS;
            int k = (int)(rem / C1), c = (int)(rem - (long)(rem / C1) * C1);
            int n = coff[sg] + c;
            long d = woff[sg] + sl * dss[sg] + ((long)((n >> 7) * 16 + (k >> 5))) * 4096
                   + (k & 31) * 128 + ((((n & 127) >> 3) ^ (k & 7)) << 3) + (n & 7);
            float vv[4] = {v.x, v.y, v.z, v.w};
            #pragma unroll
            for (int e = 0; e < 4; e++)
                g_WH[d + e] = __float2half_rn(vv[e]);
        }
    }
    // bias concat (8 slots x 1536)
    for (long i = (long)blockIdx.x * blockDim.x + threadIdx.x; i < 8 * 1536;
         i += (long)gridDim.x * blockDim.x) {
        int slot = (int)(i / 1536), c = (int)(i % 1536);
        float v;
        if (slot < 6) v = (c < 1024) ? lcb[slot * 1024 + c] : lvb[slot * 512 + c - 1024];
        else {
            int s = slot - 6;
            v = (c < 1024) ? gcb[s * 1024 + c] : gvb[s * 512 + c - 1024];
        }
        g_biasC[slot * 1536 + c] = v;
    }
}

// ---------------- GEMM: fp16 A x fp16 W, 1 MMA/k16, BN=256, BK=64 --------------
#define A_SUB 10240
#define A_BYTES 20480
#define B_BYTES 32768
#define STAGE 53248
#define GSMEM 159768
__global__ void __launch_bounds__(256, 1) mma_gemm_k(
    const __half* __restrict__ A, const __half* __restrict__ WH,
    const float* __restrict__ bias, const float* __restrict__ H2,
    __half* __restrict__ C,
    int K, int lda, int ldc,
    long sAi, long sBi, long sCi, long sBias, int flags)
{
    extern __shared__ char dsm[];
    uint32_t sb0 = smem_u32(dsm);
    uint32_t mbar0 = sb0 + 3 * STAGE;

    int z = blockIdx.z;
    A  += z * sAi;
    WH += z * sBi;
    C  += z * sCi;
    if (bias) bias += z * sBias;

    int tid = threadIdx.x, lane = tid & 31, wid = tid >> 5;
    int wm = wid & 1, wn = wid >> 1;
    int m0 = blockIdx.y * 128;
    int bx = blockIdx.x, n0 = bx * 256;
    int nc = K / 64;                       // 8 chunks
    int nk32 = K / 32;                     // 32-k blocks per n-block (16)

    if (tid == 0) {
        MBAR_INIT(mbar0, 1); MBAR_INIT(mbar0 + 8, 1); MBAR_INIT(mbar0 + 16, 1);
        FENCE_ASYNC_SHARED();
    }
    __syncthreads();

    auto fillA = [&](int c) {
        int k0 = c * 64;
        uint32_t st = sb0 + (c % 3) * STAGE;
        int row = tid >> 2, u = tid & 3;
        #pragma unroll
        for (int sub = 0; sub < 2; sub++) {
            #pragma unroll
            for (int it = 0; it < 2; it++) {
                int idx = tid + it * 256;
                int rr = idx >> 2, uu = idx & 3;
                CPA16(st + sub * A_SUB + rr * 80 + uu * 16,
                      A + (long)(m0 + rr) * lda + k0 + sub * 32 + uu * 8);
            }
        }
        (void)row; (void)u;
    };
    auto fillB = [&](int c) {
        uint32_t st = sb0 + (c % 3) * STAGE + A_BYTES;
        uint32_t mb = mbar0 + (c % 3) * 8;
        MBAR_EXPECT(mb, 32768u);
        long off0 = ((long)(bx * 2)     * nk32 + 2 * c) * 4096;
        long off1 = ((long)(bx * 2 + 1) * nk32 + 2 * c) * 4096;
        BULK(st,         WH + off0, 16384, mb);
        BULK(st + 16384, WH + off1, 16384, mb);
    };

    float acc[4][8][4] = {};

    fillA(0); CPA_COMMIT();
    fillA(1); CPA_COMMIT();
    if (tid == 0) { fillB(0); fillB(1); }

    int alr = lane & 15, alc = (lane >> 4) << 3;
    int btr = (lane & 7) + (((lane >> 3) & 1) << 3);
    int btcc = (lane >> 4) & 1;

    for (int c = 0; c < nc; c++) {
        CPA_WAIT1();
        MBAR_WAIT(mbar0 + (c % 3) * 8, (c / 3) & 1);
        __syncthreads();
        if (c + 2 < nc) { fillA(c + 2); if (tid == 0) fillB(c + 2); }
        CPA_COMMIT();

        uint32_t base = sb0 + (c % 3) * STAGE;

        #pragma unroll
        for (int kk = 0; kk < 4; kk++) {
            uint32_t ah[4][4], bh[8][2];
            uint32_t aA = base + (kk >> 1) * A_SUB +
                          (uint32_t)(((wm * 64 + alr) * 40 + (kk & 1) * 16 + alc) * 2);
            #pragma unroll
            for (int mt = 0; mt < 4; mt++)
                LDM_X4(ah[mt], aA + (uint32_t)(mt * 16 * 80));
            int krow = (kk & 1) * 16 + btr;
            uint32_t bB = base + A_BYTES + (wn >> 1) * 16384 + (kk >> 1) * 8192;
            #pragma unroll
            for (int p = 0; p < 4; p++) {
                int c16 = (wn & 1) * 8 + p * 2 + btcc;
                uint32_t ad = bB + (uint32_t)(krow * 256 + ((c16 ^ (krow & 7)) << 4));
                uint32_t r[4];
                LDM_X4T(r, ad);
                bh[2*p][0]=r[0]; bh[2*p][1]=r[1]; bh[2*p+1][0]=r[2]; bh[2*p+1][1]=r[3];
            }
            #pragma unroll
            for (int mt = 0; mt < 4; mt++)
                #pragma unroll
                for (int nt = 0; nt < 8; nt++)
                    MMAF16(acc[mt][nt], ah[mt], bh[nt]);
        }
    }

    const float* H2b = (flags & 8) ? (H2 + ((long)(m0 >> 9) * Nn + z) * 512) : nullptr;

    #pragma unroll
    for (int mt = 0; mt < 4; mt++) {
        int row = m0 + wm * 64 + mt * 16 + (lane >> 2);
        #pragma unroll
        for (int nt = 0; nt < 8; nt++) {
            int col = n0 + wn * 64 + nt * 8 + (lane & 3) * 2;
            float d0 = acc[mt][nt][0], d1 = acc[mt][nt][1];
            float d2 = acc[mt][nt][2], d3 = acc[mt][nt][3];
            if (bias) {
                float b0 = bias[col], b1 = bias[col + 1];
                d0 += b0; d1 += b1; d2 += b0; d3 += b1;
            }
            if (flags & 2) {
                d0 = fmaxf(d0, 0.f); d1 = fmaxf(d1, 0.f);
                d2 = fmaxf(d2, 0.f); d3 = fmaxf(d3, 0.f);
            }
            if (H2b) {
                float f0 = H2b[col], f1 = H2b[col + 1];
                d0 *= f0; d1 *= f1; d2 *= f0; d3 *= f1;
            }
            long o0 = (long)row * ldc + col;
            long o1 = o0 + (long)8 * ldc;
            *reinterpret_cast<uint32_t*>(C + o0) = packh2(d0, d1);
            *reinterpret_cast<uint32_t*>(C + o1) = packh2(d2, d3);
        }
    }
}

// ---------------- flash global attention ---------------------------------------
#define FQ 0
#define FK 18432
#define FV 36864
#define FMSK 55296
#define FSMEM 57344
#define FLDQ 72

__global__ void __launch_bounds__(256, 1) flash_k(const float* __restrict__ mask,
                                                  float* __restrict__ outp)
{
    extern __shared__ char sm[];
    uint32_t sb = smem_u32(sm);
    float* mbias = reinterpret_cast<float*>(sm + FMSK);
    int tid = threadIdx.x, lane = tid & 31, w = tid >> 5;
    int b = blockIdx.y >> 3, h = blockIdx.y & 7;
    int l0 = blockIdx.x * 128;
    long base = (long)b * 512 * 1536;

    for (int i = tid; i < 1024; i += 256) {
        int row = i >> 3, u = i & 7;
        *reinterpret_cast<uint4*>(sm + FQ + row * 144 + u * 16) =
            *reinterpret_cast<const uint4*>(g_CT + base + (long)(l0 + row) * 1536 + 1024 + h * DH + u * 8);
    }
    for (int i = tid; i < 512; i += 256)
        mbias[i] = (mask[(long)b * 512 + i] != 0.f) ? 0.f : -1e9f;

    float O[8][4];
    #pragma unroll
    for (int i = 0; i < 8; i++)
        #pragma unroll
        for (int e = 0; e < 4; e++) O[i][e] = 0.f;
    float mrow[2] = {-1e30f, -1e30f}, lrow[2] = {0.f, 0.f};

    int alr = lane & 15, alc = (lane >> 4) << 3;
    int blr = (lane & 7) + (((lane >> 4) & 1) << 3), blc = ((lane >> 3) & 1) << 3;
    int btr = (lane & 7) + (((lane >> 3) & 1) << 3), btc = ((lane >> 4) & 1) << 3;
    int c0 = (lane & 3) * 2;

    for (int mi = 0; mi < 4; mi++) {
        int m0 = mi * 128;
        __syncthreads();
        for (int i = tid; i < 1024; i += 256) {
            int row = i >> 3, u = i & 7;
            long gq = base + (long)(m0 + row) * 1536 + h * DH + u * 8;
            *reinterpret_cast<uint4*>(sm + FK + row * 144 + u * 16) =
                *reinterpret_cast<const uint4*>(g_CT + gq);
            *reinterpret_cast<uint4*>(sm + FV + row * 144 + u * 16) =
                *reinterpret_cast<const uint4*>(g_CT + gq + 512);
        }
        __syncthreads();

        float S[16][4];
        #pragma unroll
        for (int i = 0; i < 16; i++)
            #pragma unroll
            for (int e = 0; e < 4; e++) S[i][e] = 0.f;

        #pragma unroll
        for (int kc = 0; kc < 4; kc++) {
            uint32_t q[4];
            LDM_X4(q, sb + FQ + (uint32_t)(((w * 16 + alr) * FLDQ + kc * 16 + alc) * 2));
            #pragma unroll
            for (int p = 0; p < 8; p++) {
                uint32_t kf[4];
                LDM_X4(kf, sb + FK + (uint32_t)(((p * 16 + blr) * FLDQ + kc * 16 + blc) * 2));
                uint32_t b0[2] = {kf[0], kf[1]}, b1[2] = {kf[2], kf[3]};
                MMAF16(S[2*p],   q, b0);
                MMAF16(S[2*p+1], q, b1);
            }
        }

        float cmax[2] = {-1e30f, -1e30f};
        #pragma unroll
        for (int nt = 0; nt < 16; nt++)
            #pragma unroll
            for (int e = 0; e < 4; e++) {
                int col = m0 + nt * 8 + c0 + (e & 1);
                float v = S[nt][e] * 0.125f + mbias[col];
                S[nt][e] = v;
                cmax[e >> 1] = fmaxf(cmax[e >> 1], v);
            }
        #pragma unroll
        for (int o = 1; o <= 2; o <<= 1) {
            cmax[0] = fmaxf(cmax[0], __shfl_xor_sync(0xffffffffu, cmax[0], o));
            cmax[1] = fmaxf(cmax[1], __shfl_xor_sync(0xffffffffu, cmax[1], o));
        }
        float mn0 = fmaxf(mrow[0], cmax[0]), mn1 = fmaxf(mrow[1], cmax[1]);
        float a0 = __expf(mrow[0] - mn0), a1 = __expf(mrow[1] - mn1);
        mrow[0] = mn0; mrow[1] = mn1;
        lrow[0] *= a0; lrow[1] *= a1;
        #pragma unroll
        for (int i = 0; i < 8; i++) {
            O[i][0] *= a0; O[i][1] *= a0; O[i][2] *= a1; O[i][3] *= a1;
        }
        #pragma unroll
        for (int nt = 0; nt < 16; nt++)
            #pragma unroll
            for (int e = 0; e < 4; e++) {
                float p = __expf(S[nt][e] - ((e < 2) ? mn0 : mn1));
                S[nt][e] = p;
                lrow[e >> 1] += p;
            }

        #pragma unroll
        for (int kc = 0; kc < 8; kc++) {
            uint32_t ph[4];
            ph[0] = packh2(S[2*kc][0],   S[2*kc][1]);
            ph[1] = packh2(S[2*kc][2],   S[2*kc][3]);
            ph[2] = packh2(S[2*kc+1][0], S[2*kc+1][1]);
            ph[3] = packh2(S[2*kc+1][2], S[2*kc+1][3]);
            #pragma unroll
            for (int p = 0; p < 4; p++) {
                uint32_t vh[4];
                LDM_X4T(vh, sb + FV + (uint32_t)(((kc * 16 + btr) * FLDQ + p * 16 + btc) * 2));
                uint32_t b0[2] = {vh[0], vh[1]}, b1[2] = {vh[2], vh[3]};
                MMAF16(O[2*p],   ph, b0);
                MMAF16(O[2*p+1], ph, b1);
            }
        }
    }

    #pragma unroll
    for (int o = 1; o <= 2; o <<= 1) {
        lrow[0] += __shfl_xor_sync(0xffffffffu, lrow[0], o);
        lrow[1] += __shfl_xor_sync(0xffffffffu, lrow[1], o);
    }
    float inv0 = 1.f / lrow[0], inv1 = 1.f / lrow[1];

    int r0g = l0 + w * 16 + (lane >> 2);
    #pragma unroll
    for (int nt = 0; nt < 8; nt++) {
        int col = h * DH + nt * 8 + c0;
        long o0 = ((long)b * 512 + r0g) * 512 + col;
        long o1 = o0 + 8 * 512;
        __half2 x0 = *reinterpret_cast<const __half2*>(g_A + o0);
        __half2 x1 = *reinterpret_cast<const __half2*>(g_A + o1);
        float d0 = __low2float(x0) + O[nt][0] * inv0;
        float d1 = __high2float(x0) + O[nt][1] * inv0;
        float d2 = __low2float(x1) + O[nt][2] * inv1;
        float d3 = __high2float(x1) + O[nt][3] * inv1;
        if (outp) {
            *reinterpret_cast<float2*>(outp + o0) = make_float2(d0, d1);
            *reinterpret_cast<float2*>(outp + o1) = make_float2(d2, d3);
        } else {
            *reinterpret_cast<uint32_t*>(g_A + o0) = packh2(d0, d1);
            *reinterpret_cast<uint32_t*>(g_A + o1) = packh2(d2, d3);
        }
    }
}

// ---------------- MMA banded local attention (band-pruned) ----------------------
#define LK2 0
#define LMQ2 18432
#define LMV2 39168
#define LBI2 59904
#define LSMEM 60480

__global__ void __launch_bounds__(256, 1) local_attn_k(const float* __restrict__ mask)
{
    extern __shared__ char sm[];
    uint32_t sb = smem_u32(sm);
    float* sBias = reinterpret_cast<float*>(sm + LBI2);
    int tid = threadIdx.x, lane = tid & 31, w = tid >> 5;
    int b = blockIdx.y >> 3, h = blockIdx.y & 7;
    int n = blockIdx.z;
    int l0 = blockIdx.x * 128;
    long base = (long)n * CTN + (long)b * 512 * 1536;

    for (int i = tid; i < 1024; i += 256) {
        int row = i >> 3, u = i & 7;
        *reinterpret_cast<uint4*>(sm + LK2 + row * 144 + u * 16) =
            *reinterpret_cast<const uint4*>(g_CT + base + (long)(l0 + row) * 1536 + 1024 + h * DH + u * 8);
    }
    for (int i = tid; i < 1152; i += 256) {
        int r = i >> 3, u = i & 7;
        int m = l0 - 8 + r;
        if (m >= 0 && m < 512) {
            long g = base + (long)m * 1536 + h * DH + u * 8;
            *reinterpret_cast<uint4*>(sm + LMQ2 + r * 144 + u * 16) =
                *reinterpret_cast<const uint4*>(g_CT + g);
            *reinterpret_cast<uint4*>(sm + LMV2 + r * 144 + u * 16) =
                *reinterpret_cast<const uint4*>(g_CT + g + 512);
        } else {
            uint4 z = make_uint4(0, 0, 0, 0);
            *reinterpret_cast<uint4*>(sm + LMQ2 + r * 144 + u * 16) = z;
            *reinterpret_cast<uint4*>(sm + LMV2 + r * 144 + u * 16) = z;
        }
    }
    for (int i = tid; i < 144; i += 256) {
        int m = l0 - 8 + i;
        sBias[i] = (m >= 0 && m < 512 && mask[(long)b * 512 + m] != 0.f) ? 0.f : -1e9f;
    }
    __syncthreads();

    int alr = lane & 15, alc = (lane >> 4) << 3;
    int blr = (lane & 7) + (((lane >> 4) & 1) << 3), blc = ((lane >> 3) & 1) << 3;
    int btr = (lane & 7) + (((lane >> 3) & 1) << 3), btc = ((lane >> 4) & 1) << 3;
    int c0 = (lane & 3) * 2;
    int r0 = w * 16 + (lane >> 2);

    float S[4][4];
    #pragma unroll
    for (int i = 0; i < 4; i++)
        #pragma unroll
        for (int e = 0; e < 4; e++) S[i][e] = 0.f;

    #pragma unroll
    for (int kc = 0; kc < 4; kc++) {
        uint32_t aq[4];
        LDM_X4(aq, sb + LK2 + (uint32_t)(((w * 16 + alr) * 72 + kc * 16 + alc) * 2));
        #pragma unroll
        for (int pi = 0; pi < 2; pi++) {
            int p = w + pi;
            uint32_t kf[4];
            LDM_X4(kf, sb + LMQ2 + (uint32_t)(((p * 16 + blr) * 72 + kc * 16 + blc) * 2));
            uint32_t b0[2] = {kf[0], kf[1]}, b1[2] = {kf[2], kf[3]};
            MMAF16(S[2*pi],   aq, b0);
            MMAF16(S[2*pi+1], aq, b1);
        }
    }

    float mx0 = -1e30f, mx1 = -1e30f;
    #pragma unroll
    for (int i = 0; i < 4; i++)
        #pragma unroll
        for (int e = 0; e < 4; e++) {
            int col = (w + (i >> 1)) * 16 + (i & 1) * 8 + c0 + (e & 1);
            int lr = (e < 2) ? r0 : (r0 + 8);
            float v = S[i][e] * 0.125f + sBias[col];
            if (col < lr + 1 || col > lr + 15) v = -1e30f;
            S[i][e] = v;
            if (e < 2) mx0 = fmaxf(mx0, v); else mx1 = fmaxf(mx1, v);
        }
    #pragma unroll
    for (int o = 1; o <= 2; o <<= 1) {
        mx0 = fmaxf(mx0, __shfl_xor_sync(0xffffffffu, mx0, o));
        mx1 = fmaxf(mx1, __shfl_xor_sync(0xffffffffu, mx1, o));
    }
    float s0 = 0.f, s1 = 0.f;
    #pragma unroll
    for (int i = 0; i < 4; i++)
        #pragma unroll
        for (int e = 0; e < 4; e++) {
            float p = __expf(S[i][e] - ((e < 2) ? mx0 : mx1));
            S[i][e] = p;
            if (e < 2) s0 += p; else s1 += p;
        }
    #pragma unroll
    for (int o = 1; o <= 2; o <<= 1) {
        s0 += __shfl_xor_sync(0xffffffffu, s0, o);
        s1 += __shfl_xor_sync(0xffffffffu, s1, o);
    }
    float inv0 = 1.f / s0, inv1 = 1.f / s1;

    float O[8][4];
    #pragma unroll
    for (int i = 0; i < 8; i++)
        #pragma unroll
        for (int e = 0; e < 4; e++) O[i][e] = 0.f;

    #pragma unroll
    for (int ki = 0; ki < 2; ki++) {
        int kc = w + ki;
        uint32_t ph[4];
        ph[0] = packh2(S[2*ki][0],   S[2*ki][1]);
        ph[1] = packh2(S[2*ki][2],   S[2*ki][3]);
        ph[2] = packh2(S[2*ki+1][0], S[2*ki+1][1]);
        ph[3] = packh2(S[2*ki+1][2], S[2*ki+1][3]);
        #pragma unroll
        for (int p = 0; p < 4; p++) {
            uint32_t vh[4];
            LDM_X4T(vh, sb + LMV2 + (uint32_t)(((kc * 16 + btr) * 72 + p * 16 + btc) * 2));
            uint32_t b0[2] = {vh[0], vh[1]}, b1[2] = {vh[2], vh[3]};
            MMAF16(O[2*p],   ph, b0);
            MMAF16(O[2*p+1], ph, b1);
        }
    }

    int gl = l0 + r0;
    #pragma unroll
    for (int nt = 0; nt < 8; nt++) {
        int col = h * DH + nt * 8 + c0;
        long o0 = (long)n * BLD + ((long)b * 512 + gl) * 512 + col;
        long o1 = o0 + 8 * 512;
        __half2 x0 = *reinterpret_cast<const __half2*>(g_M + o0);
        __half2 x1 = *reinterpret_cast<const __half2*>(g_M + o1);
        *reinterpret_cast<uint32_t*>(g_M + o0) =
            packh2(__low2float(x0) + O[nt][0] * inv0, __high2float(x0) + O[nt][1] * inv0);
        *reinterpret_cast<uint32_t*>(g_M + o1) =
            packh2(__low2float(x1) + O[nt][2] * inv1, __high2float(x1) + O[nt][3] * inv1);
    }
}

// ---------------- small kernels ------------------------------------------------
__global__ void h2_k(const float* __restrict__ se, const float* __restrict__ w2,
                     const float* __restrict__ b2)
{
    __shared__ float red[8][128];
    int bn = blockIdx.x;
    int n = bn % Nn;
    int h = blockIdx.y * 128 + threadIdx.x;
    int ty = threadIdx.y;
    const float* x = se + (long)bn * Dd;
    const float* w = w2 + (long)n * Dd * Dd + h;
    int d0 = ty * 64;
    float a0 = 0.f, a1 = 0.f, a2 = 0.f, a3 = 0.f;
    #pragma unroll 4
    for (int d = d0; d < d0 + 64; d += 4) {
        a0 = fmaf(x[d],     w[(long)d * Dd],       a0);
        a1 = fmaf(x[d + 1], w[(long)(d + 1) * Dd], a1);
        a2 = fmaf(x[d + 2], w[(long)(d + 2) * Dd], a2);
        a3 = fmaf(x[d + 3], w[(long)(d + 3) * Dd], a3);
    }
    red[ty][threadIdx.x] = (a0 + a1) + (a2 + a3);
    __syncthreads();
    if (ty == 0) {
        float acc = b2[n * Dd + h];
        #pragma unroll
        for (int e = 0; e < 8; e++) acc += red[e][threadIdx.x];
        g_H2[(long)bn * Dd + h] = fmaxf(acc, 0.f);
    }
}

__global__ void satt_k(const float* __restrict__ se, const float* __restrict__ w1,
                       const float* __restrict__ w2, float* __restrict__ out_tail)
{
    __shared__ float red[4][256];
    __shared__ float s1[256];
    __shared__ float alpha[Nn];
    int b = blockIdx.x, t = threadIdx.x, y = threadIdx.y;
    for (int n = 0; n < Nn; n++) {
        const float* x = se + ((long)b * Nn + n) * Dd;
        int d0 = y * 128;
        float a0 = 0.f, a1 = 0.f, a2 = 0.f, a3 = 0.f;
        #pragma unroll 4
        for (int d = d0; d < d0 + 128; d += 4) {
            a0 = fmaf(x[d],     w1[(long)d * AH + t],       a0);
            a1 = fmaf(x[d + 1], w1[(long)(d + 1) * AH + t], a1);
            a2 = fmaf(x[d + 2], w1[(long)(d + 2) * AH + t], a2);
            a3 = fmaf(x[d + 3], w1[(long)(d + 3) * AH + t], a3);
        }
        red[y][t] = (a0 + a1) + (a2 + a3);
        __syncthreads();
        if (y == 0) {
            float dot = red[0][t] + red[1][t] + red[2][t] + red[3][t];
            s1[t] = tanhf(dot) * w2[t];
        }
        __syncthreads();
        for (int o = 128; o; o >>= 1) {
            if (y == 0 && t < o) s1[t] += s1[t + o];
            __syncthreads();
        }
        if (y == 0 && t == 0) alpha[n] = s1[0];
        __syncthreads();
    }
    if (y == 0 && t == 0) {
        float mx = fmaxf(alpha[0], fmaxf(alpha[1], alpha[2]));
        float e[Nn], sum = 0.f;
        for (int n = 0; n < Nn; n++) { e[n] = expf(alpha[n] - mx); sum += e[n]; }
        for (int n = 0; n < Nn; n++) {
            float w = e[n] / sum;
            g_SW[b * Nn + n] = w;
            out_tail[b * Nn + n] = w;
        }
    }
}

__global__ void agg_k()
{
    long half_total = BLD / 2;
    long stride = (long)Ll * Dd / 2;
    for (long i = (long)blockIdx.x * blockDim.x + threadIdx.x; i < half_total;
         i += (long)gridDim.x * blockDim.x) {
        int b = (int)(i / stride);
        float a0 = 0.f, a1 = 0.f;
        #pragma unroll
        for (int n = 0; n < Nn; n++) {
            float sw = g_SW[b * Nn + n];
            __half2 v = *reinterpret_cast<const __half2*>(g_M + (long)n * BLD + i * 2);
            a0 = fmaf(sw, __low2float(v), a0);
            a1 = fmaf(sw, __high2float(v), a1);
        }
        *reinterpret_cast<uint32_t*>(g_A + i * 2) = packh2(a0, a1);
    }
}

// ---------------- host orchestration ------------------------------------------
static void mgemm(const __half* A, const __half* WH,
                  const float* bias, const float* H2, __half* C,
                  int N, int K, int lda, int ldc, int batches,
                  long sAi, long sBi, long sCi, long sBias, int flags)
{
    dim3 grid(N / 256, 64, batches);
    mma_gemm_k<<<grid, 256, GSMEM>>>(A, WH, bias, H2, C, K,
                                     lda, ldc, sAi, sBi, sCi, sBias, flags);
}

extern "C" void kernel_launch(void* const* d_in, const int* in_sizes, int n_in,
                              void* d_out, int out_size)
{
    const float* seg   = (const float*)d_in[0];
    const float* mask  = (const float*)d_in[1];
    const float* se    = (const float*)d_in[2];
    const float* hw1   = (const float*)d_in[3];
    const float* hb1   = (const float*)d_in[4];
    const float* hw2   = (const float*)d_in[5];
    const float* hb2   = (const float*)d_in[6];
    const float* hw3   = (const float*)d_in[7];
    const float* hb3   = (const float*)d_in[8];
    const float* lcW   = (const float*)d_in[9];
    const float* lcb   = (const float*)d_in[10];
    const float* lvW   = (const float*)d_in[11];
    const float* lvb   = (const float*)d_in[12];
    const float* gcW   = (const float*)d_in[13];
    const float* gcb   = (const float*)d_in[14];
    const float* gvW   = (const float*)d_in[15];
    const float* gvb   = (const float*)d_in[16];
    const float* sw1   = (const float*)d_in[17];
    const float* sw2   = (const float*)d_in[18];
    float* out = (float*)d_out;

    cudaFuncSetAttribute(mma_gemm_k,   cudaFuncAttributeMaxDynamicSharedMemorySize, GSMEM);
    cudaFuncSetAttribute(flash_k,      cudaFuncAttributeMaxDynamicSharedMemorySize, FSMEM);
    cudaFuncSetAttribute(local_attn_k, cudaFuncAttributeMaxDynamicSharedMemorySize, LSMEM);

    __half *pSeg, *pWH, *pB1, *pM, *pCT, *pA;
    float *pBias, *pH2;
    cudaGetSymbolAddress((void**)&pSeg, g_seg);
    cudaGetSymbolAddress((void**)&pWH, g_WH);
    cudaGetSymbolAddress((void**)&pB1, g_B1);
    cudaGetSymbolAddress((void**)&pM,  g_M);
    cudaGetSymbolAddress((void**)&pCT, g_CT);
    cudaGetSymbolAddress((void**)&pA,  g_A);
    cudaGetSymbolAddress((void**)&pBias, g_biasC);
    cudaGetSymbolAddress((void**)&pH2, g_H2);

    // merged prepass
    prep_all_k<<<1024, 256>>>(seg, hw1, hw3, lcW, lvW, gcW, gvW, lcb, lvb, gcb, gvb);

    // 1) h2
    h2_k<<<dim3(Bb * Nn, 4), dim3(128, 8)>>>(se, hw2, hb2);

    // 2) h1 = relu(seg @ w1 + b1) * h2
    mgemm(pSeg, pWH + OFF_HW1, hb1, pH2, pB1,
          512, 512, 512, 512, Nn, 0, 262144L, BLD, 512, 2 | 8);

    // 3) m = relu(h1m @ w3 + b3)
    mgemm(pB1, pWH + OFF_HW3, hb3, nullptr, pM,
          512, 512, 512, 512, Nn, BLD, 262144L, BLD, 512, 2);

    // 4) local NL: projection + band-pruned MMA attention
    for (int s = 0; s < 2; s++) {
        mgemm(pM, pWH + OFF_LCV + (long)s * 786432, pBias + s * 1536, nullptr, pCT,
              1536, 512, 512, 1536, Nn, BLD, 2L * 786432, CTN, 3072, 0);
        local_attn_k<<<dim3(4, Bb * Hh, Nn), 256, LSMEM>>>(mask);
    }

    // 5) segment attention weights
    satt_k<<<Bb, dim3(256, 4)>>>(se, sw1, sw2, out + BLD);

    // 6) aggregate
    agg_k<<<2048, 256>>>();

    // 7) global NL: projection + flash attention
    for (int s = 0; s < 2; s++) {
        mgemm(pA, pWH + OFF_GCV + (long)s * 786432, pBias + (6 + s) * 1536, nullptr, pCT,
              1536, 512, 512, 1536, 1, 0, 0, 0, 0, 0);
        flash_k<<<dim3(4, Bb * Hh), 256, FSMEM>>>(mask, (s == 1) ? out : nullptr);
    }
}